// round 3
// baseline (speedup 1.0000x reference)
#include <cuda_runtime.h>

// Problem constants
static constexpr int BB   = 4;
static constexpr int S    = 1024;
static constexpr int F    = 128;
static constexpr int HH   = 512;
static constexpr int NHD  = 8;
static constexpr int DH   = 64;
static constexpr int OO   = 128;
static constexpr int ROWS = BB * S;         // 4096
static constexpr int RH   = ROWS * HH;

// Scratch (device globals; no runtime allocation allowed)
__device__ float g_bufA[3 * RH];
__device__ float g_bufB[3 * RH];
__device__ float g_Kh[RH];                  // [b][h][i][d]
__device__ float g_Qh[RH];
__device__ float g_Vh[RH];
__device__ float g_E[(long)BB * NHD * S * S];  // [z=b*8+h][j][i]
__device__ float g_rd[(long)BB * S * S];       // [b][j][i] 1/sum_h
__device__ float g_attn[RH];                   // [b][j][f = d*8+h]

// ---------------- packed f32x2 helpers ----------------
typedef unsigned long long u64;

__device__ __forceinline__ u64 dup2(float a) {
    u64 r;
    asm("mov.b64 %0, {%1, %1};" : "=l"(r) : "r"(__float_as_uint(a)));
    return r;
}
__device__ __forceinline__ void ffma2(u64& c, u64 a, u64 b) {
    asm("fma.rn.f32x2 %0, %1, %2, %0;" : "+l"(c) : "l"(a), "l"(b));
}
__device__ __forceinline__ u64 add2(u64 a, u64 b) {
    u64 d;
    asm("add.rn.f32x2 %0, %1, %2;" : "=l"(d) : "l"(a), "l"(b));
    return d;
}
__device__ __forceinline__ u64 abs2(u64 a) {
    u64 d;
    asm("and.b64 %0, %1, 0x7FFFFFFF7FFFFFFF;" : "=l"(d) : "l"(a));
    return d;
}
__device__ __forceinline__ void unpk2(float& lo, float& hi, u64 v) {
    unsigned int l, h;
    asm("mov.b64 {%0, %1}, %2;" : "=r"(l), "=r"(h) : "l"(v));
    lo = __uint_as_float(l);
    hi = __uint_as_float(h);
}

struct GemmBatch {
    const float* A[3];
    const float* B[3];
    const float* bias[3];
    float*       C[3];
};

// ---------------------------------------------------------------------------
// Batched (z = branch) double-buffered 128x128x8 SGEMM, fused bias/ReLU,
// optional fused head-split permute epilogue. FFMA2 inner product.
// ---------------------------------------------------------------------------
__global__ __launch_bounds__(256) void sgemm_bias_x2b(
    GemmBatch gb, int M, int N, int K, int relu, int permute)
{
    __shared__ float As[2][8][128];
    __shared__ float Bs[2][8][128];

    const int z = blockIdx.z;
    const float* __restrict__ A    = gb.A[z];
    const float* __restrict__ B    = gb.B[z];
    const float* __restrict__ bias = gb.bias[z];
    float* __restrict__ C          = gb.C[z];

    const int tid = threadIdx.x;
    const int bx = blockIdx.x, by = blockIdx.y;

    const int ar = tid >> 1;          // 0..127
    const int ac = (tid & 1) << 2;    // 0 or 4
    const int br = tid >> 5;          // 0..7
    const int bc = (tid & 31) << 2;   // 0..124

    const float* Ap = A + (long)(by * 128 + ar) * K + ac;
    const float* Bp = B + (long)br * N + bx * 128 + bc;

    float4 a4 = *(const float4*)Ap;
    float4 b4 = *(const float4*)Bp;
    As[0][ac + 0][ar] = a4.x; As[0][ac + 1][ar] = a4.y;
    As[0][ac + 2][ar] = a4.z; As[0][ac + 3][ar] = a4.w;
    *(float4*)&Bs[0][br][bc] = b4;
    __syncthreads();

    const int ty = tid >> 4, tx = tid & 15;

    u64 acc2[8][4];
#pragma unroll
    for (int m = 0; m < 8; m++)
#pragma unroll
        for (int n = 0; n < 4; n++) acc2[m][n] = 0ULL;

    const int nt = K >> 3;
    int buf = 0;
    for (int kt = 0; kt < nt; kt++) {
        if (kt + 1 < nt) {
            a4 = *(const float4*)(Ap + (kt + 1) * 8);
            b4 = *(const float4*)(Bp + (long)(kt + 1) * 8 * N);
        }
#pragma unroll
        for (int k = 0; k < 8; k++) {
            float af[8];
            u64 b2[4];
            *(float4*)&af[0] = *(const float4*)&As[buf][k][ty * 8];
            *(float4*)&af[4] = *(const float4*)&As[buf][k][ty * 8 + 4];
            *(ulonglong2*)&b2[0] = *(const ulonglong2*)&Bs[buf][k][tx * 8];
            *(ulonglong2*)&b2[2] = *(const ulonglong2*)&Bs[buf][k][tx * 8 + 4];
#pragma unroll
            for (int m = 0; m < 8; m++) {
                const u64 a2 = dup2(af[m]);
#pragma unroll
                for (int n = 0; n < 4; n++) ffma2(acc2[m][n], a2, b2[n]);
            }
        }
        if (kt + 1 < nt) {
            buf ^= 1;
            As[buf][ac + 0][ar] = a4.x; As[buf][ac + 1][ar] = a4.y;
            As[buf][ac + 2][ar] = a4.z; As[buf][ac + 3][ar] = a4.w;
            *(float4*)&Bs[buf][br][bc] = b4;
            __syncthreads();
        }
    }

    float bb[8];
#pragma unroll
    for (int n = 0; n < 8; n++) bb[n] = bias[bx * 128 + tx * 8 + n];

#pragma unroll
    for (int m = 0; m < 8; m++) {
        const int row = by * 128 + ty * 8 + m;
        float o[8];
#pragma unroll
        for (int n = 0; n < 4; n++) {
            float lo, hi;
            unpk2(lo, hi, acc2[m][n]);
            float v0 = lo + bb[2 * n], v1 = hi + bb[2 * n + 1];
            o[2 * n]     = relu ? fmaxf(v0, 0.f) : v0;
            o[2 * n + 1] = relu ? fmaxf(v1, 0.f) : v1;
        }
        if (permute) {
            // row = b*1024 + i ; f = bx*128 + tx*8 + n -> h = n, d = bx*16+tx
            const int b = row >> 10, i = row & 1023;
            const int d = bx * 16 + tx;
            float* yp = C + ((long)(b * 8) * 1024 + i) * 64 + d;
#pragma unroll
            for (int n = 0; n < 8; n++) yp[n * 65536] = o[n];
        } else {
            float* cp = C + (long)row * N + bx * 128 + tx * 8;
            *(float4*)(cp + 0) = make_float4(o[0], o[1], o[2], o[3]);
            *(float4*)(cp + 4) = make_float4(o[4], o[5], o[6], o[7]);
        }
    }
}

// ---------------------------------------------------------------------------
// Final projection GEMM: C[M,128] = A[M,512] @ B[512,128] + bias.
// Tile 32(M) x 64(N), grid (2, M/32) = 256 CTAs for good residency.
// ---------------------------------------------------------------------------
__global__ __launch_bounds__(256) void sgemm_final(
    const float* __restrict__ A, const float* __restrict__ B,
    const float* __restrict__ bias, float* __restrict__ C,
    int M, int N, int K)
{
    __shared__ float As[16][32];
    __shared__ float Bs[16][64];

    const int tid = threadIdx.x;
    const int bx = blockIdx.x, by = blockIdx.y;

    const int ar = tid >> 3;          // 0..31
    const int ac = (tid & 7) << 1;    // 0..14 (2 cols each)
    const int brr = tid >> 4;         // 0..15
    const int bcc = (tid & 15) << 2;  // 0..60

    const float* Ap = A + (long)(by * 32 + ar) * K + ac;
    const float* Bp = B + (long)brr * N + bx * 64 + bcc;

    const int ty = tid >> 4, tx = tid & 15;

    u64 acc2[4];                       // (j-pair) x 4 n
#pragma unroll
    for (int n = 0; n < 4; n++) acc2[n] = 0ULL;

    const int nt = K >> 4;             // 32
    for (int kt = 0; kt < nt; kt++) {
        const float2 a2l = *(const float2*)(Ap + kt * 16);
        const float4 bv  = *(const float4*)(Bp + (long)kt * 16 * N);
        if (kt) __syncthreads();
        As[ac + 0][ar] = a2l.x;
        As[ac + 1][ar] = a2l.y;
        *(float4*)&Bs[brr][bcc] = bv;
        __syncthreads();
#pragma unroll
        for (int k = 0; k < 16; k++) {
            const u64 a2 = *(const u64*)&As[k][ty * 2];
            float bf[4];
            *(float4*)&bf[0] = *(const float4*)&Bs[k][tx * 4];
#pragma unroll
            for (int n = 0; n < 4; n++) ffma2(acc2[n], a2, dup2(bf[n]));
        }
    }

    const int j0 = by * 32 + ty * 2;
    const int c0 = bx * 64 + tx * 4;
#pragma unroll
    for (int n = 0; n < 4; n++) {
        float lo, hi;
        unpk2(lo, hi, acc2[n]);
        const float bb = bias[c0 + n];
        C[(long)j0 * N + c0 + n]       = lo + bb;
        C[(long)(j0 + 1) * N + c0 + n] = hi + bb;
    }
}

// ---------------------------------------------------------------------------
// Phase A1: distance-GEMM.  E[z][j][i] = exp(-0.5 * (sum_d |Q[z,j,d]-K[z,i,d]|)^2)
// ---------------------------------------------------------------------------
__global__ __launch_bounds__(256) void dist_exp_x2(
    const float* __restrict__ Qh, const float* __restrict__ Kh,
    float* __restrict__ E)
{
    __shared__ float Qs[16][256];   // duplicated pairs
    __shared__ float Ks[16][128];   // negated

    const int z   = blockIdx.z;
    const int tid = threadIdx.x;
    const int r   = tid >> 1;
    const int dc  = (tid & 1) << 3;
    const int ty  = tid >> 4, tx = tid & 15;

    const float* Qp = Qh + (long)(z * 1024 + blockIdx.y * 128 + r) * 64 + dc;
    const float* Kp = Kh + (long)(z * 1024 + blockIdx.x * 128 + r) * 64 + dc;

    u64 acc2[8][4];
#pragma unroll
    for (int m = 0; m < 8; m++)
#pragma unroll
        for (int n = 0; n < 4; n++) acc2[m][n] = 0ULL;

    for (int kt = 0; kt < 4; kt++) {
        const float4 q0 = *(const float4*)(Qp + kt * 16);
        const float4 q1 = *(const float4*)(Qp + kt * 16 + 4);
        const float4 k0 = *(const float4*)(Kp + kt * 16);
        const float4 k1 = *(const float4*)(Kp + kt * 16 + 4);
        if (kt) __syncthreads();
        float qv[8] = {q0.x, q0.y, q0.z, q0.w, q1.x, q1.y, q1.z, q1.w};
        float kv[8] = {k0.x, k0.y, k0.z, k0.w, k1.x, k1.y, k1.z, k1.w};
#pragma unroll
        for (int t = 0; t < 8; t++) {
            *(float2*)&Qs[dc + t][2 * r] = make_float2(qv[t], qv[t]);
            Ks[dc + t][r] = -kv[t];
        }
        __syncthreads();
#pragma unroll
        for (int k = 0; k < 16; k++) {
            u64 q2[8], k2[4];
#pragma unroll
            for (int m = 0; m < 8; m++)
                q2[m] = *(const u64*)&Qs[k][2 * (ty * 8 + m)];
            *(ulonglong2*)&k2[0] = *(const ulonglong2*)&Ks[k][tx * 8];
            *(ulonglong2*)&k2[2] = *(const ulonglong2*)&Ks[k][tx * 8 + 4];
#pragma unroll
            for (int m = 0; m < 8; m++)
#pragma unroll
                for (int n = 0; n < 4; n++) {
                    const u64 t2 = abs2(add2(q2[m], k2[n]));
                    acc2[m][n] = add2(acc2[m][n], t2);
                }
        }
    }

    const long base = ((long)(z * 1024 + blockIdx.y * 128 + ty * 8)) * 1024
                    + blockIdx.x * 128 + tx * 8;
#pragma unroll
    for (int m = 0; m < 8; m++) {
        float o[8];
#pragma unroll
        for (int n = 0; n < 4; n++) {
            float lo, hi;
            unpk2(lo, hi, acc2[m][n]);
            o[2 * n]     = __expf(-0.5f * lo * lo);
            o[2 * n + 1] = __expf(-0.5f * hi * hi);
        }
        *(float4*)(E + base + (long)m * 1024 + 0) = make_float4(o[0], o[1], o[2], o[3]);
        *(float4*)(E + base + (long)m * 1024 + 4) = make_float4(o[4], o[5], o[6], o[7]);
    }
}

// ---------------------------------------------------------------------------
// Phase A2: rdenom[b][j][i] = 1 / sum_h E[b*8+h][j][i]
// ---------------------------------------------------------------------------
__global__ __launch_bounds__(256) void denom_kernel(
    const float* __restrict__ E, float* __restrict__ rd)
{
    const int gid = blockIdx.x * 256 + threadIdx.x;  // 1048576 float4s
    const int b   = gid >> 18;
    const int rem = gid & ((1 << 18) - 1);
    const float4* Ep = (const float4*)E;
    float4 s = make_float4(0.f, 0.f, 0.f, 0.f);
#pragma unroll
    for (int h = 0; h < 8; h++) {
        const float4 v = Ep[(((long)(b * 8 + h)) << 18) + rem];
        s.x += v.x; s.y += v.y; s.z += v.z; s.w += v.w;
    }
    ((float4*)rd)[gid] = make_float4(1.f / s.x, 1.f / s.y, 1.f / s.z, 1.f / s.w);
}

// ---------------------------------------------------------------------------
// Phase B: out[b][j][d*8+h] = sum_i (E[z][j][i]*rd[b][j][i]) * V[z][i][d]
// 64-j tiles for residency: grid (1,16,32) = 512 CTAs, small reg footprint.
// ---------------------------------------------------------------------------
__global__ __launch_bounds__(256) void attn_v_x2(
    const float* __restrict__ E, const float* __restrict__ rd,
    const float* __restrict__ Vh, float* __restrict__ Oo)
{
    __shared__ float As[16][64];
    __shared__ float Vs[16][64];

    const int z = blockIdx.z, b = z >> 3, h = z & 7;
    const int tid = threadIdx.x;
    const int jr = tid >> 2, ic = (tid & 3) << 2;     // A: j-row 0..63, i-col base
    const int vr = tid >> 4, vc = (tid & 15) << 2;    // V: i-row, d-col
    const int ty = tid >> 4, tx = tid & 15;

    const float* Ep = E  + ((long)(z * 1024 + blockIdx.y * 64 + jr)) * 1024 + ic;
    const float* Rp = rd + ((long)(b * 1024 + blockIdx.y * 64 + jr)) * 1024 + ic;
    const float* Vp = Vh + (long)(z * 1024 + vr) * 64 + vc;

    u64 acc2[2][4];   // [j-pair (ty*4 + 2p)][d]
#pragma unroll
    for (int m = 0; m < 2; m++)
#pragma unroll
        for (int n = 0; n < 4; n++) acc2[m][n] = 0ULL;

    for (int kt = 0; kt < 64; kt++) {
        const float4 e0 = *(const float4*)(Ep + kt * 16);
        const float4 r0 = *(const float4*)(Rp + kt * 16);
        const float4 v4 = *(const float4*)(Vp + (long)kt * 16 * 64);
        if (kt) __syncthreads();
        As[ic + 0][jr] = e0.x * r0.x; As[ic + 1][jr] = e0.y * r0.y;
        As[ic + 2][jr] = e0.z * r0.z; As[ic + 3][jr] = e0.w * r0.w;
        *(float4*)&Vs[vr][vc] = v4;
        __syncthreads();
#pragma unroll
        for (int k = 0; k < 16; k++) {
            u64 a2[2];
            float vf[4];
            *(ulonglong2*)&a2[0] = *(const ulonglong2*)&As[k][ty * 4];
            *(float4*)&vf[0] = *(const float4*)&Vs[k][tx * 4];
#pragma unroll
            for (int n = 0; n < 4; n++) {
                const u64 v2 = dup2(vf[n]);
#pragma unroll
                for (int m = 0; m < 2; m++) ffma2(acc2[m][n], a2[m], v2);
            }
        }
    }

    const int j0 = blockIdx.y * 64 + ty * 4;
#pragma unroll
    for (int m = 0; m < 2; m++) {
        float* op0 = Oo + (long)(b * 1024 + j0 + 2 * m) * 512 + h;
        float* op1 = Oo + (long)(b * 1024 + j0 + 2 * m + 1) * 512 + h;
#pragma unroll
        for (int n = 0; n < 4; n++) {
            float lo, hi;
            unpk2(lo, hi, acc2[m][n]);
            op0[(tx * 4 + n) * 8] = lo;
            op1[(tx * 4 + n) * 8] = hi;
        }
    }
}

// ---------------------------------------------------------------------------
extern "C" void kernel_launch(void* const* d_in, const int* in_sizes, int n_in,
                              void* d_out, int out_size)
{
    const float* KEY   = (const float*)d_in[0];
    const float* VALUE = (const float*)d_in[1];
    const float* QUERY = (const float*)d_in[2];

    float *bufA, *bufB, *Kh, *Qh, *Vh, *E, *rd, *attn;
    cudaGetSymbolAddress((void**)&bufA, g_bufA);
    cudaGetSymbolAddress((void**)&bufB, g_bufB);
    cudaGetSymbolAddress((void**)&Kh,   g_Kh);
    cudaGetSymbolAddress((void**)&Qh,   g_Qh);
    cudaGetSymbolAddress((void**)&Vh,   g_Vh);
    cudaGetSymbolAddress((void**)&E,    g_E);
    cudaGetSymbolAddress((void**)&rd,   g_rd);
    cudaGetSymbolAddress((void**)&attn, g_attn);

    const dim3 blk(256);
    const dim3 gmlp(HH / 128, ROWS / 128, 3);   // (4, 32, 3) = 384 CTAs

    // Branch order: 0=K (input KEY, weights d_in[3..8]),
    //               1=Q (QUERY, d_in[9..14]), 2=V (VALUE, d_in[15..20])
    const float* X[3]  = {KEY, QUERY, VALUE};
    const int    wb[3] = {3, 9, 15};
    float* headed[3]   = {Kh, Qh, Vh};

    GemmBatch l1{}, l2{}, l3{};
    for (int z = 0; z < 3; z++) {
        l1.A[z] = X[z];
        l1.B[z] = (const float*)d_in[wb[z] + 0];
        l1.bias[z] = (const float*)d_in[wb[z] + 1];
        l1.C[z] = bufA + (long)z * RH;

        l2.A[z] = bufA + (long)z * RH;
        l2.B[z] = (const float*)d_in[wb[z] + 2];
        l2.bias[z] = (const float*)d_in[wb[z] + 3];
        l2.C[z] = bufB + (long)z * RH;

        l3.A[z] = bufB + (long)z * RH;
        l3.B[z] = (const float*)d_in[wb[z] + 4];
        l3.bias[z] = (const float*)d_in[wb[z] + 5];
        l3.C[z] = headed[z];
    }

    sgemm_bias_x2b<<<gmlp, blk>>>(l1, ROWS, HH, F,  1, 0);
    sgemm_bias_x2b<<<gmlp, blk>>>(l2, ROWS, HH, HH, 1, 0);
    sgemm_bias_x2b<<<gmlp, blk>>>(l3, ROWS, HH, HH, 0, 1);

    dist_exp_x2<<<dim3(8, 8, 32), blk>>>(Qh, Kh, E);
    denom_kernel<<<4096, blk>>>(E, rd);
    attn_v_x2<<<dim3(1, 16, 32), blk>>>(E, rd, Vh, attn);

    sgemm_final<<<dim3(OO / 64, ROWS / 32), blk>>>(
        attn, (const float*)d_in[21], (const float*)d_in[22],
        (float*)d_out, ROWS, OO, HH);
}

// round 5
// speedup vs baseline: 1.5963x; 1.5963x over previous
#include <cuda_runtime.h>

// Problem constants
static constexpr int BB   = 4;
static constexpr int S    = 1024;
static constexpr int F    = 128;
static constexpr int HH   = 512;
static constexpr int NHD  = 8;
static constexpr int DH   = 64;
static constexpr int OO   = 128;
static constexpr int ROWS = BB * S;         // 4096
static constexpr int RH   = ROWS * HH;

// Scratch (device globals; no runtime allocation allowed)
__device__ float g_bufA[3 * RH];
__device__ float g_bufB[3 * RH];
__device__ float g_Kh[RH];                  // [b][h][i][d]
__device__ float g_Qh[RH];
__device__ float g_Vh[RH];
__device__ float g_E[(long)BB * NHD * S * S];  // [z=b*8+h][j][i]
__device__ float g_rd[(long)BB * S * S];       // [b][j][i] 1/sum_h
__device__ float g_attn[RH];                   // [b][j][f = d*8+h]

// ---------------- packed f32x2 helpers ----------------
typedef unsigned long long u64;

__device__ __forceinline__ u64 dup2(float a) {
    u64 r;
    asm("mov.b64 %0, {%1, %1};" : "=l"(r) : "r"(__float_as_uint(a)));
    return r;
}
__device__ __forceinline__ void ffma2(u64& c, u64 a, u64 b) {
    asm("fma.rn.f32x2 %0, %1, %2, %0;" : "+l"(c) : "l"(a), "l"(b));
}
__device__ __forceinline__ u64 add2(u64 a, u64 b) {
    u64 d;
    asm("add.rn.f32x2 %0, %1, %2;" : "=l"(d) : "l"(a), "l"(b));
    return d;
}
__device__ __forceinline__ u64 abs2(u64 a) {
    u64 d;
    asm("and.b64 %0, %1, 0x7FFFFFFF7FFFFFFF;" : "=l"(d) : "l"(a));
    return d;
}
__device__ __forceinline__ void unpk2(float& lo, float& hi, u64 v) {
    unsigned int l, h;
    asm("mov.b64 {%0, %1}, %2;" : "=r"(l), "=r"(h) : "l"(v));
    lo = __uint_as_float(l);
    hi = __uint_as_float(h);
}

struct GemmBatch {
    const float* A[3];
    const float* B[3];
    const float* bias[3];
    float*       C[3];
};

// ---------------------------------------------------------------------------
// Batched (z = branch) double-buffered 128x128x8 SGEMM, fused bias/ReLU,
// optional fused head-split permute epilogue. FFMA2 inner product.
// __launch_bounds__(256, 2): hard 128-reg cap -> guaranteed 2 CTAs/SM.
// ---------------------------------------------------------------------------
__global__ __launch_bounds__(256, 2) void sgemm_bias_x2b(
    GemmBatch gb, int M, int N, int K, int relu, int permute)
{
    __shared__ float As[2][8][128];
    __shared__ float Bs[2][8][128];

    const int z = blockIdx.z;
    const float* __restrict__ A    = gb.A[z];
    const float* __restrict__ B    = gb.B[z];
    const float* __restrict__ bias = gb.bias[z];
    float* __restrict__ C          = gb.C[z];

    const int tid = threadIdx.x;
    const int bx = blockIdx.x, by = blockIdx.y;

    const int ar = tid >> 1;          // 0..127
    const int ac = (tid & 1) << 2;    // 0 or 4
    const int br = tid >> 5;          // 0..7
    const int bc = (tid & 31) << 2;   // 0..124

    const float* Ap = A + (long)(by * 128 + ar) * K + ac;
    const float* Bp = B + (long)br * N + bx * 128 + bc;

    float4 a4 = *(const float4*)Ap;
    float4 b4 = *(const float4*)Bp;
    As[0][ac + 0][ar] = a4.x; As[0][ac + 1][ar] = a4.y;
    As[0][ac + 2][ar] = a4.z; As[0][ac + 3][ar] = a4.w;
    *(float4*)&Bs[0][br][bc] = b4;
    __syncthreads();

    const int ty = tid >> 4, tx = tid & 15;

    u64 acc2[8][4];
#pragma unroll
    for (int m = 0; m < 8; m++)
#pragma unroll
        for (int n = 0; n < 4; n++) acc2[m][n] = 0ULL;

    const int nt = K >> 3;
    int buf = 0;
    for (int kt = 0; kt < nt; kt++) {
        if (kt + 1 < nt) {
            a4 = *(const float4*)(Ap + (kt + 1) * 8);
            b4 = *(const float4*)(Bp + (long)(kt + 1) * 8 * N);
        }
#pragma unroll
        for (int k = 0; k < 8; k++) {
            float af[8];
            u64 b2[4];
            *(float4*)&af[0] = *(const float4*)&As[buf][k][ty * 8];
            *(float4*)&af[4] = *(const float4*)&As[buf][k][ty * 8 + 4];
            *(ulonglong2*)&b2[0] = *(const ulonglong2*)&Bs[buf][k][tx * 8];
            *(ulonglong2*)&b2[2] = *(const ulonglong2*)&Bs[buf][k][tx * 8 + 4];
#pragma unroll
            for (int m = 0; m < 8; m++) {
                const u64 a2 = dup2(af[m]);
#pragma unroll
                for (int n = 0; n < 4; n++) ffma2(acc2[m][n], a2, b2[n]);
            }
        }
        if (kt + 1 < nt) {
            buf ^= 1;
            As[buf][ac + 0][ar] = a4.x; As[buf][ac + 1][ar] = a4.y;
            As[buf][ac + 2][ar] = a4.z; As[buf][ac + 3][ar] = a4.w;
            *(float4*)&Bs[buf][br][bc] = b4;
            __syncthreads();
        }
    }

    float bb[8];
#pragma unroll
    for (int n = 0; n < 8; n++) bb[n] = bias[bx * 128 + tx * 8 + n];

#pragma unroll
    for (int m = 0; m < 8; m++) {
        const int row = by * 128 + ty * 8 + m;
        float o[8];
#pragma unroll
        for (int n = 0; n < 4; n++) {
            float lo, hi;
            unpk2(lo, hi, acc2[m][n]);
            float v0 = lo + bb[2 * n], v1 = hi + bb[2 * n + 1];
            o[2 * n]     = relu ? fmaxf(v0, 0.f) : v0;
            o[2 * n + 1] = relu ? fmaxf(v1, 0.f) : v1;
        }
        if (permute) {
            // row = b*1024 + i ; f = bx*128 + tx*8 + n -> h = n, d = bx*16+tx
            const int b = row >> 10, i = row & 1023;
            const int d = bx * 16 + tx;
            float* yp = C + ((long)(b * 8) * 1024 + i) * 64 + d;
#pragma unroll
            for (int n = 0; n < 8; n++) yp[n * 65536] = o[n];
        } else {
            float* cp = C + (long)row * N + bx * 128 + tx * 8;
            *(float4*)(cp + 0) = make_float4(o[0], o[1], o[2], o[3]);
            *(float4*)(cp + 4) = make_float4(o[4], o[5], o[6], o[7]);
        }
    }
}

// ---------------------------------------------------------------------------
// Final projection GEMM: C[M,128] = A[M,512] @ B[512,128] + bias.
// Tile 32(M) x 64(N), grid (2, M/32) = 256 CTAs.
// ---------------------------------------------------------------------------
__global__ __launch_bounds__(256, 2) void sgemm_final(
    const float* __restrict__ A, const float* __restrict__ B,
    const float* __restrict__ bias, float* __restrict__ C,
    int M, int N, int K)
{
    __shared__ float As[16][32];
    __shared__ float Bs[16][64];

    const int tid = threadIdx.x;
    const int bx = blockIdx.x, by = blockIdx.y;

    const int ar = tid >> 3;          // 0..31
    const int ac = (tid & 7) << 1;    // 0..14 (2 cols each)
    const int brr = tid >> 4;         // 0..15
    const int bcc = (tid & 15) << 2;  // 0..60

    const float* Ap = A + (long)(by * 32 + ar) * K + ac;
    const float* Bp = B + (long)brr * N + bx * 64 + bcc;

    const int ty = tid >> 4, tx = tid & 15;

    u64 acc2[4];
#pragma unroll
    for (int n = 0; n < 4; n++) acc2[n] = 0ULL;

    const int nt = K >> 4;             // 32
    for (int kt = 0; kt < nt; kt++) {
        const float2 a2l = *(const float2*)(Ap + kt * 16);
        const float4 bv  = *(const float4*)(Bp + (long)kt * 16 * N);
        if (kt) __syncthreads();
        As[ac + 0][ar] = a2l.x;
        As[ac + 1][ar] = a2l.y;
        *(float4*)&Bs[brr][bcc] = bv;
        __syncthreads();
#pragma unroll
        for (int k = 0; k < 16; k++) {
            const u64 a2 = *(const u64*)&As[k][ty * 2];
            float bf[4];
            *(float4*)&bf[0] = *(const float4*)&Bs[k][tx * 4];
#pragma unroll
            for (int n = 0; n < 4; n++) ffma2(acc2[n], a2, dup2(bf[n]));
        }
    }

    const int j0 = by * 32 + ty * 2;
    const int c0 = bx * 64 + tx * 4;
#pragma unroll
    for (int n = 0; n < 4; n++) {
        float lo, hi;
        unpk2(lo, hi, acc2[n]);
        const float bb = bias[c0 + n];
        C[(long)j0 * N + c0 + n]       = lo + bb;
        C[(long)(j0 + 1) * N + c0 + n] = hi + bb;
    }
}

// ---------------------------------------------------------------------------
// Phase A1: distance-GEMM.  E[z][j][i] = exp(-0.5 * (sum_d |Q[z,j,d]-K[z,i,d]|)^2)
// Q duplicated in pairs (LDS.128 loads), K negated; abs on alu pipe.
// ---------------------------------------------------------------------------
__global__ __launch_bounds__(256, 2) void dist_exp_x2(
    const float* __restrict__ Qh, const float* __restrict__ Kh,
    float* __restrict__ E)
{
    __shared__ float Qs[16][256];   // duplicated pairs
    __shared__ float Ks[16][128];   // negated

    const int z   = blockIdx.z;
    const int tid = threadIdx.x;
    const int r   = tid >> 1;
    const int dc  = (tid & 1) << 3;
    const int ty  = tid >> 4, tx = tid & 15;

    const float* Qp = Qh + (long)(z * 1024 + blockIdx.y * 128 + r) * 64 + dc;
    const float* Kp = Kh + (long)(z * 1024 + blockIdx.x * 128 + r) * 64 + dc;

    u64 acc2[8][4];
#pragma unroll
    for (int m = 0; m < 8; m++)
#pragma unroll
        for (int n = 0; n < 4; n++) acc2[m][n] = 0ULL;

    for (int kt = 0; kt < 4; kt++) {
        const float4 q0 = *(const float4*)(Qp + kt * 16);
        const float4 q1 = *(const float4*)(Qp + kt * 16 + 4);
        const float4 k0 = *(const float4*)(Kp + kt * 16);
        const float4 k1 = *(const float4*)(Kp + kt * 16 + 4);
        if (kt) __syncthreads();
        float qv[8] = {q0.x, q0.y, q0.z, q0.w, q1.x, q1.y, q1.z, q1.w};
        float kv[8] = {k0.x, k0.y, k0.z, k0.w, k1.x, k1.y, k1.z, k1.w};
#pragma unroll
        for (int t = 0; t < 8; t++) {
            *(float2*)&Qs[dc + t][2 * r] = make_float2(qv[t], qv[t]);
            Ks[dc + t][r] = -kv[t];
        }
        __syncthreads();
#pragma unroll
        for (int k = 0; k < 16; k++) {
            u64 q2[8], k2[4];
            *(ulonglong2*)&q2[0] = *(const ulonglong2*)&Qs[k][2 * (ty * 8) + 0];
            *(ulonglong2*)&q2[2] = *(const ulonglong2*)&Qs[k][2 * (ty * 8) + 4];
            *(ulonglong2*)&q2[4] = *(const ulonglong2*)&Qs[k][2 * (ty * 8) + 8];
            *(ulonglong2*)&q2[6] = *(const ulonglong2*)&Qs[k][2 * (ty * 8) + 12];
            *(ulonglong2*)&k2[0] = *(const ulonglong2*)&Ks[k][tx * 8];
            *(ulonglong2*)&k2[2] = *(const ulonglong2*)&Ks[k][tx * 8 + 4];
#pragma unroll
            for (int m = 0; m < 8; m++)
#pragma unroll
                for (int n = 0; n < 4; n++) {
                    const u64 t2 = abs2(add2(q2[m], k2[n]));
                    acc2[m][n] = add2(acc2[m][n], t2);
                }
        }
    }

    const long base = ((long)(z * 1024 + blockIdx.y * 128 + ty * 8)) * 1024
                    + blockIdx.x * 128 + tx * 8;
#pragma unroll
    for (int m = 0; m < 8; m++) {
        float o[8];
#pragma unroll
        for (int n = 0; n < 4; n++) {
            float lo, hi;
            unpk2(lo, hi, acc2[m][n]);
            o[2 * n]     = __expf(-0.5f * lo * lo);
            o[2 * n + 1] = __expf(-0.5f * hi * hi);
        }
        *(float4*)(E + base + (long)m * 1024 + 0) = make_float4(o[0], o[1], o[2], o[3]);
        *(float4*)(E + base + (long)m * 1024 + 4) = make_float4(o[4], o[5], o[6], o[7]);
    }
}

// ---------------------------------------------------------------------------
// Phase A2: rdenom[b][j][i] = 1 / sum_h E[b*8+h][j][i]
// ---------------------------------------------------------------------------
__global__ __launch_bounds__(256) void denom_kernel(
    const float* __restrict__ E, float* __restrict__ rd)
{
    const int gid = blockIdx.x * 256 + threadIdx.x;  // 1048576 float4s
    const int b   = gid >> 18;
    const int rem = gid & ((1 << 18) - 1);
    const float4* Ep = (const float4*)E;
    float4 s = make_float4(0.f, 0.f, 0.f, 0.f);
#pragma unroll
    for (int h = 0; h < 8; h++) {
        const float4 v = Ep[(((long)(b * 8 + h)) << 18) + rem];
        s.x += v.x; s.y += v.y; s.z += v.z; s.w += v.w;
    }
    ((float4*)rd)[gid] = make_float4(1.f / s.x, 1.f / s.y, 1.f / s.z, 1.f / s.w);
}

// ---------------------------------------------------------------------------
// Phase B: out[b][j][d*8+h] = sum_i (E[z][j][i]*rd[b][j][i]) * V[z][i][d]
// 64-j tiles: grid (1,16,32) = 512 CTAs.
// ---------------------------------------------------------------------------
__global__ __launch_bounds__(256, 2) void attn_v_x2(
    const float* __restrict__ E, const float* __restrict__ rd,
    const float* __restrict__ Vh, float* __restrict__ Oo)
{
    __shared__ float As[16][64];
    __shared__ float Vs[16][64];

    const int z = blockIdx.z, b = z >> 3, h = z & 7;
    const int tid = threadIdx.x;
    const int jr = tid >> 2, ic = (tid & 3) << 2;     // A: j-row 0..63, i-col base
    const int vr = tid >> 4, vc = (tid & 15) << 2;    // V: i-row, d-col
    const int ty = tid >> 4, tx = tid & 15;

    const float* Ep = E  + ((long)(z * 1024 + blockIdx.y * 64 + jr)) * 1024 + ic;
    const float* Rp = rd + ((long)(b * 1024 + blockIdx.y * 64 + jr)) * 1024 + ic;
    const float* Vp = Vh + (long)(z * 1024 + vr) * 64 + vc;

    u64 acc2[2][4];   // [j-pair][d]
#pragma unroll
    for (int m = 0; m < 2; m++)
#pragma unroll
        for (int n = 0; n < 4; n++) acc2[m][n] = 0ULL;

    for (int kt = 0; kt < 64; kt++) {
        const float4 e0 = *(const float4*)(Ep + kt * 16);
        const float4 r0 = *(const float4*)(Rp + kt * 16);
        const float4 v4 = *(const float4*)(Vp + (long)kt * 16 * 64);
        if (kt) __syncthreads();
        As[ic + 0][jr] = e0.x * r0.x; As[ic + 1][jr] = e0.y * r0.y;
        As[ic + 2][jr] = e0.z * r0.z; As[ic + 3][jr] = e0.w * r0.w;
        *(float4*)&Vs[vr][vc] = v4;
        __syncthreads();
#pragma unroll
        for (int k = 0; k < 16; k++) {
            u64 a2[2];
            float vf[4];
            *(ulonglong2*)&a2[0] = *(const ulonglong2*)&As[k][ty * 4];
            *(float4*)&vf[0] = *(const float4*)&Vs[k][tx * 4];
#pragma unroll
            for (int n = 0; n < 4; n++) {
                const u64 v2 = dup2(vf[n]);
#pragma unroll
                for (int m = 0; m < 2; m++) ffma2(acc2[m][n], a2[m], v2);
            }
        }
    }

    const int j0 = blockIdx.y * 64 + ty * 4;
#pragma unroll
    for (int m = 0; m < 2; m++) {
        float* op0 = Oo + (long)(b * 1024 + j0 + 2 * m) * 512 + h;
        float* op1 = Oo + (long)(b * 1024 + j0 + 2 * m + 1) * 512 + h;
#pragma unroll
        for (int n = 0; n < 4; n++) {
            float lo, hi;
            unpk2(lo, hi, acc2[m][n]);
            op0[(tx * 4 + n) * 8] = lo;
            op1[(tx * 4 + n) * 8] = hi;
        }
    }
}

// ---------------------------------------------------------------------------
extern "C" void kernel_launch(void* const* d_in, const int* in_sizes, int n_in,
                              void* d_out, int out_size)
{
    const float* KEY   = (const float*)d_in[0];
    const float* VALUE = (const float*)d_in[1];
    const float* QUERY = (const float*)d_in[2];

    float *bufA, *bufB, *Kh, *Qh, *Vh, *E, *rd, *attn;
    cudaGetSymbolAddress((void**)&bufA, g_bufA);
    cudaGetSymbolAddress((void**)&bufB, g_bufB);
    cudaGetSymbolAddress((void**)&Kh,   g_Kh);
    cudaGetSymbolAddress((void**)&Qh,   g_Qh);
    cudaGetSymbolAddress((void**)&Vh,   g_Vh);
    cudaGetSymbolAddress((void**)&E,    g_E);
    cudaGetSymbolAddress((void**)&rd,   g_rd);
    cudaGetSymbolAddress((void**)&attn, g_attn);

    const dim3 blk(256);
    const dim3 gmlp(HH / 128, ROWS / 128, 3);   // (4, 32, 3) = 384 CTAs

    const float* X[3]  = {KEY, QUERY, VALUE};
    const int    wb[3] = {3, 9, 15};
    float* headed[3]   = {Kh, Qh, Vh};

    GemmBatch l1{}, l2{}, l3{};
    for (int z = 0; z < 3; z++) {
        l1.A[z] = X[z];
        l1.B[z] = (const float*)d_in[wb[z] + 0];
        l1.bias[z] = (const float*)d_in[wb[z] + 1];
        l1.C[z] = bufA + (long)z * RH;

        l2.A[z] = bufA + (long)z * RH;
        l2.B[z] = (const float*)d_in[wb[z] + 2];
        l2.bias[z] = (const float*)d_in[wb[z] + 3];
        l2.C[z] = bufB + (long)z * RH;

        l3.A[z] = bufB + (long)z * RH;
        l3.B[z] = (const float*)d_in[wb[z] + 4];
        l3.bias[z] = (const float*)d_in[wb[z] + 5];
        l3.C[z] = headed[z];
    }

    sgemm_bias_x2b<<<gmlp, blk>>>(l1, ROWS, HH, F,  1, 0);
    sgemm_bias_x2b<<<gmlp, blk>>>(l2, ROWS, HH, HH, 1, 0);
    sgemm_bias_x2b<<<gmlp, blk>>>(l3, ROWS, HH, HH, 0, 1);

    dist_exp_x2<<<dim3(8, 8, 32), blk>>>(Qh, Kh, E);
    denom_kernel<<<4096, blk>>>(E, rd);
    attn_v_x2<<<dim3(1, 16, 32), blk>>>(E, rd, Vh, attn);

    sgemm_final<<<dim3(OO / 64, ROWS / 32), blk>>>(
        attn, (const float*)d_in[21], (const float*)d_in[22],
        (float*)d_out, ROWS, OO, HH);
}

// round 9
// speedup vs baseline: 1.8195x; 1.1399x over previous
#include <cuda_runtime.h>
#include <cuda_bf16.h>
#include <cstdint>

// Problem constants
static constexpr int BB   = 4;
static constexpr int S    = 1024;
static constexpr int F    = 128;
static constexpr int HH   = 512;
static constexpr int OO   = 128;
static constexpr int ROWS = BB * S;         // 4096
static constexpr int RH   = ROWS * HH;

// ---------------- scratch (device globals) ----------------
__device__ __nv_bfloat16 g_XH[3 * ROWS * F];
__device__ __nv_bfloat16 g_XL[3 * ROWS * F];
__device__ __nv_bfloat16 g_W1H[3 * HH * F];    // transposed [n][k]
__device__ __nv_bfloat16 g_W1L[3 * HH * F];
__device__ __nv_bfloat16 g_W2H[3 * HH * HH];
__device__ __nv_bfloat16 g_W2L[3 * HH * HH];
__device__ __nv_bfloat16 g_W3H[3 * HH * HH];
__device__ __nv_bfloat16 g_W3L[3 * HH * HH];
__device__ __nv_bfloat16 g_C1H[3 * RH];
__device__ __nv_bfloat16 g_C1L[3 * RH];
__device__ __nv_bfloat16 g_C2H[3 * RH];
__device__ __nv_bfloat16 g_C2L[3 * RH];
__device__ float g_Kh[RH];                     // [b][h][i][d]
__device__ float g_Qh[RH];
__device__ float g_Vh[RH];
__device__ float g_E[(long)BB * 8 * S * S];    // [z][j][i]
__device__ float g_rd[(long)BB * S * S];       // [b][j][i]
__device__ float g_attn[RH];                   // [b][j][f=d*8+h]

// ---------------- packed f32x2 helpers ----------------
typedef unsigned long long u64;

__device__ __forceinline__ u64 dup2(float a) {
    u64 r;
    asm("mov.b64 %0, {%1, %1};" : "=l"(r) : "r"(__float_as_uint(a)));
    return r;
}
__device__ __forceinline__ void ffma2(u64& c, u64 a, u64 b) {
    asm("fma.rn.f32x2 %0, %1, %2, %0;" : "+l"(c) : "l"(a), "l"(b));
}
__device__ __forceinline__ u64 add2(u64 a, u64 b) {
    u64 d;
    asm("add.rn.f32x2 %0, %1, %2;" : "=l"(d) : "l"(a), "l"(b));
    return d;
}
__device__ __forceinline__ u64 abs2(u64 a) {
    u64 d;
    asm("and.b64 %0, %1, 0x7FFFFFFF7FFFFFFF;" : "=l"(d) : "l"(a));
    return d;
}
__device__ __forceinline__ void unpk2(float& lo, float& hi, u64 v) {
    unsigned int l, h;
    asm("mov.b64 {%0, %1}, %2;" : "=r"(l), "=r"(h) : "l"(v));
    lo = __uint_as_float(l);
    hi = __uint_as_float(h);
}

// ---------------- mma.sync helpers (base sm_80+ features) ----
__device__ __forceinline__ uint32_t smem_u32(const void* p) {
    uint32_t a;
    asm("{ .reg .u64 t; cvta.to.shared.u64 t, %1; cvt.u32.u64 %0, t; }"
        : "=r"(a) : "l"(p));
    return a;
}
__device__ __forceinline__ uint32_t swz(uint32_t x) { return x ^ ((x >> 3) & 0x70); }

__device__ __forceinline__ void ldsm4(uint32_t* r, uint32_t a) {
    asm volatile("ldmatrix.sync.aligned.m8n8.x4.shared.b16 {%0,%1,%2,%3}, [%4];"
                 : "=r"(r[0]), "=r"(r[1]), "=r"(r[2]), "=r"(r[3]) : "r"(a));
}
__device__ __forceinline__ void mma16816(float* c, const uint32_t* a,
                                         uint32_t b0, uint32_t b1) {
    asm volatile(
        "mma.sync.aligned.m16n8k16.row.col.f32.bf16.bf16.f32 "
        "{%0,%1,%2,%3}, {%4,%5,%6,%7}, {%8,%9}, {%0,%1,%2,%3};"
        : "+f"(c[0]), "+f"(c[1]), "+f"(c[2]), "+f"(c[3])
        : "r"(a[0]), "r"(a[1]), "r"(a[2]), "r"(a[3]), "r"(b0), "r"(b1));
}

// ---------------------------------------------------------------------------
// Pre-split input activations: X f32 -> (hi, lo) bf16, same layout.
// ---------------------------------------------------------------------------
__global__ __launch_bounds__(256) void split_x(
    const float* __restrict__ K_, const float* __restrict__ Q_,
    const float* __restrict__ V_)
{
    const int gid = blockIdx.x * 256 + threadIdx.x;
    const int per = ROWS * F / 4;
    const int z = gid / per, r = gid - z * per;
    const float* src = (z == 0) ? K_ : ((z == 1) ? Q_ : V_);
    const float4 v = ((const float4*)src)[r];
    float x[4] = {v.x, v.y, v.z, v.w};
    unsigned hp[2], lp[2];
#pragma unroll
    for (int p = 0; p < 2; p++) {
        __nv_bfloat16 h0 = __float2bfloat16(x[2 * p]);
        __nv_bfloat16 h1 = __float2bfloat16(x[2 * p + 1]);
        __nv_bfloat16 l0 = __float2bfloat16(x[2 * p] - __bfloat162float(h0));
        __nv_bfloat16 l1 = __float2bfloat16(x[2 * p + 1] - __bfloat162float(h1));
        hp[p] = ((unsigned)__bfloat16_as_ushort(h1) << 16) | __bfloat16_as_ushort(h0);
        lp[p] = ((unsigned)__bfloat16_as_ushort(l1) << 16) | __bfloat16_as_ushort(l0);
    }
    const long e0 = (long)z * (ROWS * F) + (long)r * 4;
    *(uint2*)(&g_XH[e0]) = make_uint2(hp[0], hp[1]);
    *(uint2*)(&g_XL[e0]) = make_uint2(lp[0], lp[1]);
}

// ---------------------------------------------------------------------------
// Weight transpose + split: W[K][512] f32 -> H/L [512][K] bf16.
// ---------------------------------------------------------------------------
struct WTJob { const float* W; __nv_bfloat16* H; __nv_bfloat16* L; int K; };
struct WTJobs { WTJob j[9]; };

__global__ __launch_bounds__(256) void wsplit(WTJobs js)
{
    const WTJob jb = js.j[blockIdx.z];
    const int K = jb.K;
    const int kb = blockIdx.y * 32;
    if (kb >= K) return;
    __shared__ float t[32][33];
    const int tx = threadIdx.x, ty = threadIdx.y;   // block (32, 8)
    const int n = blockIdx.x * 32 + tx;
#pragma unroll
    for (int jj = 0; jj < 32; jj += 8)
        t[ty + jj][tx] = jb.W[(long)(kb + ty + jj) * HH + n];
    __syncthreads();
    const int nn = blockIdx.x * 32 + ty;
    const int kk = kb + tx;
#pragma unroll
    for (int jj = 0; jj < 32; jj += 8) {
        const float v = t[tx][ty + jj];
        const __nv_bfloat16 h = __float2bfloat16(v);
        jb.H[(long)(nn + jj) * K + kk] = h;
        jb.L[(long)(nn + jj) * K + kk] = __float2bfloat16(v - __bfloat162float(h));
    }
}

// ---------------------------------------------------------------------------
// Split-bf16 MLP layer via mma.sync (HMMA path; compiles on plain sm_103).
// CTA = 128x128 tile, 8 warps (warp tile 32x64). K chunks of 64.
// D = (Ah+Al) @ (Wh+Wl)' with all 4 cross terms -> fp32-grade accuracy.
// mode 1: relu + split-bf16 output. mode 2: no relu, head-permute f32 output.
// ---------------------------------------------------------------------------
struct MmaL {
    const __nv_bfloat16 *Ah[3], *Al[3], *WH[3], *WL[3];
    const float* bias[3];
    __nv_bfloat16 *Ch[3], *Cl[3];
    float* P[3];
};

static constexpr int OFF_AH = 0;
static constexpr int OFF_AL = 16384;
static constexpr int OFF_WH = 32768;
static constexpr int OFF_WL = 49152;
static constexpr int SMEM_MMA = 65536;

__global__ __launch_bounds__(256, 2) void mlp_mma(MmaL p, int K, int mode)
{
    extern __shared__ char smem[];
    const uint32_t sb = smem_u32(smem);
    const int tid = threadIdx.x, wid = tid >> 5, lane = tid & 31;
    const int z = blockIdx.z, bx = blockIdx.x, by = blockIdx.y;

    const int m0 = (wid & 3) * 32;      // warp M offset in tile
    const int n0 = (wid >> 2) * 64;     // warp N offset in tile

    // global load mapping: 2 threads per row, 32 bf16 (64B) each
    const int arow = tid >> 1;
    const int aseg = (tid & 1);
    const __nv_bfloat16* Ahp = p.Ah[z] + (long)(by * 128 + arow) * K + aseg * 32;
    const __nv_bfloat16* Alp = p.Al[z] + (long)(by * 128 + arow) * K + aseg * 32;
    const __nv_bfloat16* WHp = p.WH[z] + (long)(bx * 128 + arow) * K + aseg * 32;
    const __nv_bfloat16* WLp = p.WL[z] + (long)(bx * 128 + arow) * K + aseg * 32;
    const uint32_t stbase = (uint32_t)(arow * 128 + aseg * 64);

    float acc[2][8][4];
#pragma unroll
    for (int mt = 0; mt < 2; mt++)
#pragma unroll
        for (int nt = 0; nt < 8; nt++)
#pragma unroll
            for (int q = 0; q < 4; q++) acc[mt][nt][q] = 0.f;

    const uint32_t rowa = lane & 15;
    const uint32_t segl = (lane >> 4) << 4;   // 0 or 16 bytes

    const int nchunks = K >> 6;
    for (int c = 0; c < nchunks; c++) {
        if (c) __syncthreads();
        {
            const int ge = c * 64;
#pragma unroll
            for (int i = 0; i < 4; i++) {
                const uint4 v = *(const uint4*)(Ahp + ge + i * 8);
                *(uint4*)(smem + OFF_AH + swz(stbase + i * 16)) = v;
            }
#pragma unroll
            for (int i = 0; i < 4; i++) {
                const uint4 v = *(const uint4*)(Alp + ge + i * 8);
                *(uint4*)(smem + OFF_AL + swz(stbase + i * 16)) = v;
            }
#pragma unroll
            for (int i = 0; i < 4; i++) {
                const uint4 v = *(const uint4*)(WHp + ge + i * 8);
                *(uint4*)(smem + OFF_WH + swz(stbase + i * 16)) = v;
            }
#pragma unroll
            for (int i = 0; i < 4; i++) {
                const uint4 v = *(const uint4*)(WLp + ge + i * 8);
                *(uint4*)(smem + OFF_WL + swz(stbase + i * 16)) = v;
            }
        }
        __syncthreads();

#pragma unroll
        for (int ks = 0; ks < 4; ks++) {
            uint32_t ah[2][4], al[2][4];
#pragma unroll
            for (int mt = 0; mt < 2; mt++) {
                const uint32_t off = (m0 + mt * 16 + rowa) * 128 + ks * 32 + segl;
                ldsm4(ah[mt], sb + OFF_AH + swz(off));
                ldsm4(al[mt], sb + OFF_AL + swz(off));
            }
#pragma unroll
            for (int ntp = 0; ntp < 4; ntp++) {
                uint32_t bh[4], bl[4];
                const uint32_t off = (n0 + ntp * 16 + rowa) * 128 + ks * 32 + segl;
                ldsm4(bh, sb + OFF_WH + swz(off));
                ldsm4(bl, sb + OFF_WL + swz(off));
#pragma unroll
                for (int mt = 0; mt < 2; mt++) {
                    float* C0 = acc[mt][2 * ntp];
                    float* C1 = acc[mt][2 * ntp + 1];
                    mma16816(C0, ah[mt], bh[0], bh[2]);
                    mma16816(C0, ah[mt], bl[0], bl[2]);
                    mma16816(C0, al[mt], bh[0], bh[2]);
                    mma16816(C0, al[mt], bl[0], bl[2]);
                    mma16816(C1, ah[mt], bh[1], bh[3]);
                    mma16816(C1, ah[mt], bl[1], bl[3]);
                    mma16816(C1, al[mt], bh[1], bh[3]);
                    mma16816(C1, al[mt], bl[1], bl[3]);
                }
            }
        }
    }

    // epilogue — NOTE: cn includes the bx*128 tile offset (R8 bug was dropping it)
    const float* bias = p.bias[z];
    const int grp = lane >> 2, qd = (lane & 3) * 2;
#pragma unroll
    for (int mt = 0; mt < 2; mt++) {
        const int r0 = by * 128 + m0 + mt * 16 + grp;
        const int r1 = r0 + 8;
#pragma unroll
        for (int nt = 0; nt < 8; nt++) {
            const int cn = bx * 128 + n0 + nt * 8 + qd;
            const float b0v = bias[cn], b1v = bias[cn + 1];
            float v00 = acc[mt][nt][0] + b0v;
            float v01 = acc[mt][nt][1] + b1v;
            float v10 = acc[mt][nt][2] + b0v;
            float v11 = acc[mt][nt][3] + b1v;
            if (mode == 1) {
                v00 = fmaxf(v00, 0.f); v01 = fmaxf(v01, 0.f);
                v10 = fmaxf(v10, 0.f); v11 = fmaxf(v11, 0.f);
                __nv_bfloat16* Ch = p.Ch[z];
                __nv_bfloat16* Cl = p.Cl[z];
                const __nv_bfloat16 h00 = __float2bfloat16(v00);
                const __nv_bfloat16 h01 = __float2bfloat16(v01);
                const __nv_bfloat16 h10 = __float2bfloat16(v10);
                const __nv_bfloat16 h11 = __float2bfloat16(v11);
                const __nv_bfloat16 l00 = __float2bfloat16(v00 - __bfloat162float(h00));
                const __nv_bfloat16 l01 = __float2bfloat16(v01 - __bfloat162float(h01));
                const __nv_bfloat16 l10 = __float2bfloat16(v10 - __bfloat162float(h10));
                const __nv_bfloat16 l11 = __float2bfloat16(v11 - __bfloat162float(h11));
                *(unsigned*)(Ch + (long)r0 * HH + cn) =
                    ((unsigned)__bfloat16_as_ushort(h01) << 16) | __bfloat16_as_ushort(h00);
                *(unsigned*)(Cl + (long)r0 * HH + cn) =
                    ((unsigned)__bfloat16_as_ushort(l01) << 16) | __bfloat16_as_ushort(l00);
                *(unsigned*)(Ch + (long)r1 * HH + cn) =
                    ((unsigned)__bfloat16_as_ushort(h11) << 16) | __bfloat16_as_ushort(h10);
                *(unsigned*)(Cl + (long)r1 * HH + cn) =
                    ((unsigned)__bfloat16_as_ushort(l11) << 16) | __bfloat16_as_ushort(l10);
            } else {
                float* P = p.P[z];
                const int b0r = r0 >> 10, i0 = r0 & 1023;
                const int b1r = r1 >> 10, i1 = r1 & 1023;
                const int h0 = cn & 7, d0 = cn >> 3;
                const int h1 = (cn + 1) & 7, d1 = (cn + 1) >> 3;
                P[((long)(b0r * 8 + h0) * 1024 + i0) * 64 + d0] = v00;
                P[((long)(b0r * 8 + h1) * 1024 + i0) * 64 + d1] = v01;
                P[((long)(b1r * 8 + h0) * 1024 + i1) * 64 + d0] = v10;
                P[((long)(b1r * 8 + h1) * 1024 + i1) * 64 + d1] = v11;
            }
        }
    }
}

// ---------------------------------------------------------------------------
// Phase A1: distance-GEMM (unchanged R5 winner).
// ---------------------------------------------------------------------------
__global__ __launch_bounds__(256, 2) void dist_exp_x2(
    const float* __restrict__ Qh, const float* __restrict__ Kh,
    float* __restrict__ E)
{
    __shared__ float Qs[16][256];
    __shared__ float Ks[16][128];

    const int z   = blockIdx.z;
    const int tid = threadIdx.x;
    const int r   = tid >> 1;
    const int dc  = (tid & 1) << 3;
    const int ty  = tid >> 4, tx = tid & 15;

    const float* Qp = Qh + (long)(z * 1024 + blockIdx.y * 128 + r) * 64 + dc;
    const float* Kp = Kh + (long)(z * 1024 + blockIdx.x * 128 + r) * 64 + dc;

    u64 acc2[8][4];
#pragma unroll
    for (int m = 0; m < 8; m++)
#pragma unroll
        for (int n = 0; n < 4; n++) acc2[m][n] = 0ULL;

    for (int kt = 0; kt < 4; kt++) {
        const float4 q0 = *(const float4*)(Qp + kt * 16);
        const float4 q1 = *(const float4*)(Qp + kt * 16 + 4);
        const float4 k0 = *(const float4*)(Kp + kt * 16);
        const float4 k1 = *(const float4*)(Kp + kt * 16 + 4);
        if (kt) __syncthreads();
        float qv[8] = {q0.x, q0.y, q0.z, q0.w, q1.x, q1.y, q1.z, q1.w};
        float kv[8] = {k0.x, k0.y, k0.z, k0.w, k1.x, k1.y, k1.z, k1.w};
#pragma unroll
        for (int t = 0; t < 8; t++) {
            *(float2*)&Qs[dc + t][2 * r] = make_float2(qv[t], qv[t]);
            Ks[dc + t][r] = -kv[t];
        }
        __syncthreads();
#pragma unroll
        for (int k = 0; k < 16; k++) {
            u64 q2[8], k2[4];
            *(ulonglong2*)&q2[0] = *(const ulonglong2*)&Qs[k][2 * (ty * 8) + 0];
            *(ulonglong2*)&q2[2] = *(const ulonglong2*)&Qs[k][2 * (ty * 8) + 4];
            *(ulonglong2*)&q2[4] = *(const ulonglong2*)&Qs[k][2 * (ty * 8) + 8];
            *(ulonglong2*)&q2[6] = *(const ulonglong2*)&Qs[k][2 * (ty * 8) + 12];
            *(ulonglong2*)&k2[0] = *(const ulonglong2*)&Ks[k][tx * 8];
            *(ulonglong2*)&k2[2] = *(const ulonglong2*)&Ks[k][tx * 8 + 4];
#pragma unroll
            for (int m = 0; m < 8; m++)
#pragma unroll
                for (int n = 0; n < 4; n++) {
                    const u64 t2 = abs2(add2(q2[m], k2[n]));
                    acc2[m][n] = add2(acc2[m][n], t2);
                }
        }
    }

    const long base = ((long)(z * 1024 + blockIdx.y * 128 + ty * 8)) * 1024
                    + blockIdx.x * 128 + tx * 8;
#pragma unroll
    for (int m = 0; m < 8; m++) {
        float o[8];
#pragma unroll
        for (int n = 0; n < 4; n++) {
            float lo, hi;
            unpk2(lo, hi, acc2[m][n]);
            o[2 * n]     = __expf(-0.5f * lo * lo);
            o[2 * n + 1] = __expf(-0.5f * hi * hi);
        }
        *(float4*)(E + base + (long)m * 1024 + 0) = make_float4(o[0], o[1], o[2], o[3]);
        *(float4*)(E + base + (long)m * 1024 + 4) = make_float4(o[4], o[5], o[6], o[7]);
    }
}

// ---------------------------------------------------------------------------
// Phase A2: rdenom (unchanged).
// ---------------------------------------------------------------------------
__global__ __launch_bounds__(256) void denom_kernel(
    const float* __restrict__ E, float* __restrict__ rd)
{
    const int gid = blockIdx.x * 256 + threadIdx.x;
    const int b   = gid >> 18;
    const int rem = gid & ((1 << 18) - 1);
    const float4* Ep = (const float4*)E;
    float4 s = make_float4(0.f, 0.f, 0.f, 0.f);
#pragma unroll
    for (int h = 0; h < 8; h++) {
        const float4 v = Ep[(((long)(b * 8 + h)) << 18) + rem];
        s.x += v.x; s.y += v.y; s.z += v.z; s.w += v.w;
    }
    ((float4*)rd)[gid] = make_float4(1.f / s.x, 1.f / s.y, 1.f / s.z, 1.f / s.w);
}

// ---------------------------------------------------------------------------
// Phase B: attn @ V (unchanged).
// ---------------------------------------------------------------------------
__global__ __launch_bounds__(256, 2) void attn_v_x2(
    const float* __restrict__ E, const float* __restrict__ rd,
    const float* __restrict__ Vh, float* __restrict__ Oo)
{
    __shared__ float As[16][64];
    __shared__ float Vs[16][64];

    const int z = blockIdx.z, b = z >> 3, h = z & 7;
    const int tid = threadIdx.x;
    const int jr = tid >> 2, ic = (tid & 3) << 2;
    const int vr = tid >> 4, vc = (tid & 15) << 2;
    const int ty = tid >> 4, tx = tid & 15;

    const float* Ep = E  + ((long)(z * 1024 + blockIdx.y * 64 + jr)) * 1024 + ic;
    const float* Rp = rd + ((long)(b * 1024 + blockIdx.y * 64 + jr)) * 1024 + ic;
    const float* Vp = Vh + (long)(z * 1024 + vr) * 64 + vc;

    u64 acc2[2][4];
#pragma unroll
    for (int m = 0; m < 2; m++)
#pragma unroll
        for (int n = 0; n < 4; n++) acc2[m][n] = 0ULL;

    for (int kt = 0; kt < 64; kt++) {
        const float4 e0 = *(const float4*)(Ep + kt * 16);
        const float4 r0 = *(const float4*)(Rp + kt * 16);
        const float4 v4 = *(const float4*)(Vp + (long)kt * 16 * 64);
        if (kt) __syncthreads();
        As[ic + 0][jr] = e0.x * r0.x; As[ic + 1][jr] = e0.y * r0.y;
        As[ic + 2][jr] = e0.z * r0.z; As[ic + 3][jr] = e0.w * r0.w;
        *(float4*)&Vs[vr][vc] = v4;
        __syncthreads();
#pragma unroll
        for (int k = 0; k < 16; k++) {
            u64 a2[2];
            float vf[4];
            *(ulonglong2*)&a2[0] = *(const ulonglong2*)&As[k][ty * 4];
            *(float4*)&vf[0] = *(const float4*)&Vs[k][tx * 4];
#pragma unroll
            for (int n = 0; n < 4; n++) {
                const u64 v2 = dup2(vf[n]);
#pragma unroll
                for (int m = 0; m < 2; m++) ffma2(acc2[m][n], a2[m], v2);
            }
        }
    }

    const int j0 = blockIdx.y * 64 + ty * 4;
#pragma unroll
    for (int m = 0; m < 2; m++) {
        float* op0 = Oo + (long)(b * 1024 + j0 + 2 * m) * 512 + h;
        float* op1 = Oo + (long)(b * 1024 + j0 + 2 * m + 1) * 512 + h;
#pragma unroll
        for (int n = 0; n < 4; n++) {
            float lo, hi;
            unpk2(lo, hi, acc2[m][n]);
            op0[(tx * 4 + n) * 8] = lo;
            op1[(tx * 4 + n) * 8] = hi;
        }
    }
}

// ---------------------------------------------------------------------------
// Final projection GEMM (unchanged).
// ---------------------------------------------------------------------------
__global__ __launch_bounds__(256, 2) void sgemm_final(
    const float* __restrict__ A, const float* __restrict__ B,
    const float* __restrict__ bias, float* __restrict__ C,
    int M, int N, int K)
{
    __shared__ float As[16][32];
    __shared__ float Bs[16][64];

    const int tid = threadIdx.x;
    const int bx = blockIdx.x, by = blockIdx.y;

    const int ar = tid >> 3;
    const int ac = (tid & 7) << 1;
    const int brr = tid >> 4;
    const int bcc = (tid & 15) << 2;

    const float* Ap = A + (long)(by * 32 + ar) * K + ac;
    const float* Bp = B + (long)brr * N + bx * 64 + bcc;

    const int ty = tid >> 4, tx = tid & 15;

    u64 acc2[4];
#pragma unroll
    for (int n = 0; n < 4; n++) acc2[n] = 0ULL;

    const int nt = K >> 4;
    for (int kt = 0; kt < nt; kt++) {
        const float2 a2l = *(const float2*)(Ap + kt * 16);
        const float4 bv  = *(const float4*)(Bp + (long)kt * 16 * N);
        if (kt) __syncthreads();
        As[ac + 0][ar] = a2l.x;
        As[ac + 1][ar] = a2l.y;
        *(float4*)&Bs[brr][bcc] = bv;
        __syncthreads();
#pragma unroll
        for (int k = 0; k < 16; k++) {
            const u64 a2 = *(const u64*)&As[k][ty * 2];
            float bf[4];
            *(float4*)&bf[0] = *(const float4*)&Bs[k][tx * 4];
#pragma unroll
            for (int n = 0; n < 4; n++) ffma2(acc2[n], a2, dup2(bf[n]));
        }
    }

    const int j0 = by * 32 + ty * 2;
    const int c0 = bx * 64 + tx * 4;
#pragma unroll
    for (int n = 0; n < 4; n++) {
        float lo, hi;
        unpk2(lo, hi, acc2[n]);
        const float bb = bias[c0 + n];
        C[(long)j0 * N + c0 + n]       = lo + bb;
        C[(long)(j0 + 1) * N + c0 + n] = hi + bb;
    }
}

// ---------------------------------------------------------------------------
extern "C" void kernel_launch(void* const* d_in, const int* in_sizes, int n_in,
                              void* d_out, int out_size)
{
    const float* KEY   = (const float*)d_in[0];
    const float* VALUE = (const float*)d_in[1];
    const float* QUERY = (const float*)d_in[2];

    float *Kh, *Qh, *Vh, *E, *rd, *attn;
    cudaGetSymbolAddress((void**)&Kh,   g_Kh);
    cudaGetSymbolAddress((void**)&Qh,   g_Qh);
    cudaGetSymbolAddress((void**)&Vh,   g_Vh);
    cudaGetSymbolAddress((void**)&E,    g_E);
    cudaGetSymbolAddress((void**)&rd,   g_rd);
    cudaGetSymbolAddress((void**)&attn, g_attn);

    __nv_bfloat16 *XH, *XL, *W1H, *W1L, *W2H, *W2L, *W3H, *W3L;
    __nv_bfloat16 *C1H, *C1L, *C2H, *C2L;
    cudaGetSymbolAddress((void**)&XH,  g_XH);
    cudaGetSymbolAddress((void**)&XL,  g_XL);
    cudaGetSymbolAddress((void**)&W1H, g_W1H);
    cudaGetSymbolAddress((void**)&W1L, g_W1L);
    cudaGetSymbolAddress((void**)&W2H, g_W2H);
    cudaGetSymbolAddress((void**)&W2L, g_W2L);
    cudaGetSymbolAddress((void**)&W3H, g_W3H);
    cudaGetSymbolAddress((void**)&W3L, g_W3L);
    cudaGetSymbolAddress((void**)&C1H, g_C1H);
    cudaGetSymbolAddress((void**)&C1L, g_C1L);
    cudaGetSymbolAddress((void**)&C2H, g_C2H);
    cudaGetSymbolAddress((void**)&C2L, g_C2L);

    cudaFuncSetAttribute(mlp_mma, cudaFuncAttributeMaxDynamicSharedMemorySize, SMEM_MMA);

    const dim3 blk(256);
    const int wb[3] = {3, 9, 15};   // K, Q, V weight base indices
    float* headed[3];
    headed[0] = Kh; headed[1] = Qh; headed[2] = Vh;

    split_x<<<3 * ROWS * F / 1024, blk>>>(KEY, QUERY, VALUE);

    WTJobs js{};
    for (int z = 0; z < 3; z++) {
        js.j[z * 3 + 0] = { (const float*)d_in[wb[z] + 0], W1H + (long)z * HH * F,
                            W1L + (long)z * HH * F,  F  };
        js.j[z * 3 + 1] = { (const float*)d_in[wb[z] + 2], W2H + (long)z * HH * HH,
                            W2L + (long)z * HH * HH, HH };
        js.j[z * 3 + 2] = { (const float*)d_in[wb[z] + 4], W3H + (long)z * HH * HH,
                            W3L + (long)z * HH * HH, HH };
    }
    wsplit<<<dim3(16, 16, 9), dim3(32, 8)>>>(js);

    MmaL l1{}, l2{}, l3{};
    for (int z = 0; z < 3; z++) {
        l1.Ah[z] = XH + (long)z * ROWS * F;
        l1.Al[z] = XL + (long)z * ROWS * F;
        l1.WH[z] = W1H + (long)z * HH * F;
        l1.WL[z] = W1L + (long)z * HH * F;
        l1.bias[z] = (const float*)d_in[wb[z] + 1];
        l1.Ch[z] = C1H + (long)z * RH;
        l1.Cl[z] = C1L + (long)z * RH;
        l1.P[z] = nullptr;

        l2.Ah[z] = C1H + (long)z * RH;
        l2.Al[z] = C1L + (long)z * RH;
        l2.WH[z] = W2H + (long)z * HH * HH;
        l2.WL[z] = W2L + (long)z * HH * HH;
        l2.bias[z] = (const float*)d_in[wb[z] + 3];
        l2.Ch[z] = C2H + (long)z * RH;
        l2.Cl[z] = C2L + (long)z * RH;
        l2.P[z] = nullptr;

        l3.Ah[z] = C2H + (long)z * RH;
        l3.Al[z] = C2L + (long)z * RH;
        l3.WH[z] = W3H + (long)z * HH * HH;
        l3.WL[z] = W3L + (long)z * HH * HH;
        l3.bias[z] = (const float*)d_in[wb[z] + 5];
        l3.Ch[z] = nullptr;
        l3.Cl[z] = nullptr;
        l3.P[z] = headed[z];
    }

    const dim3 gmma(HH / 128, ROWS / 128, 3);   // (4, 32, 3)
    mlp_mma<<<gmma, blk, SMEM_MMA>>>(l1, F,  1);
    mlp_mma<<<gmma, blk, SMEM_MMA>>>(l2, HH, 1);
    mlp_mma<<<gmma, blk, SMEM_MMA>>>(l3, HH, 2);

    dist_exp_x2<<<dim3(8, 8, 32), blk>>>(Qh, Kh, E);
    denom_kernel<<<4096, blk>>>(E, rd);
    attn_v_x2<<<dim3(1, 16, 32), blk>>>(E, rd, Vh, attn);

    sgemm_final<<<dim3(OO / 64, ROWS / 32), blk>>>(
        attn, (const float*)d_in[21], (const float*)d_in[22],
        (float*)d_out, ROWS, OO, HH);
}

// round 10
// speedup vs baseline: 1.9474x; 1.0703x over previous
#include <cuda_runtime.h>
#include <cuda_bf16.h>
#include <cstdint>

// Problem constants
static constexpr int BB   = 4;
static constexpr int S    = 1024;
static constexpr int F    = 128;
static constexpr int HH   = 512;
static constexpr int OO   = 128;
static constexpr int ROWS = BB * S;         // 4096
static constexpr int RH   = ROWS * HH;

// ---------------- scratch (device globals) ----------------
__device__ __nv_bfloat16 g_XH[3 * ROWS * F];
__device__ __nv_bfloat16 g_XL[3 * ROWS * F];
__device__ __nv_bfloat16 g_W1H[3 * HH * F];    // transposed [n][k]
__device__ __nv_bfloat16 g_W1L[3 * HH * F];
__device__ __nv_bfloat16 g_W2H[3 * HH * HH];
__device__ __nv_bfloat16 g_W2L[3 * HH * HH];
__device__ __nv_bfloat16 g_W3H[3 * HH * HH];
__device__ __nv_bfloat16 g_W3L[3 * HH * HH];
__device__ __nv_bfloat16 g_C1H[3 * RH];
__device__ __nv_bfloat16 g_C1L[3 * RH];
__device__ __nv_bfloat16 g_C2H[3 * RH];
__device__ __nv_bfloat16 g_C2L[3 * RH];
__device__ float g_Kh[RH];                     // [b][h][i][d]
__device__ float g_Qh[RH];
__device__ float g_Vh[RH];
__device__ float g_E[(long)BB * 8 * S * S];    // [z][j][i]
__device__ float g_rd[(long)BB * S * S];       // [b][j][i]
__device__ float g_attn[RH];                   // [b][j][f=d*8+h]

// ---------------- packed f32x2 helpers ----------------
typedef unsigned long long u64;

__device__ __forceinline__ u64 dup2(float a) {
    u64 r;
    asm("mov.b64 %0, {%1, %1};" : "=l"(r) : "r"(__float_as_uint(a)));
    return r;
}
__device__ __forceinline__ void ffma2(u64& c, u64 a, u64 b) {
    asm("fma.rn.f32x2 %0, %1, %2, %0;" : "+l"(c) : "l"(a), "l"(b));
}
__device__ __forceinline__ u64 add2(u64 a, u64 b) {
    u64 d;
    asm("add.rn.f32x2 %0, %1, %2;" : "=l"(d) : "l"(a), "l"(b));
    return d;
}
__device__ __forceinline__ u64 abs2(u64 a) {
    u64 d;
    asm("and.b64 %0, %1, 0x7FFFFFFF7FFFFFFF;" : "=l"(d) : "l"(a));
    return d;
}
__device__ __forceinline__ void unpk2(float& lo, float& hi, u64 v) {
    unsigned int l, h;
    asm("mov.b64 {%0, %1}, %2;" : "=r"(l), "=r"(h) : "l"(v));
    lo = __uint_as_float(l);
    hi = __uint_as_float(h);
}

// ---------------- mma.sync / cp.async helpers (base sm_80+ features) -------
__device__ __forceinline__ uint32_t smem_u32(const void* p) {
    uint32_t a;
    asm("{ .reg .u64 t; cvta.to.shared.u64 t, %1; cvt.u32.u64 %0, t; }"
        : "=r"(a) : "l"(p));
    return a;
}
__device__ __forceinline__ uint32_t swz(uint32_t x) { return x ^ ((x >> 3) & 0x70); }
__device__ __forceinline__ uint32_t swz64(uint32_t x) { return x ^ ((x >> 3) & 0x30); }

__device__ __forceinline__ void ldsm4(uint32_t* r, uint32_t a) {
    asm volatile("ldmatrix.sync.aligned.m8n8.x4.shared.b16 {%0,%1,%2,%3}, [%4];"
                 : "=r"(r[0]), "=r"(r[1]), "=r"(r[2]), "=r"(r[3]) : "r"(a));
}
__device__ __forceinline__ void mma16816(float* c, const uint32_t* a,
                                         uint32_t b0, uint32_t b1) {
    asm volatile(
        "mma.sync.aligned.m16n8k16.row.col.f32.bf16.bf16.f32 "
        "{%0,%1,%2,%3}, {%4,%5,%6,%7}, {%8,%9}, {%0,%1,%2,%3};"
        : "+f"(c[0]), "+f"(c[1]), "+f"(c[2]), "+f"(c[3])
        : "r"(a[0]), "r"(a[1]), "r"(a[2]), "r"(a[3]), "r"(b0), "r"(b1));
}
__device__ __forceinline__ void cpasync16(uint32_t s, const void* g) {
    asm volatile("cp.async.cg.shared.global [%0], [%1], 16;" :: "r"(s), "l"(g));
}
__device__ __forceinline__ void cpcommit() {
    asm volatile("cp.async.commit_group;" ::: "memory");
}
template <int N> __device__ __forceinline__ void cpwait() {
    asm volatile("cp.async.wait_group %0;" :: "n"(N) : "memory");
}

// ---------------------------------------------------------------------------
// Pre-split input activations: X f32 -> (hi, lo) bf16, same layout.
// ---------------------------------------------------------------------------
__global__ __launch_bounds__(256) void split_x(
    const float* __restrict__ K_, const float* __restrict__ Q_,
    const float* __restrict__ V_)
{
    const int gid = blockIdx.x * 256 + threadIdx.x;
    const int per = ROWS * F / 4;
    const int z = gid / per, r = gid - z * per;
    const float* src = (z == 0) ? K_ : ((z == 1) ? Q_ : V_);
    const float4 v = ((const float4*)src)[r];
    float x[4] = {v.x, v.y, v.z, v.w};
    unsigned hp[2], lp[2];
#pragma unroll
    for (int p = 0; p < 2; p++) {
        __nv_bfloat16 h0 = __float2bfloat16(x[2 * p]);
        __nv_bfloat16 h1 = __float2bfloat16(x[2 * p + 1]);
        __nv_bfloat16 l0 = __float2bfloat16(x[2 * p] - __bfloat162float(h0));
        __nv_bfloat16 l1 = __float2bfloat16(x[2 * p + 1] - __bfloat162float(h1));
        hp[p] = ((unsigned)__bfloat16_as_ushort(h1) << 16) | __bfloat16_as_ushort(h0);
        lp[p] = ((unsigned)__bfloat16_as_ushort(l1) << 16) | __bfloat16_as_ushort(l0);
    }
    const long e0 = (long)z * (ROWS * F) + (long)r * 4;
    *(uint2*)(&g_XH[e0]) = make_uint2(hp[0], hp[1]);
    *(uint2*)(&g_XL[e0]) = make_uint2(lp[0], lp[1]);
}

// ---------------------------------------------------------------------------
// Weight transpose + split: W[K][512] f32 -> H/L [512][K] bf16.
// ---------------------------------------------------------------------------
struct WTJob { const float* W; __nv_bfloat16* H; __nv_bfloat16* L; int K; };
struct WTJobs { WTJob j[9]; };

__global__ __launch_bounds__(256) void wsplit(WTJobs js)
{
    const WTJob jb = js.j[blockIdx.z];
    const int K = jb.K;
    const int kb = blockIdx.y * 32;
    if (kb >= K) return;
    __shared__ float t[32][33];
    const int tx = threadIdx.x, ty = threadIdx.y;   // block (32, 8)
    const int n = blockIdx.x * 32 + tx;
#pragma unroll
    for (int jj = 0; jj < 32; jj += 8)
        t[ty + jj][tx] = jb.W[(long)(kb + ty + jj) * HH + n];
    __syncthreads();
    const int nn = blockIdx.x * 32 + ty;
    const int kk = kb + tx;
#pragma unroll
    for (int jj = 0; jj < 32; jj += 8) {
        const float v = t[tx][ty + jj];
        const __nv_bfloat16 h = __float2bfloat16(v);
        jb.H[(long)(nn + jj) * K + kk] = h;
        jb.L[(long)(nn + jj) * K + kk] = __float2bfloat16(v - __bfloat162float(h));
    }
}

// ---------------------------------------------------------------------------
// Split-bf16 MLP layer via mma.sync, cp.async 3-stage pipeline.
// CTA = 128x128 tile, 8 warps (warp tile 32x64). Stage = 32 K-cols.
// D = Ah*Wh' + Ah*Wl' + Al*Wh' (Al*Wl ~2^-18, dropped).
// mode 1: relu + split-bf16 output. mode 2: no relu, head-permute f32 output.
// ---------------------------------------------------------------------------
struct MmaL {
    const __nv_bfloat16 *Ah[3], *Al[3], *WH[3], *WL[3];
    const float* bias[3];
    __nv_bfloat16 *Ch[3], *Cl[3];
    float* P[3];
};

// stage layout: AH +0, AL +8192, WH +16384, WL +24576 (each 128 rows x 64B)
static constexpr int STG_BYTES = 32768;
static constexpr int SMEM_MMA  = 3 * STG_BYTES;   // 98304

__global__ __launch_bounds__(256, 2) void mlp_mma(MmaL p, int K, int mode)
{
    extern __shared__ char smem[];
    const uint32_t sb = smem_u32(smem);
    const int tid = threadIdx.x, wid = tid >> 5, lane = tid & 31;
    const int z = blockIdx.z, bx = blockIdx.x, by = blockIdx.y;

    const int m0 = (wid & 3) * 32;      // warp M offset in tile
    const int n0 = (wid >> 2) * 64;     // warp N offset in tile

    // cp.async mapping: thread -> (row = tid>>1, 32B half-row = tid&1)
    const int row  = tid >> 1;
    const int hseg = tid & 1;
    const __nv_bfloat16* Ahp = p.Ah[z] + (long)(by * 128 + row) * K + hseg * 16;
    const __nv_bfloat16* Alp = p.Al[z] + (long)(by * 128 + row) * K + hseg * 16;
    const __nv_bfloat16* WHp = p.WH[z] + (long)(bx * 128 + row) * K + hseg * 16;
    const __nv_bfloat16* WLp = p.WL[z] + (long)(bx * 128 + row) * K + hseg * 16;
    const uint32_t st0 = (uint32_t)(row * 64 + hseg * 32);
    const uint32_t sA0 = swz64(st0), sA1 = swz64(st0 + 16);

    float acc[2][8][4];
#pragma unroll
    for (int mt = 0; mt < 2; mt++)
#pragma unroll
        for (int nt = 0; nt < 8; nt++)
#pragma unroll
            for (int q = 0; q < 4; q++) acc[mt][nt][q] = 0.f;

    const uint32_t rowa = lane & 15;
    const uint32_t segl = (lane >> 4) << 4;   // 0 or 16 bytes

    const int nst = K >> 5;                   // stages of 32 cols

    auto issue_stage = [&](int s, int st) {
        const uint32_t base = sb + (uint32_t)st * STG_BYTES;
        const int gc = s * 32;
        cpasync16(base + 0     + sA0, Ahp + gc);
        cpasync16(base + 0     + sA1, Ahp + gc + 8);
        cpasync16(base + 8192  + sA0, Alp + gc);
        cpasync16(base + 8192  + sA1, Alp + gc + 8);
        cpasync16(base + 16384 + sA0, WHp + gc);
        cpasync16(base + 16384 + sA1, WHp + gc + 8);
        cpasync16(base + 24576 + sA0, WLp + gc);
        cpasync16(base + 24576 + sA1, WLp + gc + 8);
    };

    issue_stage(0, 0); cpcommit();
    issue_stage(1, 1); cpcommit();

    int st = 0;
    for (int s = 0; s < nst; s++) {
        if (s == nst - 1) cpwait<0>(); else cpwait<1>();
        __syncthreads();
        if (s + 2 < nst) {
            int st2 = st + 2; if (st2 >= 3) st2 -= 3;
            issue_stage(s + 2, st2);
            cpcommit();
        }
        const uint32_t base = sb + (uint32_t)st * STG_BYTES;
#pragma unroll
        for (int ks = 0; ks < 2; ks++) {
            uint32_t ah[2][4], al[2][4];
#pragma unroll
            for (int mt = 0; mt < 2; mt++) {
                const uint32_t off = (m0 + mt * 16 + rowa) * 64 + ks * 32 + segl;
                ldsm4(ah[mt], base + swz64(off));
                ldsm4(al[mt], base + 8192 + swz64(off));
            }
#pragma unroll
            for (int ntp = 0; ntp < 4; ntp++) {
                uint32_t bh[4], bl[4];
                const uint32_t off = (n0 + ntp * 16 + rowa) * 64 + ks * 32 + segl;
                ldsm4(bh, base + 16384 + swz64(off));
                ldsm4(bl, base + 24576 + swz64(off));
#pragma unroll
                for (int mt = 0; mt < 2; mt++) {
                    float* C0 = acc[mt][2 * ntp];
                    float* C1 = acc[mt][2 * ntp + 1];
                    mma16816(C0, ah[mt], bh[0], bh[2]);
                    mma16816(C0, ah[mt], bl[0], bl[2]);
                    mma16816(C0, al[mt], bh[0], bh[2]);
                    mma16816(C1, ah[mt], bh[1], bh[3]);
                    mma16816(C1, ah[mt], bl[1], bl[3]);
                    mma16816(C1, al[mt], bh[1], bh[3]);
                }
            }
        }
        st++; if (st >= 3) st -= 3;
    }

    // epilogue — cn includes the bx*128 tile offset
    const float* bias = p.bias[z];
    const int grp = lane >> 2, qd = (lane & 3) * 2;
#pragma unroll
    for (int mt = 0; mt < 2; mt++) {
        const int r0 = by * 128 + m0 + mt * 16 + grp;
        const int r1 = r0 + 8;
#pragma unroll
        for (int nt = 0; nt < 8; nt++) {
            const int cn = bx * 128 + n0 + nt * 8 + qd;
            const float b0v = bias[cn], b1v = bias[cn + 1];
            float v00 = acc[mt][nt][0] + b0v;
            float v01 = acc[mt][nt][1] + b1v;
            float v10 = acc[mt][nt][2] + b0v;
            float v11 = acc[mt][nt][3] + b1v;
            if (mode == 1) {
                v00 = fmaxf(v00, 0.f); v01 = fmaxf(v01, 0.f);
                v10 = fmaxf(v10, 0.f); v11 = fmaxf(v11, 0.f);
                __nv_bfloat16* Ch = p.Ch[z];
                __nv_bfloat16* Cl = p.Cl[z];
                const __nv_bfloat16 h00 = __float2bfloat16(v00);
                const __nv_bfloat16 h01 = __float2bfloat16(v01);
                const __nv_bfloat16 h10 = __float2bfloat16(v10);
                const __nv_bfloat16 h11 = __float2bfloat16(v11);
                const __nv_bfloat16 l00 = __float2bfloat16(v00 - __bfloat162float(h00));
                const __nv_bfloat16 l01 = __float2bfloat16(v01 - __bfloat162float(h01));
                const __nv_bfloat16 l10 = __float2bfloat16(v10 - __bfloat162float(h10));
                const __nv_bfloat16 l11 = __float2bfloat16(v11 - __bfloat162float(h11));
                *(unsigned*)(Ch + (long)r0 * HH + cn) =
                    ((unsigned)__bfloat16_as_ushort(h01) << 16) | __bfloat16_as_ushort(h00);
                *(unsigned*)(Cl + (long)r0 * HH + cn) =
                    ((unsigned)__bfloat16_as_ushort(l01) << 16) | __bfloat16_as_ushort(l00);
                *(unsigned*)(Ch + (long)r1 * HH + cn) =
                    ((unsigned)__bfloat16_as_ushort(h11) << 16) | __bfloat16_as_ushort(h10);
                *(unsigned*)(Cl + (long)r1 * HH + cn) =
                    ((unsigned)__bfloat16_as_ushort(l11) << 16) | __bfloat16_as_ushort(l10);
            } else {
                float* P = p.P[z];
                const int b0r = r0 >> 10, i0 = r0 & 1023;
                const int b1r = r1 >> 10, i1 = r1 & 1023;
                const int h0 = cn & 7, d0 = cn >> 3;
                const int h1 = (cn + 1) & 7, d1 = (cn + 1) >> 3;
                P[((long)(b0r * 8 + h0) * 1024 + i0) * 64 + d0] = v00;
                P[((long)(b0r * 8 + h1) * 1024 + i0) * 64 + d1] = v01;
                P[((long)(b1r * 8 + h0) * 1024 + i1) * 64 + d0] = v10;
                P[((long)(b1r * 8 + h1) * 1024 + i1) * 64 + d1] = v11;
            }
        }
    }
}

// ---------------------------------------------------------------------------
// Phase A1: distance-GEMM (unchanged R5 winner).
// ---------------------------------------------------------------------------
__global__ __launch_bounds__(256, 2) void dist_exp_x2(
    const float* __restrict__ Qh, const float* __restrict__ Kh,
    float* __restrict__ E)
{
    __shared__ float Qs[16][256];
    __shared__ float Ks[16][128];

    const int z   = blockIdx.z;
    const int tid = threadIdx.x;
    const int r   = tid >> 1;
    const int dc  = (tid & 1) << 3;
    const int ty  = tid >> 4, tx = tid & 15;

    const float* Qp = Qh + (long)(z * 1024 + blockIdx.y * 128 + r) * 64 + dc;
    const float* Kp = Kh + (long)(z * 1024 + blockIdx.x * 128 + r) * 64 + dc;

    u64 acc2[8][4];
#pragma unroll
    for (int m = 0; m < 8; m++)
#pragma unroll
        for (int n = 0; n < 4; n++) acc2[m][n] = 0ULL;

    for (int kt = 0; kt < 4; kt++) {
        const float4 q0 = *(const float4*)(Qp + kt * 16);
        const float4 q1 = *(const float4*)(Qp + kt * 16 + 4);
        const float4 k0 = *(const float4*)(Kp + kt * 16);
        const float4 k1 = *(const float4*)(Kp + kt * 16 + 4);
        if (kt) __syncthreads();
        float qv[8] = {q0.x, q0.y, q0.z, q0.w, q1.x, q1.y, q1.z, q1.w};
        float kv[8] = {k0.x, k0.y, k0.z, k0.w, k1.x, k1.y, k1.z, k1.w};
#pragma unroll
        for (int t = 0; t < 8; t++) {
            *(float2*)&Qs[dc + t][2 * r] = make_float2(qv[t], qv[t]);
            Ks[dc + t][r] = -kv[t];
        }
        __syncthreads();
#pragma unroll
        for (int k = 0; k < 16; k++) {
            u64 q2[8], k2[4];
            *(ulonglong2*)&q2[0] = *(const ulonglong2*)&Qs[k][2 * (ty * 8) + 0];
            *(ulonglong2*)&q2[2] = *(const ulonglong2*)&Qs[k][2 * (ty * 8) + 4];
            *(ulonglong2*)&q2[4] = *(const ulonglong2*)&Qs[k][2 * (ty * 8) + 8];
            *(ulonglong2*)&q2[6] = *(const ulonglong2*)&Qs[k][2 * (ty * 8) + 12];
            *(ulonglong2*)&k2[0] = *(const ulonglong2*)&Ks[k][tx * 8];
            *(ulonglong2*)&k2[2] = *(const ulonglong2*)&Ks[k][tx * 8 + 4];
#pragma unroll
            for (int m = 0; m < 8; m++)
#pragma unroll
                for (int n = 0; n < 4; n++) {
                    const u64 t2 = abs2(add2(q2[m], k2[n]));
                    acc2[m][n] = add2(acc2[m][n], t2);
                }
        }
    }

    const long base = ((long)(z * 1024 + blockIdx.y * 128 + ty * 8)) * 1024
                    + blockIdx.x * 128 + tx * 8;
#pragma unroll
    for (int m = 0; m < 8; m++) {
        float o[8];
#pragma unroll
        for (int n = 0; n < 4; n++) {
            float lo, hi;
            unpk2(lo, hi, acc2[m][n]);
            o[2 * n]     = __expf(-0.5f * lo * lo);
            o[2 * n + 1] = __expf(-0.5f * hi * hi);
        }
        *(float4*)(E + base + (long)m * 1024 + 0) = make_float4(o[0], o[1], o[2], o[3]);
        *(float4*)(E + base + (long)m * 1024 + 4) = make_float4(o[4], o[5], o[6], o[7]);
    }
}

// ---------------------------------------------------------------------------
// Phase A2: rdenom (unchanged).
// ---------------------------------------------------------------------------
__global__ __launch_bounds__(256) void denom_kernel(
    const float* __restrict__ E, float* __restrict__ rd)
{
    const int gid = blockIdx.x * 256 + threadIdx.x;
    const int b   = gid >> 18;
    const int rem = gid & ((1 << 18) - 1);
    const float4* Ep = (const float4*)E;
    float4 s = make_float4(0.f, 0.f, 0.f, 0.f);
#pragma unroll
    for (int h = 0; h < 8; h++) {
        const float4 v = Ep[(((long)(b * 8 + h)) << 18) + rem];
        s.x += v.x; s.y += v.y; s.z += v.z; s.w += v.w;
    }
    ((float4*)rd)[gid] = make_float4(1.f / s.x, 1.f / s.y, 1.f / s.z, 1.f / s.w);
}

// ---------------------------------------------------------------------------
// Phase B: attn @ V (unchanged).
// ---------------------------------------------------------------------------
__global__ __launch_bounds__(256, 2) void attn_v_x2(
    const float* __restrict__ E, const float* __restrict__ rd,
    const float* __restrict__ Vh, float* __restrict__ Oo)
{
    __shared__ float As[16][64];
    __shared__ float Vs[16][64];

    const int z = blockIdx.z, b = z >> 3, h = z & 7;
    const int tid = threadIdx.x;
    const int jr = tid >> 2, ic = (tid & 3) << 2;
    const int vr = tid >> 4, vc = (tid & 15) << 2;
    const int ty = tid >> 4, tx = tid & 15;

    const float* Ep = E  + ((long)(z * 1024 + blockIdx.y * 64 + jr)) * 1024 + ic;
    const float* Rp = rd + ((long)(b * 1024 + blockIdx.y * 64 + jr)) * 1024 + ic;
    const float* Vp = Vh + (long)(z * 1024 + vr) * 64 + vc;

    u64 acc2[2][4];
#pragma unroll
    for (int m = 0; m < 2; m++)
#pragma unroll
        for (int n = 0; n < 4; n++) acc2[m][n] = 0ULL;

    for (int kt = 0; kt < 64; kt++) {
        const float4 e0 = *(const float4*)(Ep + kt * 16);
        const float4 r0 = *(const float4*)(Rp + kt * 16);
        const float4 v4 = *(const float4*)(Vp + (long)kt * 16 * 64);
        if (kt) __syncthreads();
        As[ic + 0][jr] = e0.x * r0.x; As[ic + 1][jr] = e0.y * r0.y;
        As[ic + 2][jr] = e0.z * r0.z; As[ic + 3][jr] = e0.w * r0.w;
        *(float4*)&Vs[vr][vc] = v4;
        __syncthreads();
#pragma unroll
        for (int k = 0; k < 16; k++) {
            u64 a2[2];
            float vf[4];
            *(ulonglong2*)&a2[0] = *(const ulonglong2*)&As[k][ty * 4];
            *(float4*)&vf[0] = *(const float4*)&Vs[k][tx * 4];
#pragma unroll
            for (int n = 0; n < 4; n++) {
                const u64 v2 = dup2(vf[n]);
#pragma unroll
                for (int m = 0; m < 2; m++) ffma2(acc2[m][n], a2[m], v2);
            }
        }
    }

    const int j0 = blockIdx.y * 64 + ty * 4;
#pragma unroll
    for (int m = 0; m < 2; m++) {
        float* op0 = Oo + (long)(b * 1024 + j0 + 2 * m) * 512 + h;
        float* op1 = Oo + (long)(b * 1024 + j0 + 2 * m + 1) * 512 + h;
#pragma unroll
        for (int n = 0; n < 4; n++) {
            float lo, hi;
            unpk2(lo, hi, acc2[m][n]);
            op0[(tx * 4 + n) * 8] = lo;
            op1[(tx * 4 + n) * 8] = hi;
        }
    }
}

// ---------------------------------------------------------------------------
// Final projection GEMM (unchanged).
// ---------------------------------------------------------------------------
__global__ __launch_bounds__(256, 2) void sgemm_final(
    const float* __restrict__ A, const float* __restrict__ B,
    const float* __restrict__ bias, float* __restrict__ C,
    int M, int N, int K)
{
    __shared__ float As[16][32];
    __shared__ float Bs[16][64];

    const int tid = threadIdx.x;
    const int bx = blockIdx.x, by = blockIdx.y;

    const int ar = tid >> 3;
    const int ac = (tid & 7) << 1;
    const int brr = tid >> 4;
    const int bcc = (tid & 15) << 2;

    const float* Ap = A + (long)(by * 32 + ar) * K + ac;
    const float* Bp = B + (long)brr * N + bx * 64 + bcc;

    const int ty = tid >> 4, tx = tid & 15;

    u64 acc2[4];
#pragma unroll
    for (int n = 0; n < 4; n++) acc2[n] = 0ULL;

    const int nt = K >> 4;
    for (int kt = 0; kt < nt; kt++) {
        const float2 a2l = *(const float2*)(Ap + kt * 16);
        const float4 bv  = *(const float4*)(Bp + (long)kt * 16 * N);
        if (kt) __syncthreads();
        As[ac + 0][ar] = a2l.x;
        As[ac + 1][ar] = a2l.y;
        *(float4*)&Bs[brr][bcc] = bv;
        __syncthreads();
#pragma unroll
        for (int k = 0; k < 16; k++) {
            const u64 a2 = *(const u64*)&As[k][ty * 2];
            float bf[4];
            *(float4*)&bf[0] = *(const float4*)&Bs[k][tx * 4];
#pragma unroll
            for (int n = 0; n < 4; n++) ffma2(acc2[n], a2, dup2(bf[n]));
        }
    }

    const int j0 = by * 32 + ty * 2;
    const int c0 = bx * 64 + tx * 4;
#pragma unroll
    for (int n = 0; n < 4; n++) {
        float lo, hi;
        unpk2(lo, hi, acc2[n]);
        const float bb = bias[c0 + n];
        C[(long)j0 * N + c0 + n]       = lo + bb;
        C[(long)(j0 + 1) * N + c0 + n] = hi + bb;
    }
}

// ---------------------------------------------------------------------------
extern "C" void kernel_launch(void* const* d_in, const int* in_sizes, int n_in,
                              void* d_out, int out_size)
{
    const float* KEY   = (const float*)d_in[0];
    const float* VALUE = (const float*)d_in[1];
    const float* QUERY = (const float*)d_in[2];

    float *Kh, *Qh, *Vh, *E, *rd, *attn;
    cudaGetSymbolAddress((void**)&Kh,   g_Kh);
    cudaGetSymbolAddress((void**)&Qh,   g_Qh);
    cudaGetSymbolAddress((void**)&Vh,   g_Vh);
    cudaGetSymbolAddress((void**)&E,    g_E);
    cudaGetSymbolAddress((void**)&rd,   g_rd);
    cudaGetSymbolAddress((void**)&attn, g_attn);

    __nv_bfloat16 *XH, *XL, *W1H, *W1L, *W2H, *W2L, *W3H, *W3L;
    __nv_bfloat16 *C1H, *C1L, *C2H, *C2L;
    cudaGetSymbolAddress((void**)&XH,  g_XH);
    cudaGetSymbolAddress((void**)&XL,  g_XL);
    cudaGetSymbolAddress((void**)&W1H, g_W1H);
    cudaGetSymbolAddress((void**)&W1L, g_W1L);
    cudaGetSymbolAddress((void**)&W2H, g_W2H);
    cudaGetSymbolAddress((void**)&W2L, g_W2L);
    cudaGetSymbolAddress((void**)&W3H, g_W3H);
    cudaGetSymbolAddress((void**)&W3L, g_W3L);
    cudaGetSymbolAddress((void**)&C1H, g_C1H);
    cudaGetSymbolAddress((void**)&C1L, g_C1L);
    cudaGetSymbolAddress((void**)&C2H, g_C2H);
    cudaGetSymbolAddress((void**)&C2L, g_C2L);

    cudaFuncSetAttribute(mlp_mma, cudaFuncAttributeMaxDynamicSharedMemorySize, SMEM_MMA);

    const dim3 blk(256);
    const int wb[3] = {3, 9, 15};   // K, Q, V weight base indices
    float* headed[3];
    headed[0] = Kh; headed[1] = Qh; headed[2] = Vh;

    split_x<<<3 * ROWS * F / 1024, blk>>>(KEY, QUERY, VALUE);

    WTJobs js{};
    for (int z = 0; z < 3; z++) {
        js.j[z * 3 + 0] = { (const float*)d_in[wb[z] + 0], W1H + (long)z * HH * F,
                            W1L + (long)z * HH * F,  F  };
        js.j[z * 3 + 1] = { (const float*)d_in[wb[z] + 2], W2H + (long)z * HH * HH,
                            W2L + (long)z * HH * HH, HH };
        js.j[z * 3 + 2] = { (const float*)d_in[wb[z] + 4], W3H + (long)z * HH * HH,
                            W3L + (long)z * HH * HH, HH };
    }
    wsplit<<<dim3(16, 16, 9), dim3(32, 8)>>>(js);

    MmaL l1{}, l2{}, l3{};
    for (int z = 0; z < 3; z++) {
        l1.Ah[z] = XH + (long)z * ROWS * F;
        l1.Al[z] = XL + (long)z * ROWS * F;
        l1.WH[z] = W1H + (long)z * HH * F;
        l1.WL[z] = W1L + (long)z * HH * F;
        l1.bias[z] = (const float*)d_in[wb[z] + 1];
        l1.Ch[z] = C1H + (long)z * RH;
        l1.Cl[z] = C1L + (long)z * RH;
        l1.P[z] = nullptr;

        l2.Ah[z] = C1H + (long)z * RH;
        l2.Al[z] = C1L + (long)z * RH;
        l2.WH[z] = W2H + (long)z * HH * HH;
        l2.WL[z] = W2L + (long)z * HH * HH;
        l2.bias[z] = (const float*)d_in[wb[z] + 3];
        l2.Ch[z] = C2H + (long)z * RH;
        l2.Cl[z] = C2L + (long)z * RH;
        l2.P[z] = nullptr;

        l3.Ah[z] = C2H + (long)z * RH;
        l3.Al[z] = C2L + (long)z * RH;
        l3.WH[z] = W3H + (long)z * HH * HH;
        l3.WL[z] = W3L + (long)z * HH * HH;
        l3.bias[z] = (const float*)d_in[wb[z] + 5];
        l3.Ch[z] = nullptr;
        l3.Cl[z] = nullptr;
        l3.P[z] = headed[z];
    }

    const dim3 gmma(HH / 128, ROWS / 128, 3);   // (4, 32, 3)
    mlp_mma<<<gmma, blk, SMEM_MMA>>>(l1, F,  1);
    mlp_mma<<<gmma, blk, SMEM_MMA>>>(l2, HH, 1);
    mlp_mma<<<gmma, blk, SMEM_MMA>>>(l3, HH, 2);

    dist_exp_x2<<<dim3(8, 8, 32), blk>>>(Qh, Kh, E);
    denom_kernel<<<4096, blk>>>(E, rd);
    attn_v_x2<<<dim3(1, 16, 32), blk>>>(E, rd, Vh, attn);

    sgemm_final<<<dim3(OO / 64, ROWS / 32), blk>>>(
        attn, (const float*)d_in[21], (const float*)d_in[22],
        (float*)d_out, ROWS, OO, HH);
}

// round 13
// speedup vs baseline: 1.9553x; 1.0040x over previous
#include <cuda_runtime.h>
#include <cuda_bf16.h>
#include <cstdint>

// Problem constants
static constexpr int BB   = 4;
static constexpr int S    = 1024;
static constexpr int F    = 128;
static constexpr int HH   = 512;
static constexpr int OO   = 128;
static constexpr int ROWS = BB * S;         // 4096
static constexpr int RH   = ROWS * HH;

// ---------------- scratch (device globals) ----------------
__device__ __nv_bfloat16 g_XH[3 * ROWS * F];
__device__ __nv_bfloat16 g_XL[3 * ROWS * F];
__device__ __nv_bfloat16 g_W1H[3 * HH * F];    // transposed [n][k]
__device__ __nv_bfloat16 g_W1L[3 * HH * F];
__device__ __nv_bfloat16 g_W2H[3 * HH * HH];
__device__ __nv_bfloat16 g_W2L[3 * HH * HH];
__device__ __nv_bfloat16 g_W3H[3 * HH * HH];
__device__ __nv_bfloat16 g_W3L[3 * HH * HH];
__device__ __nv_bfloat16 g_C1H[3 * RH];
__device__ __nv_bfloat16 g_C1L[3 * RH];
__device__ __nv_bfloat16 g_C2H[3 * RH];
__device__ __nv_bfloat16 g_C2L[3 * RH];
__device__ float g_Kh[RH];                     // [b][h][i][d]
__device__ float g_Qh[RH];
__device__ float g_Vh[RH];
__device__ float g_E[(long)BB * 8 * S * S];    // [z][j][i]
__device__ float g_rd[(long)BB * S * S];       // [b][j][i]
__device__ float g_attn[RH];                   // [b][j][f=d*8+h]

// ---------------- packed f32x2 helpers ----------------
typedef unsigned long long u64;

__device__ __forceinline__ u64 dup2(float a) {
    u64 r;
    asm("mov.b64 %0, {%1, %1};" : "=l"(r) : "r"(__float_as_uint(a)));
    return r;
}
__device__ __forceinline__ void ffma2(u64& c, u64 a, u64 b) {
    asm("fma.rn.f32x2 %0, %1, %2, %0;" : "+l"(c) : "l"(a), "l"(b));
}
__device__ __forceinline__ u64 add2(u64 a, u64 b) {
    u64 d;
    asm("add.rn.f32x2 %0, %1, %2;" : "=l"(d) : "l"(a), "l"(b));
    return d;
}
__device__ __forceinline__ u64 abs2(u64 a) {
    u64 d;
    asm("and.b64 %0, %1, 0x7FFFFFFF7FFFFFFF;" : "=l"(d) : "l"(a));
    return d;
}
__device__ __forceinline__ void unpk2(float& lo, float& hi, u64 v) {
    unsigned int l, h;
    asm("mov.b64 {%0, %1}, %2;" : "=r"(l), "=r"(h) : "l"(v));
    lo = __uint_as_float(l);
    hi = __uint_as_float(h);
}

// ---------------- mma.sync / cp.async helpers (base sm_80+ features) -------
__device__ __forceinline__ uint32_t smem_u32(const void* p) {
    uint32_t a;
    asm("{ .reg .u64 t; cvta.to.shared.u64 t, %1; cvt.u32.u64 %0, t; }"
        : "=r"(a) : "l"(p));
    return a;
}
__device__ __forceinline__ uint32_t swz64(uint32_t x) { return x ^ ((x >> 3) & 0x30); }

__device__ __forceinline__ void ldsm4(uint32_t* r, uint32_t a) {
    asm volatile("ldmatrix.sync.aligned.m8n8.x4.shared.b16 {%0,%1,%2,%3}, [%4];"
                 : "=r"(r[0]), "=r"(r[1]), "=r"(r[2]), "=r"(r[3]) : "r"(a));
}
__device__ __forceinline__ void mma16816(float* c, const uint32_t* a,
                                         uint32_t b0, uint32_t b1) {
    asm volatile(
        "mma.sync.aligned.m16n8k16.row.col.f32.bf16.bf16.f32 "
        "{%0,%1,%2,%3}, {%4,%5,%6,%7}, {%8,%9}, {%0,%1,%2,%3};"
        : "+f"(c[0]), "+f"(c[1]), "+f"(c[2]), "+f"(c[3])
        : "r"(a[0]), "r"(a[1]), "r"(a[2]), "r"(a[3]), "r"(b0), "r"(b1));
}
__device__ __forceinline__ void cpasync16(uint32_t s, const void* g) {
    asm volatile("cp.async.cg.shared.global [%0], [%1], 16;" :: "r"(s), "l"(g));
}
__device__ __forceinline__ void cpcommit() {
    asm volatile("cp.async.commit_group;" ::: "memory");
}
template <int N> __device__ __forceinline__ void cpwait() {
    asm volatile("cp.async.wait_group %0;" :: "n"(N) : "memory");
}

// ---------------------------------------------------------------------------
// Pre-split input activations: X f32 -> (hi, lo) bf16, same layout.
// ---------------------------------------------------------------------------
__global__ __launch_bounds__(256) void split_x(
    const float* __restrict__ K_, const float* __restrict__ Q_,
    const float* __restrict__ V_)
{
    const int gid = blockIdx.x * 256 + threadIdx.x;
    const int per = ROWS * F / 4;
    const int z = gid / per, r = gid - z * per;
    const float* src = (z == 0) ? K_ : ((z == 1) ? Q_ : V_);
    const float4 v = ((const float4*)src)[r];
    float x[4] = {v.x, v.y, v.z, v.w};
    unsigned hp[2], lp[2];
#pragma unroll
    for (int p = 0; p < 2; p++) {
        __nv_bfloat16 h0 = __float2bfloat16(x[2 * p]);
        __nv_bfloat16 h1 = __float2bfloat16(x[2 * p + 1]);
        __nv_bfloat16 l0 = __float2bfloat16(x[2 * p] - __bfloat162float(h0));
        __nv_bfloat16 l1 = __float2bfloat16(x[2 * p + 1] - __bfloat162float(h1));
        hp[p] = ((unsigned)__bfloat16_as_ushort(h1) << 16) | __bfloat16_as_ushort(h0);
        lp[p] = ((unsigned)__bfloat16_as_ushort(l1) << 16) | __bfloat16_as_ushort(l0);
    }
    const long e0 = (long)z * (ROWS * F) + (long)r * 4;
    *(uint2*)(&g_XH[e0]) = make_uint2(hp[0], hp[1]);
    *(uint2*)(&g_XL[e0]) = make_uint2(lp[0], lp[1]);
}

// ---------------------------------------------------------------------------
// Weight transpose + split: W[K][512] f32 -> H/L [512][K] bf16.
// ---------------------------------------------------------------------------
struct WTJob { const float* W; __nv_bfloat16* H; __nv_bfloat16* L; int K; };
struct WTJobs { WTJob j[9]; };

__global__ __launch_bounds__(256) void wsplit(WTJobs js)
{
    const WTJob jb = js.j[blockIdx.z];
    const int K = jb.K;
    const int kb = blockIdx.y * 32;
    if (kb >= K) return;
    __shared__ float t[32][33];
    const int tx = threadIdx.x, ty = threadIdx.y;   // block (32, 8)
    const int n = blockIdx.x * 32 + tx;
#pragma unroll
    for (int jj = 0; jj < 32; jj += 8)
        t[ty + jj][tx] = jb.W[(long)(kb + ty + jj) * HH + n];
    __syncthreads();
    const int nn = blockIdx.x * 32 + ty;
    const int kk = kb + tx;
#pragma unroll
    for (int jj = 0; jj < 32; jj += 8) {
        const float v = t[tx][ty + jj];
        const __nv_bfloat16 h = __float2bfloat16(v);
        jb.H[(long)(nn + jj) * K + kk] = h;
        jb.L[(long)(nn + jj) * K + kk] = __float2bfloat16(v - __bfloat162float(h));
    }
}

// ---------------------------------------------------------------------------
// Split-bf16 MLP layer via mma.sync, cp.async 3-stage pipeline (R10 winner).
// ---------------------------------------------------------------------------
struct MmaL {
    const __nv_bfloat16 *Ah[3], *Al[3], *WH[3], *WL[3];
    const float* bias[3];
    __nv_bfloat16 *Ch[3], *Cl[3];
    float* P[3];
};

static constexpr int STG_BYTES = 32768;
static constexpr int SMEM_MMA  = 3 * STG_BYTES;   // 98304

__global__ __launch_bounds__(256, 2) void mlp_mma(MmaL p, int K, int mode)
{
    extern __shared__ char smem[];
    const uint32_t sb = smem_u32(smem);
    const int tid = threadIdx.x, wid = tid >> 5, lane = tid & 31;
    const int z = blockIdx.z, bx = blockIdx.x, by = blockIdx.y;

    const int m0 = (wid & 3) * 32;      // warp M offset in tile
    const int n0 = (wid >> 2) * 64;     // warp N offset in tile

    const int row  = tid >> 1;
    const int hseg = tid & 1;
    const __nv_bfloat16* Ahp = p.Ah[z] + (long)(by * 128 + row) * K + hseg * 16;
    const __nv_bfloat16* Alp = p.Al[z] + (long)(by * 128 + row) * K + hseg * 16;
    const __nv_bfloat16* WHp = p.WH[z] + (long)(bx * 128 + row) * K + hseg * 16;
    const __nv_bfloat16* WLp = p.WL[z] + (long)(bx * 128 + row) * K + hseg * 16;
    const uint32_t st0 = (uint32_t)(row * 64 + hseg * 32);
    const uint32_t sA0 = swz64(st0), sA1 = swz64(st0 + 16);

    float acc[2][8][4];
#pragma unroll
    for (int mt = 0; mt < 2; mt++)
#pragma unroll
        for (int nt = 0; nt < 8; nt++)
#pragma unroll
            for (int q = 0; q < 4; q++) acc[mt][nt][q] = 0.f;

    const uint32_t rowa = lane & 15;
    const uint32_t segl = (lane >> 4) << 4;

    const int nst = K >> 5;

    auto issue_stage = [&](int s, int st) {
        const uint32_t base = sb + (uint32_t)st * STG_BYTES;
        const int gc = s * 32;
        cpasync16(base + 0     + sA0, Ahp + gc);
        cpasync16(base + 0     + sA1, Ahp + gc + 8);
        cpasync16(base + 8192  + sA0, Alp + gc);
        cpasync16(base + 8192  + sA1, Alp + gc + 8);
        cpasync16(base + 16384 + sA0, WHp + gc);
        cpasync16(base + 16384 + sA1, WHp + gc + 8);
        cpasync16(base + 24576 + sA0, WLp + gc);
        cpasync16(base + 24576 + sA1, WLp + gc + 8);
    };

    issue_stage(0, 0); cpcommit();
    issue_stage(1, 1); cpcommit();

    int st = 0;
    for (int s = 0; s < nst; s++) {
        if (s == nst - 1) cpwait<0>(); else cpwait<1>();
        __syncthreads();
        if (s + 2 < nst) {
            int st2 = st + 2; if (st2 >= 3) st2 -= 3;
            issue_stage(s + 2, st2);
            cpcommit();
        }
        const uint32_t base = sb + (uint32_t)st * STG_BYTES;
#pragma unroll
        for (int ks = 0; ks < 2; ks++) {
            uint32_t ah[2][4], al[2][4];
#pragma unroll
            for (int mt = 0; mt < 2; mt++) {
                const uint32_t off = (m0 + mt * 16 + rowa) * 64 + ks * 32 + segl;
                ldsm4(ah[mt], base + swz64(off));
                ldsm4(al[mt], base + 8192 + swz64(off));
            }
#pragma unroll
            for (int ntp = 0; ntp < 4; ntp++) {
                uint32_t bh[4], bl[4];
                const uint32_t off = (n0 + ntp * 16 + rowa) * 64 + ks * 32 + segl;
                ldsm4(bh, base + 16384 + swz64(off));
                ldsm4(bl, base + 24576 + swz64(off));
#pragma unroll
                for (int mt = 0; mt < 2; mt++) {
                    float* C0 = acc[mt][2 * ntp];
                    float* C1 = acc[mt][2 * ntp + 1];
                    mma16816(C0, ah[mt], bh[0], bh[2]);
                    mma16816(C0, ah[mt], bl[0], bl[2]);
                    mma16816(C0, al[mt], bh[0], bh[2]);
                    mma16816(C1, ah[mt], bh[1], bh[3]);
                    mma16816(C1, ah[mt], bl[1], bl[3]);
                    mma16816(C1, al[mt], bh[1], bh[3]);
                }
            }
        }
        st++; if (st >= 3) st -= 3;
    }

    // epilogue — cn includes the bx*128 tile offset
    const float* bias = p.bias[z];
    const int grp = lane >> 2, qd = (lane & 3) * 2;
#pragma unroll
    for (int mt = 0; mt < 2; mt++) {
        const int r0 = by * 128 + m0 + mt * 16 + grp;
        const int r1 = r0 + 8;
#pragma unroll
        for (int nt = 0; nt < 8; nt++) {
            const int cn = bx * 128 + n0 + nt * 8 + qd;
            const float b0v = bias[cn], b1v = bias[cn + 1];
            float v00 = acc[mt][nt][0] + b0v;
            float v01 = acc[mt][nt][1] + b1v;
            float v10 = acc[mt][nt][2] + b0v;
            float v11 = acc[mt][nt][3] + b1v;
            if (mode == 1) {
                v00 = fmaxf(v00, 0.f); v01 = fmaxf(v01, 0.f);
                v10 = fmaxf(v10, 0.f); v11 = fmaxf(v11, 0.f);
                __nv_bfloat16* Ch = p.Ch[z];
                __nv_bfloat16* Cl = p.Cl[z];
                const __nv_bfloat16 h00 = __float2bfloat16(v00);
                const __nv_bfloat16 h01 = __float2bfloat16(v01);
                const __nv_bfloat16 h10 = __float2bfloat16(v10);
                const __nv_bfloat16 h11 = __float2bfloat16(v11);
                const __nv_bfloat16 l00 = __float2bfloat16(v00 - __bfloat162float(h00));
                const __nv_bfloat16 l01 = __float2bfloat16(v01 - __bfloat162float(h01));
                const __nv_bfloat16 l10 = __float2bfloat16(v10 - __bfloat162float(h10));
                const __nv_bfloat16 l11 = __float2bfloat16(v11 - __bfloat162float(h11));
                *(unsigned*)(Ch + (long)r0 * HH + cn) =
                    ((unsigned)__bfloat16_as_ushort(h01) << 16) | __bfloat16_as_ushort(h00);
                *(unsigned*)(Cl + (long)r0 * HH + cn) =
                    ((unsigned)__bfloat16_as_ushort(l01) << 16) | __bfloat16_as_ushort(l00);
                *(unsigned*)(Ch + (long)r1 * HH + cn) =
                    ((unsigned)__bfloat16_as_ushort(h11) << 16) | __bfloat16_as_ushort(h10);
                *(unsigned*)(Cl + (long)r1 * HH + cn) =
                    ((unsigned)__bfloat16_as_ushort(l11) << 16) | __bfloat16_as_ushort(l10);
            } else {
                float* P = p.P[z];
                const int b0r = r0 >> 10, i0 = r0 & 1023;
                const int b1r = r1 >> 10, i1 = r1 & 1023;
                const int h0 = cn & 7, d0 = cn >> 3;
                const int h1 = (cn + 1) & 7, d1 = (cn + 1) >> 3;
                P[((long)(b0r * 8 + h0) * 1024 + i0) * 64 + d0] = v00;
                P[((long)(b0r * 8 + h1) * 1024 + i0) * 64 + d1] = v01;
                P[((long)(b1r * 8 + h0) * 1024 + i1) * 64 + d0] = v10;
                P[((long)(b1r * 8 + h1) * 1024 + i1) * 64 + d1] = v11;
            }
        }
    }
}

// ---------------------------------------------------------------------------
// Phase A1: distance-GEMM, retiled 64(j) x 128(i) for 3 CTAs/SM.
// E[z][j][i] = exp(-0.5 * (sum_d |Q[z,j,d]-K[z,i,d]|)^2)
// Q stored duplicated in pairs, K negated; abs on alu pipe.
// ---------------------------------------------------------------------------
__global__ __launch_bounds__(256, 3) void dist_exp_x2(
    const float* __restrict__ Qh, const float* __restrict__ Kh,
    float* __restrict__ E)
{
    __shared__ float Qs[16][128];   // 64 j rows, duplicated pairs
    __shared__ float Ks[16][128];   // 128 i rows, negated

    const int z   = blockIdx.z;
    const int tid = threadIdx.x;
    const int ty  = tid >> 4, tx = tid & 15;

    const int qr = tid >> 2;            // 0..63
    const int qc = (tid & 3) << 2;      // 0,4,8,12
    const int kr = tid >> 1;            // 0..127
    const int kc = (tid & 1) << 3;      // 0,8

    const float* Qp = Qh + (long)(z * 1024 + blockIdx.y * 64 + qr) * 64 + qc;
    const float* Kp = Kh + (long)(z * 1024 + blockIdx.x * 128 + kr) * 64 + kc;

    u64 acc2[4][4];
#pragma unroll
    for (int m = 0; m < 4; m++)
#pragma unroll
        for (int n = 0; n < 4; n++) acc2[m][n] = 0ULL;

    for (int kt = 0; kt < 4; kt++) {
        const float4 q4 = *(const float4*)(Qp + kt * 16);
        const float4 k0 = *(const float4*)(Kp + kt * 16);
        const float4 k1 = *(const float4*)(Kp + kt * 16 + 4);
        if (kt) __syncthreads();
        const float qv[4] = {q4.x, q4.y, q4.z, q4.w};
        const float kv[8] = {k0.x, k0.y, k0.z, k0.w, k1.x, k1.y, k1.z, k1.w};
#pragma unroll
        for (int t = 0; t < 4; t++)
            *(float2*)&Qs[qc + t][2 * qr] = make_float2(qv[t], qv[t]);
#pragma unroll
        for (int t = 0; t < 8; t++)
            Ks[kc + t][kr] = -kv[t];
        __syncthreads();
#pragma unroll
        for (int k = 0; k < 16; k++) {
            u64 q2[4], k2[4];
            *(ulonglong2*)&q2[0] = *(const ulonglong2*)&Qs[k][2 * (ty * 4) + 0];
            *(ulonglong2*)&q2[2] = *(const ulonglong2*)&Qs[k][2 * (ty * 4) + 4];
            *(ulonglong2*)&k2[0] = *(const ulonglong2*)&Ks[k][tx * 8];
            *(ulonglong2*)&k2[2] = *(const ulonglong2*)&Ks[k][tx * 8 + 4];
#pragma unroll
            for (int m = 0; m < 4; m++)
#pragma unroll
                for (int n = 0; n < 4; n++) {
                    const u64 t2 = abs2(add2(q2[m], k2[n]));
                    acc2[m][n] = add2(acc2[m][n], t2);
                }
        }
    }

    const long base = ((long)(z * 1024 + blockIdx.y * 64 + ty * 4)) * 1024
                    + blockIdx.x * 128 + tx * 8;
#pragma unroll
    for (int m = 0; m < 4; m++) {
        float o[8];
#pragma unroll
        for (int n = 0; n < 4; n++) {
            float lo, hi;
            unpk2(lo, hi, acc2[m][n]);
            o[2 * n]     = __expf(-0.5f * lo * lo);
            o[2 * n + 1] = __expf(-0.5f * hi * hi);
        }
        *(float4*)(E + base + (long)m * 1024 + 0) = make_float4(o[0], o[1], o[2], o[3]);
        *(float4*)(E + base + (long)m * 1024 + 4) = make_float4(o[4], o[5], o[6], o[7]);
    }
}

// ---------------------------------------------------------------------------
// Phase A2: rdenom (unchanged).
// ---------------------------------------------------------------------------
__global__ __launch_bounds__(256) void denom_kernel(
    const float* __restrict__ E, float* __restrict__ rd)
{
    const int gid = blockIdx.x * 256 + threadIdx.x;
    const int b   = gid >> 18;
    const int rem = gid & ((1 << 18) - 1);
    const float4* Ep = (const float4*)E;
    float4 s = make_float4(0.f, 0.f, 0.f, 0.f);
#pragma unroll
    for (int h = 0; h < 8; h++) {
        const float4 v = Ep[(((long)(b * 8 + h)) << 18) + rem];
        s.x += v.x; s.y += v.y; s.z += v.z; s.w += v.w;
    }
    ((float4*)rd)[gid] = make_float4(1.f / s.x, 1.f / s.y, 1.f / s.z, 1.f / s.w);
}

// ---------------------------------------------------------------------------
// Phase B: attn @ V (unchanged).
// ---------------------------------------------------------------------------
__global__ __launch_bounds__(256, 2) void attn_v_x2(
    const float* __restrict__ E, const float* __restrict__ rd,
    const float* __restrict__ Vh, float* __restrict__ Oo)
{
    __shared__ float As[16][64];
    __shared__ float Vs[16][64];

    const int z = blockIdx.z, b = z >> 3, h = z & 7;
    const int tid = threadIdx.x;
    const int jr = tid >> 2, ic = (tid & 3) << 2;
    const int vr = tid >> 4, vc = (tid & 15) << 2;
    const int ty = tid >> 4, tx = tid & 15;

    const float* Ep = E  + ((long)(z * 1024 + blockIdx.y * 64 + jr)) * 1024 + ic;
    const float* Rp = rd + ((long)(b * 1024 + blockIdx.y * 64 + jr)) * 1024 + ic;
    const float* Vp = Vh + (long)(z * 1024 + vr) * 64 + vc;

    u64 acc2[2][4];
#pragma unroll
    for (int m = 0; m < 2; m++)
#pragma unroll
        for (int n = 0; n < 4; n++) acc2[m][n] = 0ULL;

    for (int kt = 0; kt < 64; kt++) {
        const float4 e0 = *(const float4*)(Ep + kt * 16);
        const float4 r0 = *(const float4*)(Rp + kt * 16);
        const float4 v4 = *(const float4*)(Vp + (long)kt * 16 * 64);
        if (kt) __syncthreads();
        As[ic + 0][jr] = e0.x * r0.x; As[ic + 1][jr] = e0.y * r0.y;
        As[ic + 2][jr] = e0.z * r0.z; As[ic + 3][jr] = e0.w * r0.w;
        *(float4*)&Vs[vr][vc] = v4;
        __syncthreads();
#pragma unroll
        for (int k = 0; k < 16; k++) {
            u64 a2[2];
            float vf[4];
            *(ulonglong2*)&a2[0] = *(const ulonglong2*)&As[k][ty * 4];
            *(float4*)&vf[0] = *(const float4*)&Vs[k][tx * 4];
#pragma unroll
            for (int n = 0; n < 4; n++) {
                const u64 v2 = dup2(vf[n]);
#pragma unroll
                for (int m = 0; m < 2; m++) ffma2(acc2[m][n], a2[m], v2);
            }
        }
    }

    const int j0 = blockIdx.y * 64 + ty * 4;
#pragma unroll
    for (int m = 0; m < 2; m++) {
        float* op0 = Oo + (long)(b * 1024 + j0 + 2 * m) * 512 + h;
        float* op1 = Oo + (long)(b * 1024 + j0 + 2 * m + 1) * 512 + h;
#pragma unroll
        for (int n = 0; n < 4; n++) {
            float lo, hi;
            unpk2(lo, hi, acc2[m][n]);
            op0[(tx * 4 + n) * 8] = lo;
            op1[(tx * 4 + n) * 8] = hi;
        }
    }
}

// ---------------------------------------------------------------------------
// Final projection GEMM (unchanged).
// ---------------------------------------------------------------------------
__global__ __launch_bounds__(256, 2) void sgemm_final(
    const float* __restrict__ A, const float* __restrict__ B,
    const float* __restrict__ bias, float* __restrict__ C,
    int M, int N, int K)
{
    __shared__ float As[16][32];
    __shared__ float Bs[16][64];

    const int tid = threadIdx.x;
    const int bx = blockIdx.x, by = blockIdx.y;

    const int ar = tid >> 3;
    const int ac = (tid & 7) << 1;
    const int brr = tid >> 4;
    const int bcc = (tid & 15) << 2;

    const float* Ap = A + (long)(by * 32 + ar) * K + ac;
    const float* Bp = B + (long)brr * N + bx * 64 + bcc;

    const int ty = tid >> 4, tx = tid & 15;

    u64 acc2[4];
#pragma unroll
    for (int n = 0; n < 4; n++) acc2[n] = 0ULL;

    const int nt = K >> 4;
    for (int kt = 0; kt < nt; kt++) {
        const float2 a2l = *(const float2*)(Ap + kt * 16);
        const float4 bv  = *(const float4*)(Bp + (long)kt * 16 * N);
        if (kt) __syncthreads();
        As[ac + 0][ar] = a2l.x;
        As[ac + 1][ar] = a2l.y;
        *(float4*)&Bs[brr][bcc] = bv;
        __syncthreads();
#pragma unroll
        for (int k = 0; k < 16; k++) {
            const u64 a2 = *(const u64*)&As[k][ty * 2];
            float bf[4];
            *(float4*)&bf[0] = *(const float4*)&Bs[k][tx * 4];
#pragma unroll
            for (int n = 0; n < 4; n++) ffma2(acc2[n], a2, dup2(bf[n]));
        }
    }

    const int j0 = by * 32 + ty * 2;
    const int c0 = bx * 64 + tx * 4;
#pragma unroll
    for (int n = 0; n < 4; n++) {
        float lo, hi;
        unpk2(lo, hi, acc2[n]);
        const float bb = bias[c0 + n];
        C[(long)j0 * N + c0 + n]       = lo + bb;
        C[(long)(j0 + 1) * N + c0 + n] = hi + bb;
    }
}

// ---------------------------------------------------------------------------
extern "C" void kernel_launch(void* const* d_in, const int* in_sizes, int n_in,
                              void* d_out, int out_size)
{
    const float* KEY   = (const float*)d_in[0];
    const float* VALUE = (const float*)d_in[1];
    const float* QUERY = (const float*)d_in[2];

    float *Kh, *Qh, *Vh, *E, *rd, *attn;
    cudaGetSymbolAddress((void**)&Kh,   g_Kh);
    cudaGetSymbolAddress((void**)&Qh,   g_Qh);
    cudaGetSymbolAddress((void**)&Vh,   g_Vh);
    cudaGetSymbolAddress((void**)&E,    g_E);
    cudaGetSymbolAddress((void**)&rd,   g_rd);
    cudaGetSymbolAddress((void**)&attn, g_attn);

    __nv_bfloat16 *XH, *XL, *W1H, *W1L, *W2H, *W2L, *W3H, *W3L;
    __nv_bfloat16 *C1H, *C1L, *C2H, *C2L;
    cudaGetSymbolAddress((void**)&XH,  g_XH);
    cudaGetSymbolAddress((void**)&XL,  g_XL);
    cudaGetSymbolAddress((void**)&W1H, g_W1H);
    cudaGetSymbolAddress((void**)&W1L, g_W1L);
    cudaGetSymbolAddress((void**)&W2H, g_W2H);
    cudaGetSymbolAddress((void**)&W2L, g_W2L);
    cudaGetSymbolAddress((void**)&W3H, g_W3H);
    cudaGetSymbolAddress((void**)&W3L, g_W3L);
    cudaGetSymbolAddress((void**)&C1H, g_C1H);
    cudaGetSymbolAddress((void**)&C1L, g_C1L);
    cudaGetSymbolAddress((void**)&C2H, g_C2H);
    cudaGetSymbolAddress((void**)&C2L, g_C2L);

    cudaFuncSetAttribute(mlp_mma, cudaFuncAttributeMaxDynamicSharedMemorySize, SMEM_MMA);

    const dim3 blk(256);
    const int wb[3] = {3, 9, 15};   // K, Q, V weight base indices
    float* headed[3];
    headed[0] = Kh; headed[1] = Qh; headed[2] = Vh;

    split_x<<<3 * ROWS * F / 1024, blk>>>(KEY, QUERY, VALUE);

    WTJobs js{};
    for (int z = 0; z < 3; z++) {
        js.j[z * 3 + 0] = { (const float*)d_in[wb[z] + 0], W1H + (long)z * HH * F,
                            W1L + (long)z * HH * F,  F  };
        js.j[z * 3 + 1] = { (const float*)d_in[wb[z] + 2], W2H + (long)z * HH * HH,
                            W2L + (long)z * HH * HH, HH };
        js.j[z * 3 + 2] = { (const float*)d_in[wb[z] + 4], W3H + (long)z * HH * HH,
                            W3L + (long)z * HH * HH, HH };
    }
    wsplit<<<dim3(16, 16, 9), dim3(32, 8)>>>(js);

    MmaL l1{}, l2{}, l3{};
    for (int z = 0; z < 3; z++) {
        l1.Ah[z] = XH + (long)z * ROWS * F;
        l1.Al[z] = XL + (long)z * ROWS * F;
        l1.WH[z] = W1H + (long)z * HH * F;
        l1.WL[z] = W1L + (long)z * HH * F;
        l1.bias[z] = (const float*)d_in[wb[z] + 1];
        l1.Ch[z] = C1H + (long)z * RH;
        l1.Cl[z] = C1L + (long)z * RH;
        l1.P[z] = nullptr;

        l2.Ah[z] = C1H + (long)z * RH;
        l2.Al[z] = C1L + (long)z * RH;
        l2.WH[z] = W2H + (long)z * HH * HH;
        l2.WL[z] = W2L + (long)z * HH * HH;
        l2.bias[z] = (const float*)d_in[wb[z] + 3];
        l2.Ch[z] = C2H + (long)z * RH;
        l2.Cl[z] = C2L + (long)z * RH;
        l2.P[z] = nullptr;

        l3.Ah[z] = C2H + (long)z * RH;
        l3.Al[z] = C2L + (long)z * RH;
        l3.WH[z] = W3H + (long)z * HH * HH;
        l3.WL[z] = W3L + (long)z * HH * HH;
        l3.bias[z] = (const float*)d_in[wb[z] + 5];
        l3.Ch[z] = nullptr;
        l3.Cl[z] = nullptr;
        l3.P[z] = headed[z];
    }

    const dim3 gmma(HH / 128, ROWS / 128, 3);   // (4, 32, 3)
    mlp_mma<<<gmma, blk, SMEM_MMA>>>(l1, F,  1);
    mlp_mma<<<gmma, blk, SMEM_MMA>>>(l2, HH, 1);
    mlp_mma<<<gmma, blk, SMEM_MMA>>>(l3, HH, 2);

    dist_exp_x2<<<dim3(8, 16, 32), blk>>>(Qh, Kh, E);
    denom_kernel<<<4096, blk>>>(E, rd);
    attn_v_x2<<<dim3(1, 16, 32), blk>>>(E, rd, Vh, attn);

    sgemm_final<<<dim3(OO / 64, ROWS / 32), blk>>>(
        attn, (const float*)d_in[21], (const float*)d_in[22],
        (float*)d_out, ROWS, OO, HH);
}

// round 15
// speedup vs baseline: 2.0140x; 1.0300x over previous
#include <cuda_runtime.h>
#include <cuda_bf16.h>
#include <cstdint>

// Problem constants
static constexpr int BB   = 4;
static constexpr int S    = 1024;
static constexpr int F    = 128;
static constexpr int HH   = 512;
static constexpr int OO   = 128;
static constexpr int ROWS = BB * S;         // 4096
static constexpr int RH   = ROWS * HH;

// ---------------- scratch (device globals) ----------------
__device__ __nv_bfloat16 g_XH[3 * ROWS * F];
__device__ __nv_bfloat16 g_XL[3 * ROWS * F];
__device__ __nv_bfloat16 g_W1H[3 * HH * F];    // transposed [n][k]
__device__ __nv_bfloat16 g_W1L[3 * HH * F];
__device__ __nv_bfloat16 g_W2H[3 * HH * HH];
__device__ __nv_bfloat16 g_W2L[3 * HH * HH];
__device__ __nv_bfloat16 g_W3H[3 * HH * HH];
__device__ __nv_bfloat16 g_W3L[3 * HH * HH];
__device__ __nv_bfloat16 g_C1H[3 * RH];
__device__ __nv_bfloat16 g_C1L[3 * RH];
__device__ __nv_bfloat16 g_C2H[3 * RH];
__device__ __nv_bfloat16 g_C2L[3 * RH];
__device__ float g_Kh[RH];                     // [b][h][i][d]
__device__ float g_Qh[RH];
__device__ float g_Vh[RH];
__device__ float g_E[(long)BB * 8 * S * S];    // [z][j][i]
__device__ float g_rd[(long)BB * S * S];       // [b][j][i]
__device__ float g_attn[RH];                   // [b][j][f=d*8+h]

// ---------------- packed f32x2 helpers ----------------
typedef unsigned long long u64;

__device__ __forceinline__ u64 dup2(float a) {
    u64 r;
    asm("mov.b64 %0, {%1, %1};" : "=l"(r) : "r"(__float_as_uint(a)));
    return r;
}
__device__ __forceinline__ void ffma2(u64& c, u64 a, u64 b) {
    asm("fma.rn.f32x2 %0, %1, %2, %0;" : "+l"(c) : "l"(a), "l"(b));
}
__device__ __forceinline__ u64 add2(u64 a, u64 b) {
    u64 d;
    asm("add.rn.f32x2 %0, %1, %2;" : "=l"(d) : "l"(a), "l"(b));
    return d;
}
__device__ __forceinline__ u64 abs2(u64 a) {
    u64 d;
    asm("and.b64 %0, %1, 0x7FFFFFFF7FFFFFFF;" : "=l"(d) : "l"(a));
    return d;
}
__device__ __forceinline__ void unpk2(float& lo, float& hi, u64 v) {
    unsigned int l, h;
    asm("mov.b64 {%0, %1}, %2;" : "=r"(l), "=r"(h) : "l"(v));
    lo = __uint_as_float(l);
    hi = __uint_as_float(h);
}

// ---------------- mma.sync / cp.async helpers (base sm_80+ features) -------
__device__ __forceinline__ uint32_t smem_u32(const void* p) {
    uint32_t a;
    asm("{ .reg .u64 t; cvta.to.shared.u64 t, %1; cvt.u32.u64 %0, t; }"
        : "=r"(a) : "l"(p));
    return a;
}
__device__ __forceinline__ uint32_t swz64(uint32_t x) { return x ^ ((x >> 3) & 0x30); }

__device__ __forceinline__ void ldsm4(uint32_t* r, uint32_t a) {
    asm volatile("ldmatrix.sync.aligned.m8n8.x4.shared.b16 {%0,%1,%2,%3}, [%4];"
                 : "=r"(r[0]), "=r"(r[1]), "=r"(r[2]), "=r"(r[3]) : "r"(a));
}
__device__ __forceinline__ void mma16816(float* c, const uint32_t* a,
                                         uint32_t b0, uint32_t b1) {
    asm volatile(
        "mma.sync.aligned.m16n8k16.row.col.f32.bf16.bf16.f32 "
        "{%0,%1,%2,%3}, {%4,%5,%6,%7}, {%8,%9}, {%0,%1,%2,%3};"
        : "+f"(c[0]), "+f"(c[1]), "+f"(c[2]), "+f"(c[3])
        : "r"(a[0]), "r"(a[1]), "r"(a[2]), "r"(a[3]), "r"(b0), "r"(b1));
}
__device__ __forceinline__ void cpasync16(uint32_t s, const void* g) {
    asm volatile("cp.async.cg.shared.global [%0], [%1], 16;" :: "r"(s), "l"(g));
}
__device__ __forceinline__ void cpcommit() {
    asm volatile("cp.async.commit_group;" ::: "memory");
}
template <int N> __device__ __forceinline__ void cpwait() {
    asm volatile("cp.async.wait_group %0;" :: "n"(N) : "memory");
}

// ---------------------------------------------------------------------------
// Pre-split input activations: X f32 -> (hi, lo) bf16, same layout.
// ---------------------------------------------------------------------------
__global__ __launch_bounds__(256) void split_x(
    const float* __restrict__ K_, const float* __restrict__ Q_,
    const float* __restrict__ V_)
{
    const int gid = blockIdx.x * 256 + threadIdx.x;
    const int per = ROWS * F / 4;
    const int z = gid / per, r = gid - z * per;
    const float* src = (z == 0) ? K_ : ((z == 1) ? Q_ : V_);
    const float4 v = ((const float4*)src)[r];
    float x[4] = {v.x, v.y, v.z, v.w};
    unsigned hp[2], lp[2];
#pragma unroll
    for (int p = 0; p < 2; p++) {
        __nv_bfloat16 h0 = __float2bfloat16(x[2 * p]);
        __nv_bfloat16 h1 = __float2bfloat16(x[2 * p + 1]);
        __nv_bfloat16 l0 = __float2bfloat16(x[2 * p] - __bfloat162float(h0));
        __nv_bfloat16 l1 = __float2bfloat16(x[2 * p + 1] - __bfloat162float(h1));
        hp[p] = ((unsigned)__bfloat16_as_ushort(h1) << 16) | __bfloat16_as_ushort(h0);
        lp[p] = ((unsigned)__bfloat16_as_ushort(l1) << 16) | __bfloat16_as_ushort(l0);
    }
    const long e0 = (long)z * (ROWS * F) + (long)r * 4;
    *(uint2*)(&g_XH[e0]) = make_uint2(hp[0], hp[1]);
    *(uint2*)(&g_XL[e0]) = make_uint2(lp[0], lp[1]);
}

// ---------------------------------------------------------------------------
// Weight transpose + split: W[K][512] f32 -> H/L [512][K] bf16.
// ---------------------------------------------------------------------------
struct WTJob { const float* W; __nv_bfloat16* H; __nv_bfloat16* L; int K; };
struct WTJobs { WTJob j[9]; };

__global__ __launch_bounds__(256) void wsplit(WTJobs js)
{
    const WTJob jb = js.j[blockIdx.z];
    const int K = jb.K;
    const int kb = blockIdx.y * 32;
    if (kb >= K) return;
    __shared__ float t[32][33];
    const int tx = threadIdx.x, ty = threadIdx.y;   // block (32, 8)
    const int n = blockIdx.x * 32 + tx;
#pragma unroll
    for (int jj = 0; jj < 32; jj += 8)
        t[ty + jj][tx] = jb.W[(long)(kb + ty + jj) * HH + n];
    __syncthreads();
    const int nn = blockIdx.x * 32 + ty;
    const int kk = kb + tx;
#pragma unroll
    for (int jj = 0; jj < 32; jj += 8) {
        const float v = t[tx][ty + jj];
        const __nv_bfloat16 h = __float2bfloat16(v);
        jb.H[(long)(nn + jj) * K + kk] = h;
        jb.L[(long)(nn + jj) * K + kk] = __float2bfloat16(v - __bfloat162float(h));
    }
}

// ---------------------------------------------------------------------------
// Split-bf16 MLP layer via mma.sync, cp.async 3-stage pipeline (R10 winner).
// ---------------------------------------------------------------------------
struct MmaL {
    const __nv_bfloat16 *Ah[3], *Al[3], *WH[3], *WL[3];
    const float* bias[3];
    __nv_bfloat16 *Ch[3], *Cl[3];
    float* P[3];
};

static constexpr int STG_BYTES = 32768;
static constexpr int SMEM_MMA  = 3 * STG_BYTES;   // 98304

__global__ __launch_bounds__(256, 2) void mlp_mma(MmaL p, int K, int mode)
{
    extern __shared__ char smem[];
    const uint32_t sb = smem_u32(smem);
    const int tid = threadIdx.x, wid = tid >> 5, lane = tid & 31;
    const int z = blockIdx.z, bx = blockIdx.x, by = blockIdx.y;

    const int m0 = (wid & 3) * 32;      // warp M offset in tile
    const int n0 = (wid >> 2) * 64;     // warp N offset in tile

    const int row  = tid >> 1;
    const int hseg = tid & 1;
    const __nv_bfloat16* Ahp = p.Ah[z] + (long)(by * 128 + row) * K + hseg * 16;
    const __nv_bfloat16* Alp = p.Al[z] + (long)(by * 128 + row) * K + hseg * 16;
    const __nv_bfloat16* WHp = p.WH[z] + (long)(bx * 128 + row) * K + hseg * 16;
    const __nv_bfloat16* WLp = p.WL[z] + (long)(bx * 128 + row) * K + hseg * 16;
    const uint32_t st0 = (uint32_t)(row * 64 + hseg * 32);
    const uint32_t sA0 = swz64(st0), sA1 = swz64(st0 + 16);

    float acc[2][8][4];
#pragma unroll
    for (int mt = 0; mt < 2; mt++)
#pragma unroll
        for (int nt = 0; nt < 8; nt++)
#pragma unroll
            for (int q = 0; q < 4; q++) acc[mt][nt][q] = 0.f;

    const uint32_t rowa = lane & 15;
    const uint32_t segl = (lane >> 4) << 4;

    const int nst = K >> 5;

    auto issue_stage = [&](int s, int st) {
        const uint32_t base = sb + (uint32_t)st * STG_BYTES;
        const int gc = s * 32;
        cpasync16(base + 0     + sA0, Ahp + gc);
        cpasync16(base + 0     + sA1, Ahp + gc + 8);
        cpasync16(base + 8192  + sA0, Alp + gc);
        cpasync16(base + 8192  + sA1, Alp + gc + 8);
        cpasync16(base + 16384 + sA0, WHp + gc);
        cpasync16(base + 16384 + sA1, WHp + gc + 8);
        cpasync16(base + 24576 + sA0, WLp + gc);
        cpasync16(base + 24576 + sA1, WLp + gc + 8);
    };

    issue_stage(0, 0); cpcommit();
    issue_stage(1, 1); cpcommit();

    int st = 0;
    for (int s = 0; s < nst; s++) {
        if (s == nst - 1) cpwait<0>(); else cpwait<1>();
        __syncthreads();
        if (s + 2 < nst) {
            int st2 = st + 2; if (st2 >= 3) st2 -= 3;
            issue_stage(s + 2, st2);
            cpcommit();
        }
        const uint32_t base = sb + (uint32_t)st * STG_BYTES;
#pragma unroll
        for (int ks = 0; ks < 2; ks++) {
            uint32_t ah[2][4], al[2][4];
#pragma unroll
            for (int mt = 0; mt < 2; mt++) {
                const uint32_t off = (m0 + mt * 16 + rowa) * 64 + ks * 32 + segl;
                ldsm4(ah[mt], base + swz64(off));
                ldsm4(al[mt], base + 8192 + swz64(off));
            }
#pragma unroll
            for (int ntp = 0; ntp < 4; ntp++) {
                uint32_t bh[4], bl[4];
                const uint32_t off = (n0 + ntp * 16 + rowa) * 64 + ks * 32 + segl;
                ldsm4(bh, base + 16384 + swz64(off));
                ldsm4(bl, base + 24576 + swz64(off));
#pragma unroll
                for (int mt = 0; mt < 2; mt++) {
                    float* C0 = acc[mt][2 * ntp];
                    float* C1 = acc[mt][2 * ntp + 1];
                    mma16816(C0, ah[mt], bh[0], bh[2]);
                    mma16816(C0, ah[mt], bl[0], bl[2]);
                    mma16816(C0, al[mt], bh[0], bh[2]);
                    mma16816(C1, ah[mt], bh[1], bh[3]);
                    mma16816(C1, ah[mt], bl[1], bl[3]);
                    mma16816(C1, al[mt], bh[1], bh[3]);
                }
            }
        }
        st++; if (st >= 3) st -= 3;
    }

    // epilogue — cn includes the bx*128 tile offset
    const float* bias = p.bias[z];
    const int grp = lane >> 2, qd = (lane & 3) * 2;
#pragma unroll
    for (int mt = 0; mt < 2; mt++) {
        const int r0 = by * 128 + m0 + mt * 16 + grp;
        const int r1 = r0 + 8;
#pragma unroll
        for (int nt = 0; nt < 8; nt++) {
            const int cn = bx * 128 + n0 + nt * 8 + qd;
            const float b0v = bias[cn], b1v = bias[cn + 1];
            float v00 = acc[mt][nt][0] + b0v;
            float v01 = acc[mt][nt][1] + b1v;
            float v10 = acc[mt][nt][2] + b0v;
            float v11 = acc[mt][nt][3] + b1v;
            if (mode == 1) {
                v00 = fmaxf(v00, 0.f); v01 = fmaxf(v01, 0.f);
                v10 = fmaxf(v10, 0.f); v11 = fmaxf(v11, 0.f);
                __nv_bfloat16* Ch = p.Ch[z];
                __nv_bfloat16* Cl = p.Cl[z];
                const __nv_bfloat16 h00 = __float2bfloat16(v00);
                const __nv_bfloat16 h01 = __float2bfloat16(v01);
                const __nv_bfloat16 h10 = __float2bfloat16(v10);
                const __nv_bfloat16 h11 = __float2bfloat16(v11);
                const __nv_bfloat16 l00 = __float2bfloat16(v00 - __bfloat162float(h00));
                const __nv_bfloat16 l01 = __float2bfloat16(v01 - __bfloat162float(h01));
                const __nv_bfloat16 l10 = __float2bfloat16(v10 - __bfloat162float(h10));
                const __nv_bfloat16 l11 = __float2bfloat16(v11 - __bfloat162float(h11));
                *(unsigned*)(Ch + (long)r0 * HH + cn) =
                    ((unsigned)__bfloat16_as_ushort(h01) << 16) | __bfloat16_as_ushort(h00);
                *(unsigned*)(Cl + (long)r0 * HH + cn) =
                    ((unsigned)__bfloat16_as_ushort(l01) << 16) | __bfloat16_as_ushort(l00);
                *(unsigned*)(Ch + (long)r1 * HH + cn) =
                    ((unsigned)__bfloat16_as_ushort(h11) << 16) | __bfloat16_as_ushort(h10);
                *(unsigned*)(Cl + (long)r1 * HH + cn) =
                    ((unsigned)__bfloat16_as_ushort(l11) << 16) | __bfloat16_as_ushort(l10);
            } else {
                float* P = p.P[z];
                const int b0r = r0 >> 10, i0 = r0 & 1023;
                const int b1r = r1 >> 10, i1 = r1 & 1023;
                const int h0 = cn & 7, d0 = cn >> 3;
                const int h1 = (cn + 1) & 7, d1 = (cn + 1) >> 3;
                P[((long)(b0r * 8 + h0) * 1024 + i0) * 64 + d0] = v00;
                P[((long)(b0r * 8 + h1) * 1024 + i0) * 64 + d1] = v01;
                P[((long)(b1r * 8 + h0) * 1024 + i1) * 64 + d0] = v10;
                P[((long)(b1r * 8 + h1) * 1024 + i1) * 64 + d1] = v11;
            }
        }
    }
}

// ---------------------------------------------------------------------------
// Phase A1: distance-GEMM, 128x128 tile + next-kt register prefetch.
// E[z][j][i] = exp(-0.5 * (sum_d |Q[z,j,d]-K[z,i,d]|)^2)
// ---------------------------------------------------------------------------
__global__ __launch_bounds__(256, 2) void dist_exp_x2(
    const float* __restrict__ Qh, const float* __restrict__ Kh,
    float* __restrict__ E)
{
    __shared__ float Qs[16][256];   // duplicated pairs
    __shared__ float Ks[16][128];   // negated

    const int z   = blockIdx.z;
    const int tid = threadIdx.x;
    const int r   = tid >> 1;
    const int dc  = (tid & 1) << 3;
    const int ty  = tid >> 4, tx = tid & 15;

    const float* Qp = Qh + (long)(z * 1024 + blockIdx.y * 128 + r) * 64 + dc;
    const float* Kp = Kh + (long)(z * 1024 + blockIdx.x * 128 + r) * 64 + dc;

    u64 acc2[8][4];
#pragma unroll
    for (int m = 0; m < 8; m++)
#pragma unroll
        for (int n = 0; n < 4; n++) acc2[m][n] = 0ULL;

    // prefetch kt=0
    float4 q0 = *(const float4*)(Qp + 0);
    float4 q1 = *(const float4*)(Qp + 4);
    float4 k0 = *(const float4*)(Kp + 0);
    float4 k1 = *(const float4*)(Kp + 4);

    for (int kt = 0; kt < 4; kt++) {
        if (kt) __syncthreads();
        {
            const float qv[8] = {q0.x, q0.y, q0.z, q0.w, q1.x, q1.y, q1.z, q1.w};
            const float kv[8] = {k0.x, k0.y, k0.z, k0.w, k1.x, k1.y, k1.z, k1.w};
#pragma unroll
            for (int t = 0; t < 8; t++) {
                *(float2*)&Qs[dc + t][2 * r] = make_float2(qv[t], qv[t]);
                Ks[dc + t][r] = -kv[t];
            }
        }
        __syncthreads();
        if (kt < 3) {   // issue next-kt loads; latency covered by inner loop
            q0 = *(const float4*)(Qp + (kt + 1) * 16);
            q1 = *(const float4*)(Qp + (kt + 1) * 16 + 4);
            k0 = *(const float4*)(Kp + (kt + 1) * 16);
            k1 = *(const float4*)(Kp + (kt + 1) * 16 + 4);
        }
#pragma unroll
        for (int k = 0; k < 16; k++) {
            u64 q2[8], k2[4];
            *(ulonglong2*)&q2[0] = *(const ulonglong2*)&Qs[k][2 * (ty * 8) + 0];
            *(ulonglong2*)&q2[2] = *(const ulonglong2*)&Qs[k][2 * (ty * 8) + 4];
            *(ulonglong2*)&q2[4] = *(const ulonglong2*)&Qs[k][2 * (ty * 8) + 8];
            *(ulonglong2*)&q2[6] = *(const ulonglong2*)&Qs[k][2 * (ty * 8) + 12];
            *(ulonglong2*)&k2[0] = *(const ulonglong2*)&Ks[k][tx * 8];
            *(ulonglong2*)&k2[2] = *(const ulonglong2*)&Ks[k][tx * 8 + 4];
#pragma unroll
            for (int m = 0; m < 8; m++)
#pragma unroll
                for (int n = 0; n < 4; n++) {
                    const u64 t2 = abs2(add2(q2[m], k2[n]));
                    acc2[m][n] = add2(acc2[m][n], t2);
                }
        }
    }

    const long base = ((long)(z * 1024 + blockIdx.y * 128 + ty * 8)) * 1024
                    + blockIdx.x * 128 + tx * 8;
#pragma unroll
    for (int m = 0; m < 8; m++) {
        float o[8];
#pragma unroll
        for (int n = 0; n < 4; n++) {
            float lo, hi;
            unpk2(lo, hi, acc2[m][n]);
            o[2 * n]     = __expf(-0.5f * lo * lo);
            o[2 * n + 1] = __expf(-0.5f * hi * hi);
        }
        *(float4*)(E + base + (long)m * 1024 + 0) = make_float4(o[0], o[1], o[2], o[3]);
        *(float4*)(E + base + (long)m * 1024 + 4) = make_float4(o[4], o[5], o[6], o[7]);
    }
}

// ---------------------------------------------------------------------------
// Phase A2: rdenom (unchanged).
// ---------------------------------------------------------------------------
__global__ __launch_bounds__(256) void denom_kernel(
    const float* __restrict__ E, float* __restrict__ rd)
{
    const int gid = blockIdx.x * 256 + threadIdx.x;
    const int b   = gid >> 18;
    const int rem = gid & ((1 << 18) - 1);
    const float4* Ep = (const float4*)E;
    float4 s = make_float4(0.f, 0.f, 0.f, 0.f);
#pragma unroll
    for (int h = 0; h < 8; h++) {
        const float4 v = Ep[(((long)(b * 8 + h)) << 18) + rem];
        s.x += v.x; s.y += v.y; s.z += v.z; s.w += v.w;
    }
    ((float4*)rd)[gid] = make_float4(1.f / s.x, 1.f / s.y, 1.f / s.z, 1.f / s.w);
}

// ---------------------------------------------------------------------------
// Phase B: attn @ V, with next-kt register prefetch.
// ---------------------------------------------------------------------------
__global__ __launch_bounds__(256, 2) void attn_v_x2(
    const float* __restrict__ E, const float* __restrict__ rd,
    const float* __restrict__ Vh, float* __restrict__ Oo)
{
    __shared__ float As[16][64];
    __shared__ float Vs[16][64];

    const int z = blockIdx.z, b = z >> 3, h = z & 7;
    const int tid = threadIdx.x;
    const int jr = tid >> 2, ic = (tid & 3) << 2;
    const int vr = tid >> 4, vc = (tid & 15) << 2;
    const int ty = tid >> 4, tx = tid & 15;

    const float* Ep = E  + ((long)(z * 1024 + blockIdx.y * 64 + jr)) * 1024 + ic;
    const float* Rp = rd + ((long)(b * 1024 + blockIdx.y * 64 + jr)) * 1024 + ic;
    const float* Vp = Vh + (long)(z * 1024 + vr) * 64 + vc;

    u64 acc2[2][4];
#pragma unroll
    for (int m = 0; m < 2; m++)
#pragma unroll
        for (int n = 0; n < 4; n++) acc2[m][n] = 0ULL;

    // prefetch kt=0
    float4 e0 = *(const float4*)(Ep);
    float4 r0 = *(const float4*)(Rp);
    float4 v4 = *(const float4*)(Vp);

    for (int kt = 0; kt < 64; kt++) {
        if (kt) __syncthreads();
        As[ic + 0][jr] = e0.x * r0.x; As[ic + 1][jr] = e0.y * r0.y;
        As[ic + 2][jr] = e0.z * r0.z; As[ic + 3][jr] = e0.w * r0.w;
        *(float4*)&Vs[vr][vc] = v4;
        __syncthreads();
        if (kt < 63) {   // issue next-kt loads; latency covered by inner loop
            e0 = *(const float4*)(Ep + (kt + 1) * 16);
            r0 = *(const float4*)(Rp + (kt + 1) * 16);
            v4 = *(const float4*)(Vp + (long)(kt + 1) * 16 * 64);
        }
#pragma unroll
        for (int k = 0; k < 16; k++) {
            u64 a2[2];
            float vf[4];
            *(ulonglong2*)&a2[0] = *(const ulonglong2*)&As[k][ty * 4];
            *(float4*)&vf[0] = *(const float4*)&Vs[k][tx * 4];
#pragma unroll
            for (int n = 0; n < 4; n++) {
                const u64 v2 = dup2(vf[n]);
#pragma unroll
                for (int m = 0; m < 2; m++) ffma2(acc2[m][n], a2[m], v2);
            }
        }
    }

    const int j0 = blockIdx.y * 64 + ty * 4;
#pragma unroll
    for (int m = 0; m < 2; m++) {
        float* op0 = Oo + (long)(b * 1024 + j0 + 2 * m) * 512 + h;
        float* op1 = Oo + (long)(b * 1024 + j0 + 2 * m + 1) * 512 + h;
#pragma unroll
        for (int n = 0; n < 4; n++) {
            float lo, hi;
            unpk2(lo, hi, acc2[m][n]);
            op0[(tx * 4 + n) * 8] = lo;
            op1[(tx * 4 + n) * 8] = hi;
        }
    }
}

// ---------------------------------------------------------------------------
// Final projection GEMM (unchanged).
// ---------------------------------------------------------------------------
__global__ __launch_bounds__(256, 2) void sgemm_final(
    const float* __restrict__ A, const float* __restrict__ B,
    const float* __restrict__ bias, float* __restrict__ C,
    int M, int N, int K)
{
    __shared__ float As[16][32];
    __shared__ float Bs[16][64];

    const int tid = threadIdx.x;
    const int bx = blockIdx.x, by = blockIdx.y;

    const int ar = tid >> 3;
    const int ac = (tid & 7) << 1;
    const int brr = tid >> 4;
    const int bcc = (tid & 15) << 2;

    const float* Ap = A + (long)(by * 32 + ar) * K + ac;
    const float* Bp = B + (long)brr * N + bx * 64 + bcc;

    const int ty = tid >> 4, tx = tid & 15;

    u64 acc2[4];
#pragma unroll
    for (int n = 0; n < 4; n++) acc2[n] = 0ULL;

    const int nt = K >> 4;
    for (int kt = 0; kt < nt; kt++) {
        const float2 a2l = *(const float2*)(Ap + kt * 16);
        const float4 bv  = *(const float4*)(Bp + (long)kt * 16 * N);
        if (kt) __syncthreads();
        As[ac + 0][ar] = a2l.x;
        As[ac + 1][ar] = a2l.y;
        *(float4*)&Bs[brr][bcc] = bv;
        __syncthreads();
#pragma unroll
        for (int k = 0; k < 16; k++) {
            const u64 a2 = *(const u64*)&As[k][ty * 2];
            float bf[4];
            *(float4*)&bf[0] = *(const float4*)&Bs[k][tx * 4];
#pragma unroll
            for (int n = 0; n < 4; n++) ffma2(acc2[n], a2, dup2(bf[n]));
        }
    }

    const int j0 = by * 32 + ty * 2;
    const int c0 = bx * 64 + tx * 4;
#pragma unroll
    for (int n = 0; n < 4; n++) {
        float lo, hi;
        unpk2(lo, hi, acc2[n]);
        const float bb = bias[c0 + n];
        C[(long)j0 * N + c0 + n]       = lo + bb;
        C[(long)(j0 + 1) * N + c0 + n] = hi + bb;
    }
}

// ---------------------------------------------------------------------------
extern "C" void kernel_launch(void* const* d_in, const int* in_sizes, int n_in,
                              void* d_out, int out_size)
{
    const float* KEY   = (const float*)d_in[0];
    const float* VALUE = (const float*)d_in[1];
    const float* QUERY = (const float*)d_in[2];

    float *Kh, *Qh, *Vh, *E, *rd, *attn;
    cudaGetSymbolAddress((void**)&Kh,   g_Kh);
    cudaGetSymbolAddress((void**)&Qh,   g_Qh);
    cudaGetSymbolAddress((void**)&Vh,   g_Vh);
    cudaGetSymbolAddress((void**)&E,    g_E);
    cudaGetSymbolAddress((void**)&rd,   g_rd);
    cudaGetSymbolAddress((void**)&attn, g_attn);

    __nv_bfloat16 *XH, *XL, *W1H, *W1L, *W2H, *W2L, *W3H, *W3L;
    __nv_bfloat16 *C1H, *C1L, *C2H, *C2L;
    cudaGetSymbolAddress((void**)&XH,  g_XH);
    cudaGetSymbolAddress((void**)&XL,  g_XL);
    cudaGetSymbolAddress((void**)&W1H, g_W1H);
    cudaGetSymbolAddress((void**)&W1L, g_W1L);
    cudaGetSymbolAddress((void**)&W2H, g_W2H);
    cudaGetSymbolAddress((void**)&W2L, g_W2L);
    cudaGetSymbolAddress((void**)&W3H, g_W3H);
    cudaGetSymbolAddress((void**)&W3L, g_W3L);
    cudaGetSymbolAddress((void**)&C1H, g_C1H);
    cudaGetSymbolAddress((void**)&C1L, g_C1L);
    cudaGetSymbolAddress((void**)&C2H, g_C2H);
    cudaGetSymbolAddress((void**)&C2L, g_C2L);

    cudaFuncSetAttribute(mlp_mma, cudaFuncAttributeMaxDynamicSharedMemorySize, SMEM_MMA);

    const dim3 blk(256);
    const int wb[3] = {3, 9, 15};   // K, Q, V weight base indices
    float* headed[3];
    headed[0] = Kh; headed[1] = Qh; headed[2] = Vh;

    split_x<<<3 * ROWS * F / 1024, blk>>>(KEY, QUERY, VALUE);

    WTJobs js{};
    for (int z = 0; z < 3; z++) {
        js.j[z * 3 + 0] = { (const float*)d_in[wb[z] + 0], W1H + (long)z * HH * F,
                            W1L + (long)z * HH * F,  F  };
        js.j[z * 3 + 1] = { (const float*)d_in[wb[z] + 2], W2H + (long)z * HH * HH,
                            W2L + (long)z * HH * HH, HH };
        js.j[z * 3 + 2] = { (const float*)d_in[wb[z] + 4], W3H + (long)z * HH * HH,
                            W3L + (long)z * HH * HH, HH };
    }
    wsplit<<<dim3(16, 16, 9), dim3(32, 8)>>>(js);

    MmaL l1{}, l2{}, l3{};
    for (int z = 0; z < 3; z++) {
        l1.Ah[z] = XH + (long)z * ROWS * F;
        l1.Al[z] = XL + (long)z * ROWS * F;
        l1.WH[z] = W1H + (long)z * HH * F;
        l1.WL[z] = W1L + (long)z * HH * F;
        l1.bias[z] = (const float*)d_in[wb[z] + 1];
        l1.Ch[z] = C1H + (long)z * RH;
        l1.Cl[z] = C1L + (long)z * RH;
        l1.P[z] = nullptr;

        l2.Ah[z] = C1H + (long)z * RH;
        l2.Al[z] = C1L + (long)z * RH;
        l2.WH[z] = W2H + (long)z * HH * HH;
        l2.WL[z] = W2L + (long)z * HH * HH;
        l2.bias[z] = (const float*)d_in[wb[z] + 3];
        l2.Ch[z] = C2H + (long)z * RH;
        l2.Cl[z] = C2L + (long)z * RH;
        l2.P[z] = nullptr;

        l3.Ah[z] = C2H + (long)z * RH;
        l3.Al[z] = C2L + (long)z * RH;
        l3.WH[z] = W3H + (long)z * HH * HH;
        l3.WL[z] = W3L + (long)z * HH * HH;
        l3.bias[z] = (const float*)d_in[wb[z] + 5];
        l3.Ch[z] = nullptr;
        l3.Cl[z] = nullptr;
        l3.P[z] = headed[z];
    }

    const dim3 gmma(HH / 128, ROWS / 128, 3);   // (4, 32, 3)
    mlp_mma<<<gmma, blk, SMEM_MMA>>>(l1, F,  1);
    mlp_mma<<<gmma, blk, SMEM_MMA>>>(l2, HH, 1);
    mlp_mma<<<gmma, blk, SMEM_MMA>>>(l3, HH, 2);

    dist_exp_x2<<<dim3(8, 8, 32), blk>>>(Qh, Kh, E);
    denom_kernel<<<4096, blk>>>(E, rd);
    attn_v_x2<<<dim3(1, 16, 32), blk>>>(E, rd, Vh, attn);

    sgemm_final<<<dim3(OO / 64, ROWS / 32), blk>>>(
        attn, (const float*)d_in[21], (const float*)d_in[22],
        (float*)d_out, ROWS, OO, HH);
}

// round 16
// speedup vs baseline: 2.2416x; 1.1130x over previous
#include <cuda_runtime.h>
#include <cuda_bf16.h>
#include <cstdint>

// Problem constants
static constexpr int BB   = 4;
static constexpr int S    = 1024;
static constexpr int F    = 128;
static constexpr int HH   = 512;
static constexpr int OO   = 128;
static constexpr int ROWS = BB * S;         // 4096
static constexpr int RH   = ROWS * HH;

// ---------------- scratch (device globals) ----------------
__device__ __nv_bfloat16 g_XH[3 * ROWS * F];
__device__ __nv_bfloat16 g_XL[3 * ROWS * F];
__device__ __nv_bfloat16 g_W1H[3 * HH * F];    // transposed [n][k]
__device__ __nv_bfloat16 g_W1L[3 * HH * F];
__device__ __nv_bfloat16 g_W2H[3 * HH * HH];
__device__ __nv_bfloat16 g_W2L[3 * HH * HH];
__device__ __nv_bfloat16 g_W3H[3 * HH * HH];
__device__ __nv_bfloat16 g_W3L[3 * HH * HH];
__device__ __nv_bfloat16 g_C1H[3 * RH];
__device__ __nv_bfloat16 g_C1L[3 * RH];
__device__ __nv_bfloat16 g_C2H[3 * RH];
__device__ __nv_bfloat16 g_C2L[3 * RH];
__device__ float g_Kh[RH];                     // [b][h][i][d]
__device__ float g_Qh[RH];
__device__ float g_Vh[RH];
__device__ float g_E[(long)BB * 8 * S * S];    // [z][j][i]
__device__ __nv_bfloat16 g_PH[(long)BB * 8 * S * S];  // normalized attn, hi
__device__ __nv_bfloat16 g_PL[(long)BB * 8 * S * S];  // normalized attn, lo
__device__ __nv_bfloat16 g_VtH[32 * 64 * S];   // V^T [z][d][i], hi
__device__ __nv_bfloat16 g_VtL[32 * 64 * S];   // V^T [z][d][i], lo
__device__ float g_attn[RH];                   // [b][j][f=d*8+h]

// ---------------- packed f32x2 helpers ----------------
typedef unsigned long long u64;

__device__ __forceinline__ u64 dup2(float a) {
    u64 r;
    asm("mov.b64 %0, {%1, %1};" : "=l"(r) : "r"(__float_as_uint(a)));
    return r;
}
__device__ __forceinline__ void ffma2(u64& c, u64 a, u64 b) {
    asm("fma.rn.f32x2 %0, %1, %2, %0;" : "+l"(c) : "l"(a), "l"(b));
}
__device__ __forceinline__ u64 add2(u64 a, u64 b) {
    u64 d;
    asm("add.rn.f32x2 %0, %1, %2;" : "=l"(d) : "l"(a), "l"(b));
    return d;
}
__device__ __forceinline__ u64 abs2(u64 a) {
    u64 d;
    asm("and.b64 %0, %1, 0x7FFFFFFF7FFFFFFF;" : "=l"(d) : "l"(a));
    return d;
}
__device__ __forceinline__ void unpk2(float& lo, float& hi, u64 v) {
    unsigned int l, h;
    asm("mov.b64 {%0, %1}, %2;" : "=r"(l), "=r"(h) : "l"(v));
    lo = __uint_as_float(l);
    hi = __uint_as_float(h);
}

// ---------------- mma.sync / cp.async helpers (base sm_80+ features) -------
__device__ __forceinline__ uint32_t smem_u32(const void* p) {
    uint32_t a;
    asm("{ .reg .u64 t; cvta.to.shared.u64 t, %1; cvt.u32.u64 %0, t; }"
        : "=r"(a) : "l"(p));
    return a;
}
__device__ __forceinline__ uint32_t swz64(uint32_t x) { return x ^ ((x >> 3) & 0x30); }

__device__ __forceinline__ void ldsm4(uint32_t* r, uint32_t a) {
    asm volatile("ldmatrix.sync.aligned.m8n8.x4.shared.b16 {%0,%1,%2,%3}, [%4];"
                 : "=r"(r[0]), "=r"(r[1]), "=r"(r[2]), "=r"(r[3]) : "r"(a));
}
__device__ __forceinline__ void mma16816(float* c, const uint32_t* a,
                                         uint32_t b0, uint32_t b1) {
    asm volatile(
        "mma.sync.aligned.m16n8k16.row.col.f32.bf16.bf16.f32 "
        "{%0,%1,%2,%3}, {%4,%5,%6,%7}, {%8,%9}, {%0,%1,%2,%3};"
        : "+f"(c[0]), "+f"(c[1]), "+f"(c[2]), "+f"(c[3])
        : "r"(a[0]), "r"(a[1]), "r"(a[2]), "r"(a[3]), "r"(b0), "r"(b1));
}
__device__ __forceinline__ void cpasync16(uint32_t s, const void* g) {
    asm volatile("cp.async.cg.shared.global [%0], [%1], 16;" :: "r"(s), "l"(g));
}
__device__ __forceinline__ void cpcommit() {
    asm volatile("cp.async.commit_group;" ::: "memory");
}
template <int N> __device__ __forceinline__ void cpwait() {
    asm volatile("cp.async.wait_group %0;" :: "n"(N) : "memory");
}

// ---------------------------------------------------------------------------
// Pre-split input activations: X f32 -> (hi, lo) bf16, same layout.
// ---------------------------------------------------------------------------
__global__ __launch_bounds__(256) void split_x(
    const float* __restrict__ K_, const float* __restrict__ Q_,
    const float* __restrict__ V_)
{
    const int gid = blockIdx.x * 256 + threadIdx.x;
    const int per = ROWS * F / 4;
    const int z = gid / per, r = gid - z * per;
    const float* src = (z == 0) ? K_ : ((z == 1) ? Q_ : V_);
    const float4 v = ((const float4*)src)[r];
    float x[4] = {v.x, v.y, v.z, v.w};
    unsigned hp[2], lp[2];
#pragma unroll
    for (int p = 0; p < 2; p++) {
        __nv_bfloat16 h0 = __float2bfloat16(x[2 * p]);
        __nv_bfloat16 h1 = __float2bfloat16(x[2 * p + 1]);
        __nv_bfloat16 l0 = __float2bfloat16(x[2 * p] - __bfloat162float(h0));
        __nv_bfloat16 l1 = __float2bfloat16(x[2 * p + 1] - __bfloat162float(h1));
        hp[p] = ((unsigned)__bfloat16_as_ushort(h1) << 16) | __bfloat16_as_ushort(h0);
        lp[p] = ((unsigned)__bfloat16_as_ushort(l1) << 16) | __bfloat16_as_ushort(l0);
    }
    const long e0 = (long)z * (ROWS * F) + (long)r * 4;
    *(uint2*)(&g_XH[e0]) = make_uint2(hp[0], hp[1]);
    *(uint2*)(&g_XL[e0]) = make_uint2(lp[0], lp[1]);
}

// ---------------------------------------------------------------------------
// Weight transpose + split: W[K][512] f32 -> H/L [512][K] bf16.
// ---------------------------------------------------------------------------
struct WTJob { const float* W; __nv_bfloat16* H; __nv_bfloat16* L; int K; };
struct WTJobs { WTJob j[9]; };

__global__ __launch_bounds__(256) void wsplit(WTJobs js)
{
    const WTJob jb = js.j[blockIdx.z];
    const int K = jb.K;
    const int kb = blockIdx.y * 32;
    if (kb >= K) return;
    __shared__ float t[32][33];
    const int tx = threadIdx.x, ty = threadIdx.y;   // block (32, 8)
    const int n = blockIdx.x * 32 + tx;
#pragma unroll
    for (int jj = 0; jj < 32; jj += 8)
        t[ty + jj][tx] = jb.W[(long)(kb + ty + jj) * HH + n];
    __syncthreads();
    const int nn = blockIdx.x * 32 + ty;
    const int kk = kb + tx;
#pragma unroll
    for (int jj = 0; jj < 32; jj += 8) {
        const float v = t[tx][ty + jj];
        const __nv_bfloat16 h = __float2bfloat16(v);
        jb.H[(long)(nn + jj) * K + kk] = h;
        jb.L[(long)(nn + jj) * K + kk] = __float2bfloat16(v - __bfloat162float(h));
    }
}

// ---------------------------------------------------------------------------
// Split-bf16 MLP layer via mma.sync, cp.async 3-stage pipeline (R10 winner).
// ---------------------------------------------------------------------------
struct MmaL {
    const __nv_bfloat16 *Ah[3], *Al[3], *WH[3], *WL[3];
    const float* bias[3];
    __nv_bfloat16 *Ch[3], *Cl[3];
    float* P[3];
};

static constexpr int STG_BYTES = 32768;
static constexpr int SMEM_MMA  = 3 * STG_BYTES;   // 98304

__global__ __launch_bounds__(256, 2) void mlp_mma(MmaL p, int K, int mode)
{
    extern __shared__ char smem[];
    const uint32_t sb = smem_u32(smem);
    const int tid = threadIdx.x, wid = tid >> 5, lane = tid & 31;
    const int z = blockIdx.z, bx = blockIdx.x, by = blockIdx.y;

    const int m0 = (wid & 3) * 32;      // warp M offset in tile
    const int n0 = (wid >> 2) * 64;     // warp N offset in tile

    const int row  = tid >> 1;
    const int hseg = tid & 1;
    const __nv_bfloat16* Ahp = p.Ah[z] + (long)(by * 128 + row) * K + hseg * 16;
    const __nv_bfloat16* Alp = p.Al[z] + (long)(by * 128 + row) * K + hseg * 16;
    const __nv_bfloat16* WHp = p.WH[z] + (long)(bx * 128 + row) * K + hseg * 16;
    const __nv_bfloat16* WLp = p.WL[z] + (long)(bx * 128 + row) * K + hseg * 16;
    const uint32_t st0 = (uint32_t)(row * 64 + hseg * 32);
    const uint32_t sA0 = swz64(st0), sA1 = swz64(st0 + 16);

    float acc[2][8][4];
#pragma unroll
    for (int mt = 0; mt < 2; mt++)
#pragma unroll
        for (int nt = 0; nt < 8; nt++)
#pragma unroll
            for (int q = 0; q < 4; q++) acc[mt][nt][q] = 0.f;

    const uint32_t rowa = lane & 15;
    const uint32_t segl = (lane >> 4) << 4;

    const int nst = K >> 5;

    auto issue_stage = [&](int s, int st) {
        const uint32_t base = sb + (uint32_t)st * STG_BYTES;
        const int gc = s * 32;
        cpasync16(base + 0     + sA0, Ahp + gc);
        cpasync16(base + 0     + sA1, Ahp + gc + 8);
        cpasync16(base + 8192  + sA0, Alp + gc);
        cpasync16(base + 8192  + sA1, Alp + gc + 8);
        cpasync16(base + 16384 + sA0, WHp + gc);
        cpasync16(base + 16384 + sA1, WHp + gc + 8);
        cpasync16(base + 24576 + sA0, WLp + gc);
        cpasync16(base + 24576 + sA1, WLp + gc + 8);
    };

    issue_stage(0, 0); cpcommit();
    issue_stage(1, 1); cpcommit();

    int st = 0;
    for (int s = 0; s < nst; s++) {
        if (s == nst - 1) cpwait<0>(); else cpwait<1>();
        __syncthreads();
        if (s + 2 < nst) {
            int st2 = st + 2; if (st2 >= 3) st2 -= 3;
            issue_stage(s + 2, st2);
            cpcommit();
        }
        const uint32_t base = sb + (uint32_t)st * STG_BYTES;
#pragma unroll
        for (int ks = 0; ks < 2; ks++) {
            uint32_t ah[2][4], al[2][4];
#pragma unroll
            for (int mt = 0; mt < 2; mt++) {
                const uint32_t off = (m0 + mt * 16 + rowa) * 64 + ks * 32 + segl;
                ldsm4(ah[mt], base + swz64(off));
                ldsm4(al[mt], base + 8192 + swz64(off));
            }
#pragma unroll
            for (int ntp = 0; ntp < 4; ntp++) {
                uint32_t bh[4], bl[4];
                const uint32_t off = (n0 + ntp * 16 + rowa) * 64 + ks * 32 + segl;
                ldsm4(bh, base + 16384 + swz64(off));
                ldsm4(bl, base + 24576 + swz64(off));
#pragma unroll
                for (int mt = 0; mt < 2; mt++) {
                    float* C0 = acc[mt][2 * ntp];
                    float* C1 = acc[mt][2 * ntp + 1];
                    mma16816(C0, ah[mt], bh[0], bh[2]);
                    mma16816(C0, ah[mt], bl[0], bl[2]);
                    mma16816(C0, al[mt], bh[0], bh[2]);
                    mma16816(C1, ah[mt], bh[1], bh[3]);
                    mma16816(C1, ah[mt], bl[1], bl[3]);
                    mma16816(C1, al[mt], bh[1], bh[3]);
                }
            }
        }
        st++; if (st >= 3) st -= 3;
    }

    // epilogue — cn includes the bx*128 tile offset
    const float* bias = p.bias[z];
    const int grp = lane >> 2, qd = (lane & 3) * 2;
#pragma unroll
    for (int mt = 0; mt < 2; mt++) {
        const int r0 = by * 128 + m0 + mt * 16 + grp;
        const int r1 = r0 + 8;
#pragma unroll
        for (int nt = 0; nt < 8; nt++) {
            const int cn = bx * 128 + n0 + nt * 8 + qd;
            const float b0v = bias[cn], b1v = bias[cn + 1];
            float v00 = acc[mt][nt][0] + b0v;
            float v01 = acc[mt][nt][1] + b1v;
            float v10 = acc[mt][nt][2] + b0v;
            float v11 = acc[mt][nt][3] + b1v;
            if (mode == 1) {
                v00 = fmaxf(v00, 0.f); v01 = fmaxf(v01, 0.f);
                v10 = fmaxf(v10, 0.f); v11 = fmaxf(v11, 0.f);
                __nv_bfloat16* Ch = p.Ch[z];
                __nv_bfloat16* Cl = p.Cl[z];
                const __nv_bfloat16 h00 = __float2bfloat16(v00);
                const __nv_bfloat16 h01 = __float2bfloat16(v01);
                const __nv_bfloat16 h10 = __float2bfloat16(v10);
                const __nv_bfloat16 h11 = __float2bfloat16(v11);
                const __nv_bfloat16 l00 = __float2bfloat16(v00 - __bfloat162float(h00));
                const __nv_bfloat16 l01 = __float2bfloat16(v01 - __bfloat162float(h01));
                const __nv_bfloat16 l10 = __float2bfloat16(v10 - __bfloat162float(h10));
                const __nv_bfloat16 l11 = __float2bfloat16(v11 - __bfloat162float(h11));
                *(unsigned*)(Ch + (long)r0 * HH + cn) =
                    ((unsigned)__bfloat16_as_ushort(h01) << 16) | __bfloat16_as_ushort(h00);
                *(unsigned*)(Cl + (long)r0 * HH + cn) =
                    ((unsigned)__bfloat16_as_ushort(l01) << 16) | __bfloat16_as_ushort(l00);
                *(unsigned*)(Ch + (long)r1 * HH + cn) =
                    ((unsigned)__bfloat16_as_ushort(h11) << 16) | __bfloat16_as_ushort(h10);
                *(unsigned*)(Cl + (long)r1 * HH + cn) =
                    ((unsigned)__bfloat16_as_ushort(l11) << 16) | __bfloat16_as_ushort(l10);
            } else {
                float* P = p.P[z];
                const int b0r = r0 >> 10, i0 = r0 & 1023;
                const int b1r = r1 >> 10, i1 = r1 & 1023;
                const int h0 = cn & 7, d0 = cn >> 3;
                const int h1 = (cn + 1) & 7, d1 = (cn + 1) >> 3;
                P[((long)(b0r * 8 + h0) * 1024 + i0) * 64 + d0] = v00;
                P[((long)(b0r * 8 + h1) * 1024 + i0) * 64 + d1] = v01;
                P[((long)(b1r * 8 + h0) * 1024 + i1) * 64 + d0] = v10;
                P[((long)(b1r * 8 + h1) * 1024 + i1) * 64 + d1] = v11;
            }
        }
    }
}

// ---------------------------------------------------------------------------
// Phase A1: distance-GEMM, 128x128 tile + next-kt register prefetch (R15).
// ---------------------------------------------------------------------------
__global__ __launch_bounds__(256, 2) void dist_exp_x2(
    const float* __restrict__ Qh, const float* __restrict__ Kh,
    float* __restrict__ E)
{
    __shared__ float Qs[16][256];   // duplicated pairs
    __shared__ float Ks[16][128];   // negated

    const int z   = blockIdx.z;
    const int tid = threadIdx.x;
    const int r   = tid >> 1;
    const int dc  = (tid & 1) << 3;
    const int ty  = tid >> 4, tx = tid & 15;

    const float* Qp = Qh + (long)(z * 1024 + blockIdx.y * 128 + r) * 64 + dc;
    const float* Kp = Kh + (long)(z * 1024 + blockIdx.x * 128 + r) * 64 + dc;

    u64 acc2[8][4];
#pragma unroll
    for (int m = 0; m < 8; m++)
#pragma unroll
        for (int n = 0; n < 4; n++) acc2[m][n] = 0ULL;

    float4 q0 = *(const float4*)(Qp + 0);
    float4 q1 = *(const float4*)(Qp + 4);
    float4 k0 = *(const float4*)(Kp + 0);
    float4 k1 = *(const float4*)(Kp + 4);

    for (int kt = 0; kt < 4; kt++) {
        if (kt) __syncthreads();
        {
            const float qv[8] = {q0.x, q0.y, q0.z, q0.w, q1.x, q1.y, q1.z, q1.w};
            const float kv[8] = {k0.x, k0.y, k0.z, k0.w, k1.x, k1.y, k1.z, k1.w};
#pragma unroll
            for (int t = 0; t < 8; t++) {
                *(float2*)&Qs[dc + t][2 * r] = make_float2(qv[t], qv[t]);
                Ks[dc + t][r] = -kv[t];
            }
        }
        __syncthreads();
        if (kt < 3) {
            q0 = *(const float4*)(Qp + (kt + 1) * 16);
            q1 = *(const float4*)(Qp + (kt + 1) * 16 + 4);
            k0 = *(const float4*)(Kp + (kt + 1) * 16);
            k1 = *(const float4*)(Kp + (kt + 1) * 16 + 4);
        }
#pragma unroll
        for (int k = 0; k < 16; k++) {
            u64 q2[8], k2[4];
            *(ulonglong2*)&q2[0] = *(const ulonglong2*)&Qs[k][2 * (ty * 8) + 0];
            *(ulonglong2*)&q2[2] = *(const ulonglong2*)&Qs[k][2 * (ty * 8) + 4];
            *(ulonglong2*)&q2[4] = *(const ulonglong2*)&Qs[k][2 * (ty * 8) + 8];
            *(ulonglong2*)&q2[6] = *(const ulonglong2*)&Qs[k][2 * (ty * 8) + 12];
            *(ulonglong2*)&k2[0] = *(const ulonglong2*)&Ks[k][tx * 8];
            *(ulonglong2*)&k2[2] = *(const ulonglong2*)&Ks[k][tx * 8 + 4];
#pragma unroll
            for (int m = 0; m < 8; m++)
#pragma unroll
                for (int n = 0; n < 4; n++) {
                    const u64 t2 = abs2(add2(q2[m], k2[n]));
                    acc2[m][n] = add2(acc2[m][n], t2);
                }
        }
    }

    const long base = ((long)(z * 1024 + blockIdx.y * 128 + ty * 8)) * 1024
                    + blockIdx.x * 128 + tx * 8;
#pragma unroll
    for (int m = 0; m < 8; m++) {
        float o[8];
#pragma unroll
        for (int n = 0; n < 4; n++) {
            float lo, hi;
            unpk2(lo, hi, acc2[m][n]);
            o[2 * n]     = __expf(-0.5f * lo * lo);
            o[2 * n + 1] = __expf(-0.5f * hi * hi);
        }
        *(float4*)(E + base + (long)m * 1024 + 0) = make_float4(o[0], o[1], o[2], o[3]);
        *(float4*)(E + base + (long)m * 1024 + 4) = make_float4(o[4], o[5], o[6], o[7]);
    }
}

// ---------------------------------------------------------------------------
// Phase A2: pnorm — P[z][j][i] = E / sum_h E, written as split-bf16 (hi,lo).
// ---------------------------------------------------------------------------
__global__ __launch_bounds__(256) void pnorm(
    const float* __restrict__ E,
    __nv_bfloat16* __restrict__ PH, __nv_bfloat16* __restrict__ PL)
{
    const int gid = blockIdx.x * 256 + threadIdx.x;   // 1M float4s
    const int b   = gid >> 18;
    const int rem = gid & ((1 << 18) - 1);
    const float4* Ep = (const float4*)E;
    float4 e[8];
    float4 s = make_float4(0.f, 0.f, 0.f, 0.f);
#pragma unroll
    for (int h = 0; h < 8; h++) {
        e[h] = Ep[(((long)(b * 8 + h)) << 18) + rem];
        s.x += e[h].x; s.y += e[h].y; s.z += e[h].z; s.w += e[h].w;
    }
    const float4 r = make_float4(1.f / s.x, 1.f / s.y, 1.f / s.z, 1.f / s.w);
#pragma unroll
    for (int h = 0; h < 8; h++) {
        const float p0 = e[h].x * r.x, p1 = e[h].y * r.y;
        const float p2 = e[h].z * r.z, p3 = e[h].w * r.w;
        const __nv_bfloat16 h0 = __float2bfloat16(p0);
        const __nv_bfloat16 h1 = __float2bfloat16(p1);
        const __nv_bfloat16 h2 = __float2bfloat16(p2);
        const __nv_bfloat16 h3 = __float2bfloat16(p3);
        const __nv_bfloat16 l0 = __float2bfloat16(p0 - __bfloat162float(h0));
        const __nv_bfloat16 l1 = __float2bfloat16(p1 - __bfloat162float(h1));
        const __nv_bfloat16 l2 = __float2bfloat16(p2 - __bfloat162float(h2));
        const __nv_bfloat16 l3 = __float2bfloat16(p3 - __bfloat162float(h3));
        const long off = (((long)(b * 8 + h)) << 20) + (long)rem * 4;
        *(uint2*)(PH + off) = make_uint2(
            ((unsigned)__bfloat16_as_ushort(h1) << 16) | __bfloat16_as_ushort(h0),
            ((unsigned)__bfloat16_as_ushort(h3) << 16) | __bfloat16_as_ushort(h2));
        *(uint2*)(PL + off) = make_uint2(
            ((unsigned)__bfloat16_as_ushort(l1) << 16) | __bfloat16_as_ushort(l0),
            ((unsigned)__bfloat16_as_ushort(l3) << 16) | __bfloat16_as_ushort(l2));
    }
}

// ---------------------------------------------------------------------------
// V transpose + split: Vh[z][i][d] f32 -> Vt[z][d][i] bf16 hi/lo.
// ---------------------------------------------------------------------------
__global__ __launch_bounds__(256) void vtrans(
    const float* __restrict__ Vh,
    __nv_bfloat16* __restrict__ VtH, __nv_bfloat16* __restrict__ VtL)
{
    __shared__ float t[32][33];
    const int z  = blockIdx.z;
    const int d0 = blockIdx.x * 32;
    const int i0 = blockIdx.y * 32;
    const int tx = threadIdx.x, ty = threadIdx.y;   // block (32, 8)
#pragma unroll
    for (int jj = 0; jj < 32; jj += 8)
        t[ty + jj][tx] = Vh[(long)z * 65536 + (long)(i0 + ty + jj) * 64 + d0 + tx];
    __syncthreads();
#pragma unroll
    for (int jj = 0; jj < 32; jj += 8) {
        const float v = t[tx][ty + jj];      // i_local=tx, d_local=ty+jj
        const __nv_bfloat16 hi = __float2bfloat16(v);
        const long idx = (long)z * 65536 + (long)(d0 + ty + jj) * 1024 + i0 + tx;
        VtH[idx] = hi;
        VtL[idx] = __float2bfloat16(v - __bfloat162float(hi));
    }
}

// ---------------------------------------------------------------------------
// Phase B: attn @ V via mma.sync split-bf16, cp.async 3-stage pipeline.
// CTA = 128(j) x 64(d), K = i in stages of 32. 8 warps, warp tile 16x64.
// out[b][j][d*8+h] = sum_i P[z,j,i] * V[z,i,d]
// ---------------------------------------------------------------------------
static constexpr int AV_STG  = 24576;            // PH 8K | PL 8K | VH 4K | VL 4K
static constexpr int SMEM_AV = 3 * AV_STG;       // 73728

__global__ __launch_bounds__(256, 2) void attn_v_mma(
    const __nv_bfloat16* __restrict__ PH, const __nv_bfloat16* __restrict__ PL,
    const __nv_bfloat16* __restrict__ VtH, const __nv_bfloat16* __restrict__ VtL,
    float* __restrict__ Oo)
{
    extern __shared__ char smem[];
    const uint32_t sb = smem_u32(smem);
    const int tid = threadIdx.x, wid = tid >> 5, lane = tid & 31;
    const int jt = blockIdx.x, z = blockIdx.y;
    const int b = z >> 3, h = z & 7;
    const int m0 = wid * 16;

    const int prow = tid >> 1, pseg = tid & 1;
    const __nv_bfloat16* PHp = PH + ((long)z << 20) + (long)(jt * 128 + prow) * 1024 + pseg * 16;
    const __nv_bfloat16* PLp = PL + ((long)z << 20) + (long)(jt * 128 + prow) * 1024 + pseg * 16;
    const int vrow = tid >> 2, vseg = tid & 3;
    const __nv_bfloat16* VHp = VtH + (long)z * 65536 + (long)vrow * 1024 + vseg * 8;
    const __nv_bfloat16* VLp = VtL + (long)z * 65536 + (long)vrow * 1024 + vseg * 8;
    const uint32_t pst0 = swz64((uint32_t)(prow * 64 + pseg * 32));
    const uint32_t pst1 = swz64((uint32_t)(prow * 64 + pseg * 32 + 16));
    const uint32_t vst  = swz64((uint32_t)(vrow * 64 + vseg * 16));

    float acc[8][4];
#pragma unroll
    for (int nt = 0; nt < 8; nt++)
#pragma unroll
        for (int q = 0; q < 4; q++) acc[nt][q] = 0.f;

    auto issue_stage = [&](int s, int st) {
        const uint32_t base = sb + (uint32_t)st * AV_STG;
        const int gc = s * 32;
        cpasync16(base + 0     + pst0, PHp + gc);
        cpasync16(base + 0     + pst1, PHp + gc + 8);
        cpasync16(base + 8192  + pst0, PLp + gc);
        cpasync16(base + 8192  + pst1, PLp + gc + 8);
        cpasync16(base + 16384 + vst,  VHp + gc);
        cpasync16(base + 20480 + vst,  VLp + gc);
    };

    issue_stage(0, 0); cpcommit();
    issue_stage(1, 1); cpcommit();

    const uint32_t rowa = lane & 15;
    const uint32_t segl = (lane >> 4) << 4;

    int st = 0;
    for (int s = 0; s < 32; s++) {
        if (s == 31) cpwait<0>(); else cpwait<1>();
        __syncthreads();
        if (s + 2 < 32) {
            int st2 = st + 2; if (st2 >= 3) st2 -= 3;
            issue_stage(s + 2, st2);
            cpcommit();
        }
        const uint32_t base = sb + (uint32_t)st * AV_STG;
#pragma unroll
        for (int ks = 0; ks < 2; ks++) {
            uint32_t ah[4], al[4];
            const uint32_t aoff = (m0 + rowa) * 64 + ks * 32 + segl;
            ldsm4(ah, base + swz64(aoff));
            ldsm4(al, base + 8192 + swz64(aoff));
#pragma unroll
            for (int ntp = 0; ntp < 4; ntp++) {
                uint32_t bh[4], bl[4];
                const uint32_t boff = (ntp * 16 + rowa) * 64 + ks * 32 + segl;
                ldsm4(bh, base + 16384 + swz64(boff));
                ldsm4(bl, base + 20480 + swz64(boff));
                float* C0 = acc[2 * ntp];
                float* C1 = acc[2 * ntp + 1];
                mma16816(C0, ah, bh[0], bh[2]);
                mma16816(C0, ah, bl[0], bl[2]);
                mma16816(C0, al, bh[0], bh[2]);
                mma16816(C1, ah, bh[1], bh[3]);
                mma16816(C1, ah, bl[1], bl[3]);
                mma16816(C1, al, bh[1], bh[3]);
            }
        }
        st++; if (st >= 3) st -= 3;
    }

    // epilogue: rows r0/r1 = j, cols = d; write Oo[b][j][d*8+h]
    const int grp = lane >> 2, qd = (lane & 3) * 2;
    const int r0 = jt * 128 + m0 + grp;
    const int r1 = r0 + 8;
#pragma unroll
    for (int nt = 0; nt < 8; nt++) {
        const int dn = nt * 8 + qd;
        float* o0 = Oo + (long)(b * 1024 + r0) * 512 + (long)dn * 8 + h;
        float* o1 = Oo + (long)(b * 1024 + r1) * 512 + (long)dn * 8 + h;
        o0[0] = acc[nt][0]; o0[8] = acc[nt][1];
        o1[0] = acc[nt][2]; o1[8] = acc[nt][3];
    }
}

// ---------------------------------------------------------------------------
// Final projection GEMM (unchanged).
// ---------------------------------------------------------------------------
__global__ __launch_bounds__(256, 2) void sgemm_final(
    const float* __restrict__ A, const float* __restrict__ B,
    const float* __restrict__ bias, float* __restrict__ C,
    int M, int N, int K)
{
    __shared__ float As[16][32];
    __shared__ float Bs[16][64];

    const int tid = threadIdx.x;
    const int bx = blockIdx.x, by = blockIdx.y;

    const int ar = tid >> 3;
    const int ac = (tid & 7) << 1;
    const int brr = tid >> 4;
    const int bcc = (tid & 15) << 2;

    const float* Ap = A + (long)(by * 32 + ar) * K + ac;
    const float* Bp = B + (long)brr * N + bx * 64 + bcc;

    const int ty = tid >> 4, tx = tid & 15;

    u64 acc2[4];
#pragma unroll
    for (int n = 0; n < 4; n++) acc2[n] = 0ULL;

    const int nt = K >> 4;
    for (int kt = 0; kt < nt; kt++) {
        const float2 a2l = *(const float2*)(Ap + kt * 16);
        const float4 bv  = *(const float4*)(Bp + (long)kt * 16 * N);
        if (kt) __syncthreads();
        As[ac + 0][ar] = a2l.x;
        As[ac + 1][ar] = a2l.y;
        *(float4*)&Bs[brr][bcc] = bv;
        __syncthreads();
#pragma unroll
        for (int k = 0; k < 16; k++) {
            const u64 a2 = *(const u64*)&As[k][ty * 2];
            float bf[4];
            *(float4*)&bf[0] = *(const float4*)&Bs[k][tx * 4];
#pragma unroll
            for (int n = 0; n < 4; n++) ffma2(acc2[n], a2, dup2(bf[n]));
        }
    }

    const int j0 = by * 32 + ty * 2;
    const int c0 = bx * 64 + tx * 4;
#pragma unroll
    for (int n = 0; n < 4; n++) {
        float lo, hi;
        unpk2(lo, hi, acc2[n]);
        const float bb = bias[c0 + n];
        C[(long)j0 * N + c0 + n]       = lo + bb;
        C[(long)(j0 + 1) * N + c0 + n] = hi + bb;
    }
}

// ---------------------------------------------------------------------------
extern "C" void kernel_launch(void* const* d_in, const int* in_sizes, int n_in,
                              void* d_out, int out_size)
{
    const float* KEY   = (const float*)d_in[0];
    const float* VALUE = (const float*)d_in[1];
    const float* QUERY = (const float*)d_in[2];

    float *Kh, *Qh, *Vh, *E, *attn;
    cudaGetSymbolAddress((void**)&Kh,   g_Kh);
    cudaGetSymbolAddress((void**)&Qh,   g_Qh);
    cudaGetSymbolAddress((void**)&Vh,   g_Vh);
    cudaGetSymbolAddress((void**)&E,    g_E);
    cudaGetSymbolAddress((void**)&attn, g_attn);

    __nv_bfloat16 *XH, *XL, *W1H, *W1L, *W2H, *W2L, *W3H, *W3L;
    __nv_bfloat16 *C1H, *C1L, *C2H, *C2L, *PHp, *PLp, *VtH, *VtL;
    cudaGetSymbolAddress((void**)&XH,  g_XH);
    cudaGetSymbolAddress((void**)&XL,  g_XL);
    cudaGetSymbolAddress((void**)&W1H, g_W1H);
    cudaGetSymbolAddress((void**)&W1L, g_W1L);
    cudaGetSymbolAddress((void**)&W2H, g_W2H);
    cudaGetSymbolAddress((void**)&W2L, g_W2L);
    cudaGetSymbolAddress((void**)&W3H, g_W3H);
    cudaGetSymbolAddress((void**)&W3L, g_W3L);
    cudaGetSymbolAddress((void**)&C1H, g_C1H);
    cudaGetSymbolAddress((void**)&C1L, g_C1L);
    cudaGetSymbolAddress((void**)&C2H, g_C2H);
    cudaGetSymbolAddress((void**)&C2L, g_C2L);
    cudaGetSymbolAddress((void**)&PHp, g_PH);
    cudaGetSymbolAddress((void**)&PLp, g_PL);
    cudaGetSymbolAddress((void**)&VtH, g_VtH);
    cudaGetSymbolAddress((void**)&VtL, g_VtL);

    cudaFuncSetAttribute(mlp_mma,    cudaFuncAttributeMaxDynamicSharedMemorySize, SMEM_MMA);
    cudaFuncSetAttribute(attn_v_mma, cudaFuncAttributeMaxDynamicSharedMemorySize, SMEM_AV);

    const dim3 blk(256);
    const int wb[3] = {3, 9, 15};   // K, Q, V weight base indices
    float* headed[3];
    headed[0] = Kh; headed[1] = Qh; headed[2] = Vh;

    split_x<<<3 * ROWS * F / 1024, blk>>>(KEY, QUERY, VALUE);

    WTJobs js{};
    for (int z = 0; z < 3; z++) {
        js.j[z * 3 + 0] = { (const float*)d_in[wb[z] + 0], W1H + (long)z * HH * F,
                            W1L + (long)z * HH * F,  F  };
        js.j[z * 3 + 1] = { (const float*)d_in[wb[z] + 2], W2H + (long)z * HH * HH,
                            W2L + (long)z * HH * HH, HH };
        js.j[z * 3 + 2] = { (const float*)d_in[wb[z] + 4], W3H + (long)z * HH * HH,
                            W3L + (long)z * HH * HH, HH };
    }
    wsplit<<<dim3(16, 16, 9), dim3(32, 8)>>>(js);

    MmaL l1{}, l2{}, l3{};
    for (int z = 0; z < 3; z++) {
        l1.Ah[z] = XH + (long)z * ROWS * F;
        l1.Al[z] = XL + (long)z * ROWS * F;
        l1.WH[z] = W1H + (long)z * HH * F;
        l1.WL[z] = W1L + (long)z * HH * F;
        l1.bias[z] = (const float*)d_in[wb[z] + 1];
        l1.Ch[z] = C1H + (long)z * RH;
        l1.Cl[z] = C1L + (long)z * RH;
        l1.P[z] = nullptr;

        l2.Ah[z] = C1H + (long)z * RH;
        l2.Al[z] = C1L + (long)z * RH;
        l2.WH[z] = W2H + (long)z * HH * HH;
        l2.WL[z] = W2L + (long)z * HH * HH;
        l2.bias[z] = (const float*)d_in[wb[z] + 3];
        l2.Ch[z] = C2H + (long)z * RH;
        l2.Cl[z] = C2L + (long)z * RH;
        l2.P[z] = nullptr;

        l3.Ah[z] = C2H + (long)z * RH;
        l3.Al[z] = C2L + (long)z * RH;
        l3.WH[z] = W3H + (long)z * HH * HH;
        l3.WL[z] = W3L + (long)z * HH * HH;
        l3.bias[z] = (const float*)d_in[wb[z] + 5];
        l3.Ch[z] = nullptr;
        l3.Cl[z] = nullptr;
        l3.P[z] = headed[z];
    }

    const dim3 gmma(HH / 128, ROWS / 128, 3);   // (4, 32, 3)
    mlp_mma<<<gmma, blk, SMEM_MMA>>>(l1, F,  1);
    mlp_mma<<<gmma, blk, SMEM_MMA>>>(l2, HH, 1);
    mlp_mma<<<gmma, blk, SMEM_MMA>>>(l3, HH, 2);

    // V transpose+split can run concurrently with dist conceptually; keep serial.
    vtrans<<<dim3(2, 32, 32), dim3(32, 8)>>>(Vh, VtH, VtL);

    dist_exp_x2<<<dim3(8, 8, 32), blk>>>(Qh, Kh, E);
    pnorm<<<4096, blk>>>(E, PHp, PLp);
    attn_v_mma<<<dim3(8, 32), blk, SMEM_AV>>>(PHp, PLp, VtH, VtL, attn);

    sgemm_final<<<dim3(OO / 64, ROWS / 32), blk>>>(
        attn, (const float*)d_in[21], (const float*)d_in[22],
        (float*)d_out, ROWS, OO, HH);
}

// round 17
// speedup vs baseline: 2.3413x; 1.0445x over previous
#include <cuda_runtime.h>
#include <cuda_bf16.h>
#include <cstdint>

// Problem constants
static constexpr int BB   = 4;
static constexpr int S    = 1024;
static constexpr int F    = 128;
static constexpr int HH   = 512;
static constexpr int OO   = 128;
static constexpr int ROWS = BB * S;         // 4096
static constexpr int RH   = ROWS * HH;

// ---------------- scratch (device globals) ----------------
__device__ __nv_bfloat16 g_XH[3 * ROWS * F];
__device__ __nv_bfloat16 g_XL[3 * ROWS * F];
__device__ __nv_bfloat16 g_W1H[3 * HH * F];    // transposed [n][k]
__device__ __nv_bfloat16 g_W1L[3 * HH * F];
__device__ __nv_bfloat16 g_W2H[3 * HH * HH];
__device__ __nv_bfloat16 g_W2L[3 * HH * HH];
__device__ __nv_bfloat16 g_W3H[3 * HH * HH];
__device__ __nv_bfloat16 g_W3L[3 * HH * HH];
__device__ __nv_bfloat16 g_WoH[OO * HH];       // Wo^T [n=128][k=512]
__device__ __nv_bfloat16 g_WoL[OO * HH];
__device__ __nv_bfloat16 g_C1H[3 * RH];
__device__ __nv_bfloat16 g_C1L[3 * RH];
__device__ __nv_bfloat16 g_C2H[3 * RH];
__device__ __nv_bfloat16 g_C2L[3 * RH];
__device__ float g_Kh[RH];                     // [b][h][i][d]
__device__ float g_Qh[RH];
__device__ float g_Vh[RH];
__device__ float g_E[(long)BB * 8 * S * S];    // [z][j][i]
__device__ __nv_bfloat16 g_PH[(long)BB * 8 * S * S];  // normalized attn, hi
__device__ __nv_bfloat16 g_PL[(long)BB * 8 * S * S];  // normalized attn, lo
__device__ __nv_bfloat16 g_VtH[32 * 64 * S];   // V^T [z][d][i], hi
__device__ __nv_bfloat16 g_VtL[32 * 64 * S];   // V^T [z][d][i], lo
__device__ __nv_bfloat16 g_AtH[RH];            // context [b][j][f], hi
__device__ __nv_bfloat16 g_AtL[RH];            // context [b][j][f], lo

// ---------------- packed f32x2 helpers ----------------
typedef unsigned long long u64;

__device__ __forceinline__ u64 dup2(float a) {
    u64 r;
    asm("mov.b64 %0, {%1, %1};" : "=l"(r) : "r"(__float_as_uint(a)));
    return r;
}
__device__ __forceinline__ u64 add2(u64 a, u64 b) {
    u64 d;
    asm("add.rn.f32x2 %0, %1, %2;" : "=l"(d) : "l"(a), "l"(b));
    return d;
}
__device__ __forceinline__ u64 abs2(u64 a) {
    u64 d;
    asm("and.b64 %0, %1, 0x7FFFFFFF7FFFFFFF;" : "=l"(d) : "l"(a));
    return d;
}
__device__ __forceinline__ void unpk2(float& lo, float& hi, u64 v) {
    unsigned int l, h;
    asm("mov.b64 {%0, %1}, %2;" : "=r"(l), "=r"(h) : "l"(v));
    lo = __uint_as_float(l);
    hi = __uint_as_float(h);
}

// ---------------- mma.sync / cp.async helpers (base sm_80+ features) -------
__device__ __forceinline__ uint32_t smem_u32(const void* p) {
    uint32_t a;
    asm("{ .reg .u64 t; cvta.to.shared.u64 t, %1; cvt.u32.u64 %0, t; }"
        : "=r"(a) : "l"(p));
    return a;
}
__device__ __forceinline__ uint32_t swz64(uint32_t x) { return x ^ ((x >> 3) & 0x30); }

__device__ __forceinline__ void ldsm4(uint32_t* r, uint32_t a) {
    asm volatile("ldmatrix.sync.aligned.m8n8.x4.shared.b16 {%0,%1,%2,%3}, [%4];"
                 : "=r"(r[0]), "=r"(r[1]), "=r"(r[2]), "=r"(r[3]) : "r"(a));
}
__device__ __forceinline__ void mma16816(float* c, const uint32_t* a,
                                         uint32_t b0, uint32_t b1) {
    asm volatile(
        "mma.sync.aligned.m16n8k16.row.col.f32.bf16.bf16.f32 "
        "{%0,%1,%2,%3}, {%4,%5,%6,%7}, {%8,%9}, {%0,%1,%2,%3};"
        : "+f"(c[0]), "+f"(c[1]), "+f"(c[2]), "+f"(c[3])
        : "r"(a[0]), "r"(a[1]), "r"(a[2]), "r"(a[3]), "r"(b0), "r"(b1));
}
__device__ __forceinline__ void cpasync16(uint32_t s, const void* g) {
    asm volatile("cp.async.cg.shared.global [%0], [%1], 16;" :: "r"(s), "l"(g));
}
__device__ __forceinline__ void cpcommit() {
    asm volatile("cp.async.commit_group;" ::: "memory");
}
template <int N> __device__ __forceinline__ void cpwait() {
    asm volatile("cp.async.wait_group %0;" :: "n"(N) : "memory");
}
__device__ __forceinline__ unsigned pack_bf16(float a, float b) {
    const __nv_bfloat16 x = __float2bfloat16(a);
    const __nv_bfloat16 y = __float2bfloat16(b);
    return ((unsigned)__bfloat16_as_ushort(y) << 16) | __bfloat16_as_ushort(x);
}

// ---------------------------------------------------------------------------
// Pre-split input activations: X f32 -> (hi, lo) bf16, same layout.
// ---------------------------------------------------------------------------
__global__ __launch_bounds__(256) void split_x(
    const float* __restrict__ K_, const float* __restrict__ Q_,
    const float* __restrict__ V_)
{
    const int gid = blockIdx.x * 256 + threadIdx.x;
    const int per = ROWS * F / 4;
    const int z = gid / per, r = gid - z * per;
    const float* src = (z == 0) ? K_ : ((z == 1) ? Q_ : V_);
    const float4 v = ((const float4*)src)[r];
    float x[4] = {v.x, v.y, v.z, v.w};
    unsigned hp[2], lp[2];
#pragma unroll
    for (int p = 0; p < 2; p++) {
        __nv_bfloat16 h0 = __float2bfloat16(x[2 * p]);
        __nv_bfloat16 h1 = __float2bfloat16(x[2 * p + 1]);
        __nv_bfloat16 l0 = __float2bfloat16(x[2 * p] - __bfloat162float(h0));
        __nv_bfloat16 l1 = __float2bfloat16(x[2 * p + 1] - __bfloat162float(h1));
        hp[p] = ((unsigned)__bfloat16_as_ushort(h1) << 16) | __bfloat16_as_ushort(h0);
        lp[p] = ((unsigned)__bfloat16_as_ushort(l1) << 16) | __bfloat16_as_ushort(l0);
    }
    const long e0 = (long)z * (ROWS * F) + (long)r * 4;
    *(uint2*)(&g_XH[e0]) = make_uint2(hp[0], hp[1]);
    *(uint2*)(&g_XL[e0]) = make_uint2(lp[0], lp[1]);
}

// ---------------------------------------------------------------------------
// Weight transpose + split: W[K][N] f32 -> H/L [N][K] bf16.
// ---------------------------------------------------------------------------
struct WTJob { const float* W; __nv_bfloat16* H; __nv_bfloat16* L; int K; int N; };
struct WTJobs { WTJob j[10]; };

__global__ __launch_bounds__(256) void wsplit(WTJobs js)
{
    const WTJob jb = js.j[blockIdx.z];
    const int K = jb.K;
    const int kb = blockIdx.y * 32;
    if (kb >= K) return;
    if (blockIdx.x * 32 >= jb.N) return;
    __shared__ float t[32][33];
    const int tx = threadIdx.x, ty = threadIdx.y;   // block (32, 8)
    const int n = blockIdx.x * 32 + tx;
#pragma unroll
    for (int jj = 0; jj < 32; jj += 8)
        t[ty + jj][tx] = jb.W[(long)(kb + ty + jj) * jb.N + n];
    __syncthreads();
    const int nn = blockIdx.x * 32 + ty;
    const int kk = kb + tx;
#pragma unroll
    for (int jj = 0; jj < 32; jj += 8) {
        const float v = t[tx][ty + jj];
        const __nv_bfloat16 h = __float2bfloat16(v);
        jb.H[(long)(nn + jj) * K + kk] = h;
        jb.L[(long)(nn + jj) * K + kk] = __float2bfloat16(v - __bfloat162float(h));
    }
}

// ---------------------------------------------------------------------------
// Split-bf16 MLP layer via mma.sync, cp.async 3-stage pipeline (R10 winner).
// ---------------------------------------------------------------------------
struct MmaL {
    const __nv_bfloat16 *Ah[3], *Al[3], *WH[3], *WL[3];
    const float* bias[3];
    __nv_bfloat16 *Ch[3], *Cl[3];
    float* P[3];
};

static constexpr int STG_BYTES = 32768;
static constexpr int SMEM_MMA  = 3 * STG_BYTES;   // 98304

__global__ __launch_bounds__(256, 2) void mlp_mma(MmaL p, int K, int mode)
{
    extern __shared__ char smem[];
    const uint32_t sb = smem_u32(smem);
    const int tid = threadIdx.x, wid = tid >> 5, lane = tid & 31;
    const int z = blockIdx.z, bx = blockIdx.x, by = blockIdx.y;

    const int m0 = (wid & 3) * 32;      // warp M offset in tile
    const int n0 = (wid >> 2) * 64;     // warp N offset in tile

    const int row  = tid >> 1;
    const int hseg = tid & 1;
    const __nv_bfloat16* Ahp = p.Ah[z] + (long)(by * 128 + row) * K + hseg * 16;
    const __nv_bfloat16* Alp = p.Al[z] + (long)(by * 128 + row) * K + hseg * 16;
    const __nv_bfloat16* WHp = p.WH[z] + (long)(bx * 128 + row) * K + hseg * 16;
    const __nv_bfloat16* WLp = p.WL[z] + (long)(bx * 128 + row) * K + hseg * 16;
    const uint32_t st0 = (uint32_t)(row * 64 + hseg * 32);
    const uint32_t sA0 = swz64(st0), sA1 = swz64(st0 + 16);

    float acc[2][8][4];
#pragma unroll
    for (int mt = 0; mt < 2; mt++)
#pragma unroll
        for (int nt = 0; nt < 8; nt++)
#pragma unroll
            for (int q = 0; q < 4; q++) acc[mt][nt][q] = 0.f;

    const uint32_t rowa = lane & 15;
    const uint32_t segl = (lane >> 4) << 4;

    const int nst = K >> 5;

    auto issue_stage = [&](int s, int st) {
        const uint32_t base = sb + (uint32_t)st * STG_BYTES;
        const int gc = s * 32;
        cpasync16(base + 0     + sA0, Ahp + gc);
        cpasync16(base + 0     + sA1, Ahp + gc + 8);
        cpasync16(base + 8192  + sA0, Alp + gc);
        cpasync16(base + 8192  + sA1, Alp + gc + 8);
        cpasync16(base + 16384 + sA0, WHp + gc);
        cpasync16(base + 16384 + sA1, WHp + gc + 8);
        cpasync16(base + 24576 + sA0, WLp + gc);
        cpasync16(base + 24576 + sA1, WLp + gc + 8);
    };

    issue_stage(0, 0); cpcommit();
    issue_stage(1, 1); cpcommit();

    int st = 0;
    for (int s = 0; s < nst; s++) {
        if (s == nst - 1) cpwait<0>(); else cpwait<1>();
        __syncthreads();
        if (s + 2 < nst) {
            int st2 = st + 2; if (st2 >= 3) st2 -= 3;
            issue_stage(s + 2, st2);
            cpcommit();
        }
        const uint32_t base = sb + (uint32_t)st * STG_BYTES;
#pragma unroll
        for (int ks = 0; ks < 2; ks++) {
            uint32_t ah[2][4], al[2][4];
#pragma unroll
            for (int mt = 0; mt < 2; mt++) {
                const uint32_t off = (m0 + mt * 16 + rowa) * 64 + ks * 32 + segl;
                ldsm4(ah[mt], base + swz64(off));
                ldsm4(al[mt], base + 8192 + swz64(off));
            }
#pragma unroll
            for (int ntp = 0; ntp < 4; ntp++) {
                uint32_t bh[4], bl[4];
                const uint32_t off = (n0 + ntp * 16 + rowa) * 64 + ks * 32 + segl;
                ldsm4(bh, base + 16384 + swz64(off));
                ldsm4(bl, base + 24576 + swz64(off));
#pragma unroll
                for (int mt = 0; mt < 2; mt++) {
                    float* C0 = acc[mt][2 * ntp];
                    float* C1 = acc[mt][2 * ntp + 1];
                    mma16816(C0, ah[mt], bh[0], bh[2]);
                    mma16816(C0, ah[mt], bl[0], bl[2]);
                    mma16816(C0, al[mt], bh[0], bh[2]);
                    mma16816(C1, ah[mt], bh[1], bh[3]);
                    mma16816(C1, ah[mt], bl[1], bl[3]);
                    mma16816(C1, al[mt], bh[1], bh[3]);
                }
            }
        }
        st++; if (st >= 3) st -= 3;
    }

    // epilogue — cn includes the bx*128 tile offset
    const float* bias = p.bias[z];
    const int grp = lane >> 2, qd = (lane & 3) * 2;
#pragma unroll
    for (int mt = 0; mt < 2; mt++) {
        const int r0 = by * 128 + m0 + mt * 16 + grp;
        const int r1 = r0 + 8;
#pragma unroll
        for (int nt = 0; nt < 8; nt++) {
            const int cn = bx * 128 + n0 + nt * 8 + qd;
            const float b0v = bias[cn], b1v = bias[cn + 1];
            float v00 = acc[mt][nt][0] + b0v;
            float v01 = acc[mt][nt][1] + b1v;
            float v10 = acc[mt][nt][2] + b0v;
            float v11 = acc[mt][nt][3] + b1v;
            if (mode == 1) {
                v00 = fmaxf(v00, 0.f); v01 = fmaxf(v01, 0.f);
                v10 = fmaxf(v10, 0.f); v11 = fmaxf(v11, 0.f);
                __nv_bfloat16* Ch = p.Ch[z];
                __nv_bfloat16* Cl = p.Cl[z];
                const __nv_bfloat16 h00 = __float2bfloat16(v00);
                const __nv_bfloat16 h01 = __float2bfloat16(v01);
                const __nv_bfloat16 h10 = __float2bfloat16(v10);
                const __nv_bfloat16 h11 = __float2bfloat16(v11);
                const __nv_bfloat16 l00 = __float2bfloat16(v00 - __bfloat162float(h00));
                const __nv_bfloat16 l01 = __float2bfloat16(v01 - __bfloat162float(h01));
                const __nv_bfloat16 l10 = __float2bfloat16(v10 - __bfloat162float(h10));
                const __nv_bfloat16 l11 = __float2bfloat16(v11 - __bfloat162float(h11));
                *(unsigned*)(Ch + (long)r0 * HH + cn) =
                    ((unsigned)__bfloat16_as_ushort(h01) << 16) | __bfloat16_as_ushort(h00);
                *(unsigned*)(Cl + (long)r0 * HH + cn) =
                    ((unsigned)__bfloat16_as_ushort(l01) << 16) | __bfloat16_as_ushort(l00);
                *(unsigned*)(Ch + (long)r1 * HH + cn) =
                    ((unsigned)__bfloat16_as_ushort(h11) << 16) | __bfloat16_as_ushort(h10);
                *(unsigned*)(Cl + (long)r1 * HH + cn) =
                    ((unsigned)__bfloat16_as_ushort(l11) << 16) | __bfloat16_as_ushort(l10);
            } else {
                float* P = p.P[z];
                const int b0r = r0 >> 10, i0 = r0 & 1023;
                const int b1r = r1 >> 10, i1 = r1 & 1023;
                const int h0 = cn & 7, d0 = cn >> 3;
                const int h1 = (cn + 1) & 7, d1 = (cn + 1) >> 3;
                P[((long)(b0r * 8 + h0) * 1024 + i0) * 64 + d0] = v00;
                P[((long)(b0r * 8 + h1) * 1024 + i0) * 64 + d1] = v01;
                P[((long)(b1r * 8 + h0) * 1024 + i1) * 64 + d0] = v10;
                P[((long)(b1r * 8 + h1) * 1024 + i1) * 64 + d1] = v11;
            }
        }
    }
}

// ---------------------------------------------------------------------------
// Phase A1: distance-GEMM, 128x128 tile + next-kt register prefetch (R15).
// ---------------------------------------------------------------------------
__global__ __launch_bounds__(256, 2) void dist_exp_x2(
    const float* __restrict__ Qh, const float* __restrict__ Kh,
    float* __restrict__ E)
{
    __shared__ float Qs[16][256];   // duplicated pairs
    __shared__ float Ks[16][128];   // negated

    const int z   = blockIdx.z;
    const int tid = threadIdx.x;
    const int r   = tid >> 1;
    const int dc  = (tid & 1) << 3;
    const int ty  = tid >> 4, tx = tid & 15;

    const float* Qp = Qh + (long)(z * 1024 + blockIdx.y * 128 + r) * 64 + dc;
    const float* Kp = Kh + (long)(z * 1024 + blockIdx.x * 128 + r) * 64 + dc;

    u64 acc2[8][4];
#pragma unroll
    for (int m = 0; m < 8; m++)
#pragma unroll
        for (int n = 0; n < 4; n++) acc2[m][n] = 0ULL;

    float4 q0 = *(const float4*)(Qp + 0);
    float4 q1 = *(const float4*)(Qp + 4);
    float4 k0 = *(const float4*)(Kp + 0);
    float4 k1 = *(const float4*)(Kp + 4);

    for (int kt = 0; kt < 4; kt++) {
        if (kt) __syncthreads();
        {
            const float qv[8] = {q0.x, q0.y, q0.z, q0.w, q1.x, q1.y, q1.z, q1.w};
            const float kv[8] = {k0.x, k0.y, k0.z, k0.w, k1.x, k1.y, k1.z, k1.w};
#pragma unroll
            for (int t = 0; t < 8; t++) {
                *(float2*)&Qs[dc + t][2 * r] = make_float2(qv[t], qv[t]);
                Ks[dc + t][r] = -kv[t];
            }
        }
        __syncthreads();
        if (kt < 3) {
            q0 = *(const float4*)(Qp + (kt + 1) * 16);
            q1 = *(const float4*)(Qp + (kt + 1) * 16 + 4);
            k0 = *(const float4*)(Kp + (kt + 1) * 16);
            k1 = *(const float4*)(Kp + (kt + 1) * 16 + 4);
        }
#pragma unroll
        for (int k = 0; k < 16; k++) {
            u64 q2[8], k2[4];
            *(ulonglong2*)&q2[0] = *(const ulonglong2*)&Qs[k][2 * (ty * 8) + 0];
            *(ulonglong2*)&q2[2] = *(const ulonglong2*)&Qs[k][2 * (ty * 8) + 4];
            *(ulonglong2*)&q2[4] = *(const ulonglong2*)&Qs[k][2 * (ty * 8) + 8];
            *(ulonglong2*)&q2[6] = *(const ulonglong2*)&Qs[k][2 * (ty * 8) + 12];
            *(ulonglong2*)&k2[0] = *(const ulonglong2*)&Ks[k][tx * 8];
            *(ulonglong2*)&k2[2] = *(const ulonglong2*)&Ks[k][tx * 8 + 4];
#pragma unroll
            for (int m = 0; m < 8; m++)
#pragma unroll
                for (int n = 0; n < 4; n++) {
                    const u64 t2 = abs2(add2(q2[m], k2[n]));
                    acc2[m][n] = add2(acc2[m][n], t2);
                }
        }
    }

    const long base = ((long)(z * 1024 + blockIdx.y * 128 + ty * 8)) * 1024
                    + blockIdx.x * 128 + tx * 8;
#pragma unroll
    for (int m = 0; m < 8; m++) {
        float o[8];
#pragma unroll
        for (int n = 0; n < 4; n++) {
            float lo, hi;
            unpk2(lo, hi, acc2[m][n]);
            o[2 * n]     = __expf(-0.5f * lo * lo);
            o[2 * n + 1] = __expf(-0.5f * hi * hi);
        }
        *(float4*)(E + base + (long)m * 1024 + 0) = make_float4(o[0], o[1], o[2], o[3]);
        *(float4*)(E + base + (long)m * 1024 + 4) = make_float4(o[4], o[5], o[6], o[7]);
    }
}

// ---------------------------------------------------------------------------
// Phase A2: pnorm — P[z][j][i] = E / sum_h E, written as split-bf16 (hi,lo).
// ---------------------------------------------------------------------------
__global__ __launch_bounds__(256) void pnorm(
    const float* __restrict__ E,
    __nv_bfloat16* __restrict__ PH, __nv_bfloat16* __restrict__ PL)
{
    const int gid = blockIdx.x * 256 + threadIdx.x;   // 1M float4s
    const int b   = gid >> 18;
    const int rem = gid & ((1 << 18) - 1);
    const float4* Ep = (const float4*)E;
    float4 e[8];
    float4 s = make_float4(0.f, 0.f, 0.f, 0.f);
#pragma unroll
    for (int h = 0; h < 8; h++) {
        e[h] = Ep[(((long)(b * 8 + h)) << 18) + rem];
        s.x += e[h].x; s.y += e[h].y; s.z += e[h].z; s.w += e[h].w;
    }
    const float4 r = make_float4(1.f / s.x, 1.f / s.y, 1.f / s.z, 1.f / s.w);
#pragma unroll
    for (int h = 0; h < 8; h++) {
        const float p0 = e[h].x * r.x, p1 = e[h].y * r.y;
        const float p2 = e[h].z * r.z, p3 = e[h].w * r.w;
        const __nv_bfloat16 h0 = __float2bfloat16(p0);
        const __nv_bfloat16 h1 = __float2bfloat16(p1);
        const __nv_bfloat16 h2 = __float2bfloat16(p2);
        const __nv_bfloat16 h3 = __float2bfloat16(p3);
        const __nv_bfloat16 l0 = __float2bfloat16(p0 - __bfloat162float(h0));
        const __nv_bfloat16 l1 = __float2bfloat16(p1 - __bfloat162float(h1));
        const __nv_bfloat16 l2 = __float2bfloat16(p2 - __bfloat162float(h2));
        const __nv_bfloat16 l3 = __float2bfloat16(p3 - __bfloat162float(h3));
        const long off = (((long)(b * 8 + h)) << 20) + (long)rem * 4;
        *(uint2*)(PH + off) = make_uint2(
            ((unsigned)__bfloat16_as_ushort(h1) << 16) | __bfloat16_as_ushort(h0),
            ((unsigned)__bfloat16_as_ushort(h3) << 16) | __bfloat16_as_ushort(h2));
        *(uint2*)(PL + off) = make_uint2(
            ((unsigned)__bfloat16_as_ushort(l1) << 16) | __bfloat16_as_ushort(l0),
            ((unsigned)__bfloat16_as_ushort(l3) << 16) | __bfloat16_as_ushort(l2));
    }
}

// ---------------------------------------------------------------------------
// V transpose + split: Vh[z][i][d] f32 -> Vt[z][d][i] bf16 hi/lo.
// ---------------------------------------------------------------------------
__global__ __launch_bounds__(256) void vtrans(
    const float* __restrict__ Vh,
    __nv_bfloat16* __restrict__ VtH, __nv_bfloat16* __restrict__ VtL)
{
    __shared__ float t[32][33];
    const int z  = blockIdx.z;
    const int d0 = blockIdx.x * 32;
    const int i0 = blockIdx.y * 32;
    const int tx = threadIdx.x, ty = threadIdx.y;   // block (32, 8)
#pragma unroll
    for (int jj = 0; jj < 32; jj += 8)
        t[ty + jj][tx] = Vh[(long)z * 65536 + (long)(i0 + ty + jj) * 64 + d0 + tx];
    __syncthreads();
#pragma unroll
    for (int jj = 0; jj < 32; jj += 8) {
        const float v = t[tx][ty + jj];      // i_local=tx, d_local=ty+jj
        const __nv_bfloat16 hi = __float2bfloat16(v);
        const long idx = (long)z * 65536 + (long)(d0 + ty + jj) * 1024 + i0 + tx;
        VtH[idx] = hi;
        VtL[idx] = __float2bfloat16(v - __bfloat162float(hi));
    }
}

// ---------------------------------------------------------------------------
// Phase B: attn @ V via mma.sync split-bf16, cp.async 3-stage pipeline.
// CTA = 128(j) x 64(d), K = i in stages of 32. Epilogue writes split-bf16.
// ---------------------------------------------------------------------------
static constexpr int AV_STG  = 24576;            // PH 8K | PL 8K | VH 4K | VL 4K
static constexpr int SMEM_AV = 3 * AV_STG;       // 73728

__global__ __launch_bounds__(256, 2) void attn_v_mma(
    const __nv_bfloat16* __restrict__ PH, const __nv_bfloat16* __restrict__ PL,
    const __nv_bfloat16* __restrict__ VtH, const __nv_bfloat16* __restrict__ VtL,
    __nv_bfloat16* __restrict__ AtH, __nv_bfloat16* __restrict__ AtL)
{
    extern __shared__ char smem[];
    const uint32_t sb = smem_u32(smem);
    const int tid = threadIdx.x, wid = tid >> 5, lane = tid & 31;
    const int jt = blockIdx.x, z = blockIdx.y;
    const int b = z >> 3, h = z & 7;
    const int m0 = wid * 16;

    const int prow = tid >> 1, pseg = tid & 1;
    const __nv_bfloat16* PHp = PH + ((long)z << 20) + (long)(jt * 128 + prow) * 1024 + pseg * 16;
    const __nv_bfloat16* PLp = PL + ((long)z << 20) + (long)(jt * 128 + prow) * 1024 + pseg * 16;
    const int vrow = tid >> 2, vseg = tid & 3;
    const __nv_bfloat16* VHp = VtH + (long)z * 65536 + (long)vrow * 1024 + vseg * 8;
    const __nv_bfloat16* VLp = VtL + (long)z * 65536 + (long)vrow * 1024 + vseg * 8;
    const uint32_t pst0 = swz64((uint32_t)(prow * 64 + pseg * 32));
    const uint32_t pst1 = swz64((uint32_t)(prow * 64 + pseg * 32 + 16));
    const uint32_t vst  = swz64((uint32_t)(vrow * 64 + vseg * 16));

    float acc[8][4];
#pragma unroll
    for (int nt = 0; nt < 8; nt++)
#pragma unroll
        for (int q = 0; q < 4; q++) acc[nt][q] = 0.f;

    auto issue_stage = [&](int s, int st) {
        const uint32_t base = sb + (uint32_t)st * AV_STG;
        const int gc = s * 32;
        cpasync16(base + 0     + pst0, PHp + gc);
        cpasync16(base + 0     + pst1, PHp + gc + 8);
        cpasync16(base + 8192  + pst0, PLp + gc);
        cpasync16(base + 8192  + pst1, PLp + gc + 8);
        cpasync16(base + 16384 + vst,  VHp + gc);
        cpasync16(base + 20480 + vst,  VLp + gc);
    };

    issue_stage(0, 0); cpcommit();
    issue_stage(1, 1); cpcommit();

    const uint32_t rowa = lane & 15;
    const uint32_t segl = (lane >> 4) << 4;

    int st = 0;
    for (int s = 0; s < 32; s++) {
        if (s == 31) cpwait<0>(); else cpwait<1>();
        __syncthreads();
        if (s + 2 < 32) {
            int st2 = st + 2; if (st2 >= 3) st2 -= 3;
            issue_stage(s + 2, st2);
            cpcommit();
        }
        const uint32_t base = sb + (uint32_t)st * AV_STG;
#pragma unroll
        for (int ks = 0; ks < 2; ks++) {
            uint32_t ah[4], al[4];
            const uint32_t aoff = (m0 + rowa) * 64 + ks * 32 + segl;
            ldsm4(ah, base + swz64(aoff));
            ldsm4(al, base + 8192 + swz64(aoff));
#pragma unroll
            for (int ntp = 0; ntp < 4; ntp++) {
                uint32_t bh[4], bl[4];
                const uint32_t boff = (ntp * 16 + rowa) * 64 + ks * 32 + segl;
                ldsm4(bh, base + 16384 + swz64(boff));
                ldsm4(bl, base + 20480 + swz64(boff));
                float* C0 = acc[2 * ntp];
                float* C1 = acc[2 * ntp + 1];
                mma16816(C0, ah, bh[0], bh[2]);
                mma16816(C0, ah, bl[0], bl[2]);
                mma16816(C0, al, bh[0], bh[2]);
                mma16816(C1, ah, bh[1], bh[3]);
                mma16816(C1, ah, bl[1], bl[3]);
                mma16816(C1, al, bh[1], bh[3]);
            }
        }
        st++; if (st >= 3) st -= 3;
    }

    // epilogue: write context as split-bf16, [b][j][f = d*8+h]
    const int grp = lane >> 2, qd = (lane & 3) * 2;
    const int r0 = jt * 128 + m0 + grp;
    const int r1 = r0 + 8;
#pragma unroll
    for (int nt = 0; nt < 8; nt++) {
        const int dn = nt * 8 + qd;
        const long o0 = (long)(b * 1024 + r0) * 512 + (long)dn * 8 + h;
        const long o1 = (long)(b * 1024 + r1) * 512 + (long)dn * 8 + h;
        const float v00 = acc[nt][0], v01 = acc[nt][1];
        const float v10 = acc[nt][2], v11 = acc[nt][3];
        const __nv_bfloat16 h00 = __float2bfloat16(v00);
        const __nv_bfloat16 h01 = __float2bfloat16(v01);
        const __nv_bfloat16 h10 = __float2bfloat16(v10);
        const __nv_bfloat16 h11 = __float2bfloat16(v11);
        AtH[o0]     = h00;
        AtH[o0 + 8] = h01;
        AtH[o1]     = h10;
        AtH[o1 + 8] = h11;
        AtL[o0]     = __float2bfloat16(v00 - __bfloat162float(h00));
        AtL[o0 + 8] = __float2bfloat16(v01 - __bfloat162float(h01));
        AtL[o1]     = __float2bfloat16(v10 - __bfloat162float(h10));
        AtL[o1 + 8] = __float2bfloat16(v11 - __bfloat162float(h11));
    }
}

// ---------------------------------------------------------------------------
// Final projection via mma.sync split-bf16: out[M,128] = At[M,512] @ Wo + bias.
// CTA = 32(M) x 128(N), K stages of 32. Warps 2(M) x 4(N), warp tile 16x32.
// ---------------------------------------------------------------------------
static constexpr int FG_STG  = 20480;   // AH 2K | AL 2K | WH 8K | WL 8K
static constexpr int SMEM_FG = 3 * FG_STG;   // 61440

__global__ __launch_bounds__(256, 2) void final_mma(
    const __nv_bfloat16* __restrict__ AH_, const __nv_bfloat16* __restrict__ AL_,
    const __nv_bfloat16* __restrict__ WoH, const __nv_bfloat16* __restrict__ WoL,
    const float* __restrict__ bias, float* __restrict__ out)
{
    extern __shared__ char smem[];
    const uint32_t sb = smem_u32(smem);
    const int tid = threadIdx.x, wid = tid >> 5, lane = tid & 31;
    const int by = blockIdx.x;

    const int m0 = (wid & 1) * 16;
    const int n0 = (wid >> 1) * 32;

    const int arow = tid >> 2, aseg = tid & 3;           // tid<128 used
    const __nv_bfloat16* AHp = AH_ + (long)(by * 32 + arow) * HH + aseg * 8;
    const __nv_bfloat16* ALp = AL_ + (long)(by * 32 + arow) * HH + aseg * 8;
    const int wrow = tid >> 1, wseg = (tid & 1) * 2;
    const __nv_bfloat16* WHp = WoH + (long)wrow * HH + wseg * 8;
    const __nv_bfloat16* WLp = WoL + (long)wrow * HH + wseg * 8;
    const uint32_t aoffs = swz64((uint32_t)(arow * 64 + aseg * 16));
    const uint32_t woff0 = swz64((uint32_t)(wrow * 64 + wseg * 16));
    const uint32_t woff1 = swz64((uint32_t)(wrow * 64 + wseg * 16 + 16));

    float acc[4][4];
#pragma unroll
    for (int nt = 0; nt < 4; nt++)
#pragma unroll
        for (int q = 0; q < 4; q++) acc[nt][q] = 0.f;

    auto issue_stage = [&](int s, int st) {
        const uint32_t base = sb + (uint32_t)st * FG_STG;
        const int gc = s * 32;
        if (tid < 128) {
            cpasync16(base + 0    + aoffs, AHp + gc);
            cpasync16(base + 2048 + aoffs, ALp + gc);
        }
        cpasync16(base + 4096  + woff0, WHp + gc);
        cpasync16(base + 4096  + woff1, WHp + gc + 8);
        cpasync16(base + 12288 + woff0, WLp + gc);
        cpasync16(base + 12288 + woff1, WLp + gc + 8);
    };

    issue_stage(0, 0); cpcommit();
    issue_stage(1, 1); cpcommit();

    const uint32_t rowa = lane & 15;
    const uint32_t segl = (lane >> 4) << 4;

    int st = 0;
    for (int s = 0; s < 16; s++) {                       // K = 512
        if (s == 15) cpwait<0>(); else cpwait<1>();
        __syncthreads();
        if (s + 2 < 16) {
            int st2 = st + 2; if (st2 >= 3) st2 -= 3;
            issue_stage(s + 2, st2);
            cpcommit();
        }
        const uint32_t base = sb + (uint32_t)st * FG_STG;
#pragma unroll
        for (int ks = 0; ks < 2; ks++) {
            uint32_t ah[4], al[4];
            const uint32_t aoff = (m0 + rowa) * 64 + ks * 32 + segl;
            ldsm4(ah, base + swz64(aoff));
            ldsm4(al, base + 2048 + swz64(aoff));
#pragma unroll
            for (int ntp = 0; ntp < 2; ntp++) {
                uint32_t bh[4], bl[4];
                const uint32_t boff = (n0 + ntp * 16 + rowa) * 64 + ks * 32 + segl;
                ldsm4(bh, base + 4096 + swz64(boff));
                ldsm4(bl, base + 12288 + swz64(boff));
                float* C0 = acc[2 * ntp];
                float* C1 = acc[2 * ntp + 1];
                mma16816(C0, ah, bh[0], bh[2]);
                mma16816(C0, ah, bl[0], bl[2]);
                mma16816(C0, al, bh[0], bh[2]);
                mma16816(C1, ah, bh[1], bh[3]);
                mma16816(C1, ah, bl[1], bl[3]);
                mma16816(C1, al, bh[1], bh[3]);
            }
        }
        st++; if (st >= 3) st -= 3;
    }

    const int grp = lane >> 2, qd = (lane & 3) * 2;
    const int r0 = by * 32 + m0 + grp;
    const int r1 = r0 + 8;
#pragma unroll
    for (int nt = 0; nt < 4; nt++) {
        const int cn = n0 + nt * 8 + qd;
        const float b0v = bias[cn], b1v = bias[cn + 1];
        out[(long)r0 * OO + cn]     = acc[nt][0] + b0v;
        out[(long)r0 * OO + cn + 1] = acc[nt][1] + b1v;
        out[(long)r1 * OO + cn]     = acc[nt][2] + b0v;
        out[(long)r1 * OO + cn + 1] = acc[nt][3] + b1v;
    }
}

// ---------------------------------------------------------------------------
extern "C" void kernel_launch(void* const* d_in, const int* in_sizes, int n_in,
                              void* d_out, int out_size)
{
    const float* KEY   = (const float*)d_in[0];
    const float* VALUE = (const float*)d_in[1];
    const float* QUERY = (const float*)d_in[2];

    float *Kh, *Qh, *Vh, *E;
    cudaGetSymbolAddress((void**)&Kh,   g_Kh);
    cudaGetSymbolAddress((void**)&Qh,   g_Qh);
    cudaGetSymbolAddress((void**)&Vh,   g_Vh);
    cudaGetSymbolAddress((void**)&E,    g_E);

    __nv_bfloat16 *XH, *XL, *W1H, *W1L, *W2H, *W2L, *W3H, *W3L, *WoH, *WoL;
    __nv_bfloat16 *C1H, *C1L, *C2H, *C2L, *PHp, *PLp, *VtH, *VtL, *AtH, *AtL;
    cudaGetSymbolAddress((void**)&XH,  g_XH);
    cudaGetSymbolAddress((void**)&XL,  g_XL);
    cudaGetSymbolAddress((void**)&W1H, g_W1H);
    cudaGetSymbolAddress((void**)&W1L, g_W1L);
    cudaGetSymbolAddress((void**)&W2H, g_W2H);
    cudaGetSymbolAddress((void**)&W2L, g_W2L);
    cudaGetSymbolAddress((void**)&W3H, g_W3H);
    cudaGetSymbolAddress((void**)&W3L, g_W3L);
    cudaGetSymbolAddress((void**)&WoH, g_WoH);
    cudaGetSymbolAddress((void**)&WoL, g_WoL);
    cudaGetSymbolAddress((void**)&C1H, g_C1H);
    cudaGetSymbolAddress((void**)&C1L, g_C1L);
    cudaGetSymbolAddress((void**)&C2H, g_C2H);
    cudaGetSymbolAddress((void**)&C2L, g_C2L);
    cudaGetSymbolAddress((void**)&PHp, g_PH);
    cudaGetSymbolAddress((void**)&PLp, g_PL);
    cudaGetSymbolAddress((void**)&VtH, g_VtH);
    cudaGetSymbolAddress((void**)&VtL, g_VtL);
    cudaGetSymbolAddress((void**)&AtH, g_AtH);
    cudaGetSymbolAddress((void**)&AtL, g_AtL);

    cudaFuncSetAttribute(mlp_mma,    cudaFuncAttributeMaxDynamicSharedMemorySize, SMEM_MMA);
    cudaFuncSetAttribute(attn_v_mma, cudaFuncAttributeMaxDynamicSharedMemorySize, SMEM_AV);
    cudaFuncSetAttribute(final_mma,  cudaFuncAttributeMaxDynamicSharedMemorySize, SMEM_FG);

    const dim3 blk(256);
    const int wb[3] = {3, 9, 15};   // K, Q, V weight base indices
    float* headed[3];
    headed[0] = Kh; headed[1] = Qh; headed[2] = Vh;

    split_x<<<3 * ROWS * F / 1024, blk>>>(KEY, QUERY, VALUE);

    WTJobs js{};
    for (int z = 0; z < 3; z++) {
        js.j[z * 3 + 0] = { (const float*)d_in[wb[z] + 0], W1H + (long)z * HH * F,
                            W1L + (long)z * HH * F,  F,  HH };
        js.j[z * 3 + 1] = { (const float*)d_in[wb[z] + 2], W2H + (long)z * HH * HH,
                            W2L + (long)z * HH * HH, HH, HH };
        js.j[z * 3 + 2] = { (const float*)d_in[wb[z] + 4], W3H + (long)z * HH * HH,
                            W3L + (long)z * HH * HH, HH, HH };
    }
    js.j[9] = { (const float*)d_in[21], WoH, WoL, HH, OO };
    wsplit<<<dim3(16, 16, 10), dim3(32, 8)>>>(js);

    MmaL l1{}, l2{}, l3{};
    for (int z = 0; z < 3; z++) {
        l1.Ah[z] = XH + (long)z * ROWS * F;
        l1.Al[z] = XL + (long)z * ROWS * F;
        l1.WH[z] = W1H + (long)z * HH * F;
        l1.WL[z] = W1L + (long)z * HH * F;
        l1.bias[z] = (const float*)d_in[wb[z] + 1];
        l1.Ch[z] = C1H + (long)z * RH;
        l1.Cl[z] = C1L + (long)z * RH;
        l1.P[z] = nullptr;

        l2.Ah[z] = C1H + (long)z * RH;
        l2.Al[z] = C1L + (long)z * RH;
        l2.WH[z] = W2H + (long)z * HH * HH;
        l2.WL[z] = W2L + (long)z * HH * HH;
        l2.bias[z] = (const float*)d_in[wb[z] + 3];
        l2.Ch[z] = C2H + (long)z * RH;
        l2.Cl[z] = C2L + (long)z * RH;
        l2.P[z] = nullptr;

        l3.Ah[z] = C2H + (long)z * RH;
        l3.Al[z] = C2L + (long)z * RH;
        l3.WH[z] = W3H + (long)z * HH * HH;
        l3.WL[z] = W3L + (long)z * HH * HH;
        l3.bias[z] = (const float*)d_in[wb[z] + 5];
        l3.Ch[z] = nullptr;
        l3.Cl[z] = nullptr;
        l3.P[z] = headed[z];
    }

    const dim3 gmma(HH / 128, ROWS / 128, 3);   // (4, 32, 3)
    mlp_mma<<<gmma, blk, SMEM_MMA>>>(l1, F,  1);
    mlp_mma<<<gmma, blk, SMEM_MMA>>>(l2, HH, 1);
    mlp_mma<<<gmma, blk, SMEM_MMA>>>(l3, HH, 2);

    vtrans<<<dim3(2, 32, 32), dim3(32, 8)>>>(Vh, VtH, VtL);

    dist_exp_x2<<<dim3(8, 8, 32), blk>>>(Qh, Kh, E);
    pnorm<<<4096, blk>>>(E, PHp, PLp);
    attn_v_mma<<<dim3(8, 32), blk, SMEM_AV>>>(PHp, PLp, VtH, VtL, AtH, AtL);

    final_mma<<<ROWS / 32, blk, SMEM_FG>>>(
        AtH, AtL, WoH, WoL, (const float*)d_in[22], (float*)d_out);
}